// round 7
// baseline (speedup 1.0000x reference)
#include <cuda_runtime.h>
#include <cuda_bf16.h>
#include <cstdint>

#define B_ 4
#define S_ 2048
#define D_ 1024
#define H_ 16
#define DH_ 64
#define MROWS (B_ * S_)
#define QKV_ELEMS (B_ * H_ * S_ * DH_)   // 8388608
#define C_ELEMS   (B_ * S_ * D_)         // 8388608

// -------- bf16 hi/lo scratch (no allocation) --------
__device__ __nv_bfloat16 g_xh[C_ELEMS],  g_xl[C_ELEMS];
__device__ __nv_bfloat16 g_wt_h[3 * H_ * DH_ * D_], g_wt_l[3 * H_ * DH_ * D_];
__device__ __nv_bfloat16 g_wo_h[D_ * D_], g_wo_l[D_ * D_];
__device__ __nv_bfloat16 g_qh[QKV_ELEMS], g_ql[QKV_ELEMS];
__device__ __nv_bfloat16 g_kh[QKV_ELEMS], g_kl[QKV_ELEMS];
__device__ __nv_bfloat16 g_vh[QKV_ELEMS], g_vl[QKV_ELEMS];
__device__ __nv_bfloat16 g_ch[C_ELEMS],  g_cl[C_ELEMS];

// ================= helpers =================
__device__ __forceinline__ uint32_t smem_u32(const void* p) {
    uint32_t a;
    asm("{ .reg .u64 t; cvta.to.shared.u64 t, %1; cvt.u32.u64 %0, t; }" : "=r"(a) : "l"(p));
    return a;
}
__device__ __forceinline__ void bsplit(float v, float& h, float& l) {
    __nv_bfloat16 bh = __float2bfloat16(v);
    h = __bfloat162float(bh);
    l = v - h;
}
__device__ __forceinline__ uint32_t packbf(float lo_elem, float hi_elem) {
    uint32_t r;
    asm("cvt.rn.bf16x2.f32 %0, %1, %2;" : "=r"(r) : "f"(hi_elem), "f"(lo_elem));
    return r;
}
#define LDSM_X4(r0, r1, r2, r3, addr) \
    asm volatile("ldmatrix.sync.aligned.m8n8.x4.shared.b16 {%0,%1,%2,%3}, [%4];" \
        : "=r"(r0), "=r"(r1), "=r"(r2), "=r"(r3) : "r"(addr))
#define LDSM_X4_T(r0, r1, r2, r3, addr) \
    asm volatile("ldmatrix.sync.aligned.m8n8.x4.trans.shared.b16 {%0,%1,%2,%3}, [%4];" \
        : "=r"(r0), "=r"(r1), "=r"(r2), "=r"(r3) : "r"(addr))
#define CP_A16(sa, gp) asm volatile("cp.async.ca.shared.global [%0], [%1], 16;" :: "r"(sa), "l"(gp))
#define CP_COMMIT()    asm volatile("cp.async.commit_group;" ::: "memory")
#define CP_WAIT(n)     asm volatile("cp.async.wait_group %0;" :: "n"(n) : "memory")

__device__ __forceinline__ void mma16816(float* c,
    uint32_t a0, uint32_t a1, uint32_t a2, uint32_t a3, uint32_t b0, uint32_t b1)
{
    asm volatile(
        "mma.sync.aligned.m16n8k16.row.col.f32.bf16.bf16.f32 "
        "{%0,%1,%2,%3}, {%4,%5,%6,%7}, {%8,%9}, {%0,%1,%2,%3};"
        : "+f"(c[0]), "+f"(c[1]), "+f"(c[2]), "+f"(c[3])
        : "r"(a0), "r"(a1), "r"(a2), "r"(a3), "r"(b0), "r"(b1));
}

// ============================================================
// Preconversion kernels (unchanged R6)
// ============================================================
__global__ __launch_bounds__(256) void conv_x_kernel(const float* __restrict__ x)
{
    int i = blockIdx.x * 256 + threadIdx.x;
    float4 v = *(const float4*)(x + 4 * (size_t)i);
    float hx, lx, hy, ly, hz, lz, hw, lw;
    bsplit(v.x, hx, lx); bsplit(v.y, hy, ly);
    bsplit(v.z, hz, lz); bsplit(v.w, hw, lw);
    uint2 wh, wl;
    wh.x = packbf(hx, hy); wh.y = packbf(hz, hw);
    wl.x = packbf(lx, ly); wl.y = packbf(lz, lw);
    *(uint2*)(g_xh + 4 * (size_t)i) = wh;
    *(uint2*)(g_xl + 4 * (size_t)i) = wl;
}

__global__ __launch_bounds__(256) void conv_w_kernel(
    const float* __restrict__ Wq, const float* __restrict__ Wk, const float* __restrict__ Wv)
{
    __shared__ float ts[64][65];
    const int tid = threadIdx.x;
    const int d0 = blockIdx.x * 64;
    const int h  = blockIdx.y;
    const int z  = blockIdx.z;
    const float* W = (z == 0) ? Wq : ((z == 1) ? Wk : Wv);
    const float* src = W + (size_t)h * D_ * DH_;

    #pragma unroll
    for (int i = 0; i < 4; ++i) {
        int idx = tid + i * 256;
        int rr = idx >> 4, cc = idx & 15;
        float4 v = *(const float4*)(src + (size_t)(d0 + rr) * DH_ + cc * 4);
        ts[rr][cc * 4 + 0] = v.x; ts[rr][cc * 4 + 1] = v.y;
        ts[rr][cc * 4 + 2] = v.z; ts[rr][cc * 4 + 3] = v.w;
    }
    __syncthreads();
    #pragma unroll
    for (int i = 0; i < 8; ++i) {
        int idx = tid + i * 256;
        int e = idx >> 5, w = idx & 31;
        float v0 = ts[2 * w][e], v1 = ts[2 * w + 1][e];
        float h0, l0, h1, l1;
        bsplit(v0, h0, l0); bsplit(v1, h1, l1);
        size_t off = ((size_t)(z * H_ + h) * DH_ + e) * D_ + d0 + 2 * w;
        *(uint32_t*)(g_wt_h + off) = packbf(h0, h1);
        *(uint32_t*)(g_wt_l + off) = packbf(l0, l1);
    }
}

__global__ __launch_bounds__(256) void conv_wo_kernel(const float* __restrict__ Wo)
{
    __shared__ float ts[64][65];
    const int tid = threadIdx.x;
    const int d0 = blockIdx.x * 64;
    const int f0 = blockIdx.y * 64;

    #pragma unroll
    for (int i = 0; i < 4; ++i) {
        int idx = tid + i * 256;
        int rr = idx >> 4, cc = idx & 15;
        float4 v = *(const float4*)(Wo + (size_t)(d0 + rr) * D_ + f0 + cc * 4);
        ts[rr][cc * 4 + 0] = v.x; ts[rr][cc * 4 + 1] = v.y;
        ts[rr][cc * 4 + 2] = v.z; ts[rr][cc * 4 + 3] = v.w;
    }
    __syncthreads();
    #pragma unroll
    for (int i = 0; i < 8; ++i) {
        int idx = tid + i * 256;
        int e = idx >> 5, w = idx & 31;
        float v0 = ts[2 * w][e], v1 = ts[2 * w + 1][e];
        float h0, l0, h1, l1;
        bsplit(v0, h0, l0); bsplit(v1, h1, l1);
        size_t off = (size_t)(f0 + e) * D_ + d0 + 2 * w;
        *(uint32_t*)(g_wo_h + off) = packbf(h0, h1);
        *(uint32_t*)(g_wo_l + off) = packbf(l0, l1);
    }
}

// ============================================================
// GEMM machinery: 128x128 tile, BK=32, double-buffered cp.async.
// NOW 512 threads / 16 warps; warp tile 32x32 (acc 32 regs).
// stage: Ah 0, Al 10240, Bh 20480, Bl 30720; rows 80B; 2 stages.
// ============================================================
#define GEMM_SMEM 81920
#define NKT (D_ / 32)

__device__ __forceinline__ void gemm_load_stage(uint32_t sbase,
    const __nv_bfloat16* p0, const __nv_bfloat16* p1,
    const __nv_bfloat16* p2, const __nv_bfloat16* p3, int tid)
{
    const __nv_bfloat16* p[4] = {p0, p1, p2, p3};
    #pragma unroll
    for (int i = 0; i < 4; ++i) {
        int idx = tid + i * 512;
        int arr = idx >> 9;
        int c = idx & 511;
        int r = c >> 2, col = c & 3;
        const __nv_bfloat16* src = p[arr] + (size_t)r * D_ + col * 8;
        uint32_t sa = sbase + arr * 10240 + r * 80 + col * 16;
        CP_A16(sa, src);
    }
}

__device__ __forceinline__ void mma_phase(uint32_t sbase, float acc[2][4][4], int wid, int lane)
{
    const int warp_m = wid & 3;
    const int warp_n = wid >> 2;
    const uint32_t a_hi_b = sbase;
    const uint32_t a_lo_b = sbase + 10240;
    const uint32_t b_hi_b = sbase + 20480;
    const uint32_t b_lo_b = sbase + 30720;

    const int a_row = warp_m * 32 + (lane & 15);
    const int a_kh  = (lane >> 4) << 3;
    const int b_row = warp_n * 32 + (lane & 7) + ((lane >> 4) << 3);
    const int b_kh  = ((lane >> 3) & 1) << 3;

    #pragma unroll
    for (int ks = 0; ks < 2; ++ks) {
        const int koff = ks * 16;
        uint32_t ah[2][4], bh[2][4], bl[2][4];
        #pragma unroll
        for (int i = 0; i < 2; ++i) {
            uint32_t addr = a_hi_b + ((a_row + i * 16) * 40 + koff + a_kh) * 2;
            LDSM_X4(ah[i][0], ah[i][1], ah[i][2], ah[i][3], addr);
        }
        #pragma unroll
        for (int jj = 0; jj < 2; ++jj) {
            uint32_t addr = b_hi_b + ((b_row + jj * 16) * 40 + koff + b_kh) * 2;
            LDSM_X4(bh[jj][0], bh[jj][1], bh[jj][2], bh[jj][3], addr);
            uint32_t addr2 = b_lo_b + ((b_row + jj * 16) * 40 + koff + b_kh) * 2;
            LDSM_X4(bl[jj][0], bl[jj][1], bl[jj][2], bl[jj][3], addr2);
        }
        #pragma unroll
        for (int i = 0; i < 2; ++i)
            #pragma unroll
            for (int j = 0; j < 4; ++j) {
                int jj = j >> 1, s = (j & 1) * 2;
                mma16816(acc[i][j], ah[i][0], ah[i][1], ah[i][2], ah[i][3], bh[jj][s], bh[jj][s + 1]);
                mma16816(acc[i][j], ah[i][0], ah[i][1], ah[i][2], ah[i][3], bl[jj][s], bl[jj][s + 1]);
            }
        #pragma unroll
        for (int i = 0; i < 2; ++i) {
            uint32_t addr = a_lo_b + ((a_row + i * 16) * 40 + koff + a_kh) * 2;
            LDSM_X4(ah[i][0], ah[i][1], ah[i][2], ah[i][3], addr);
        }
        #pragma unroll
        for (int i = 0; i < 2; ++i)
            #pragma unroll
            for (int j = 0; j < 4; ++j) {
                int jj = j >> 1, s = (j & 1) * 2;
                mma16816(acc[i][j], ah[i][0], ah[i][1], ah[i][2], ah[i][3], bh[jj][s], bh[jj][s + 1]);
            }
    }
}

// ============================================================
// Kernel 1: QKV projection. grid = (64, 8, 3), block 512.
// ============================================================
__global__ __launch_bounds__(512, 1) void qkv_mma_kernel()
{
    extern __shared__ char sm[];
    const uint32_t smb = smem_u32(sm);
    const int tid = threadIdx.x;
    const int wid = tid >> 5;
    const int lane = tid & 31;

    const int z = blockIdx.z;
    const int hp = blockIdx.y;
    const int m0 = blockIdx.x * 128;

    __nv_bfloat16* outh = (z == 0) ? g_qh : ((z == 1) ? g_kh : g_vh);
    __nv_bfloat16* outl = (z == 0) ? g_ql : ((z == 1) ? g_kl : g_vl);
    const float scale = (z == 0) ? 0.125f : 1.0f;

    const __nv_bfloat16* ah = g_xh + (size_t)m0 * D_;
    const __nv_bfloat16* al = g_xl + (size_t)m0 * D_;
    const __nv_bfloat16* bh = g_wt_h + (size_t)(z * H_ + hp * 2) * DH_ * D_;
    const __nv_bfloat16* bl = g_wt_l + (size_t)(z * H_ + hp * 2) * DH_ * D_;

    float acc[2][4][4];
    #pragma unroll
    for (int i = 0; i < 2; ++i)
        #pragma unroll
        for (int j = 0; j < 4; ++j)
            #pragma unroll
            for (int q = 0; q < 4; ++q) acc[i][j][q] = 0.f;

    gemm_load_stage(smb, ah, al, bh, bl, tid);
    CP_COMMIT();

    for (int kt = 0; kt < NKT; ++kt) {
        if (kt + 1 < NKT) {
            int k1 = (kt + 1) * 32;
            gemm_load_stage(smb + ((kt + 1) & 1) * 40960,
                            ah + k1, al + k1, bh + k1, bl + k1, tid);
            CP_COMMIT();
            CP_WAIT(1);
        } else {
            CP_WAIT(0);
        }
        __syncthreads();
        mma_phase(smb + (kt & 1) * 40960, acc, wid, lane);
        __syncthreads();
    }

    const int warp_m = wid & 3;
    const int warp_n = wid >> 2;
    #pragma unroll
    for (int i = 0; i < 2; ++i) {
        #pragma unroll
        for (int j = 0; j < 4; ++j) {
            int r0 = m0 + warp_m * 32 + i * 16 + (lane >> 2);
            int col = warp_n * 32 + j * 8 + (lane & 3) * 2;
            int hh = hp * 2 + (col >> 6);
            int ee = col & 63;
            #pragma unroll
            for (int half = 0; half < 2; ++half) {
                int r = r0 + half * 8;
                int b = r >> 11, s = r & 2047;
                float v0 = acc[i][j][2 * half] * scale;
                float v1 = acc[i][j][2 * half + 1] * scale;
                float h0, l0, h1, l1;
                bsplit(v0, h0, l0); bsplit(v1, h1, l1);
                size_t off = ((size_t)(b * H_ + hh) * S_ + s) * DH_ + ee;
                *(uint32_t*)(outh + off) = packbf(h0, h1);
                *(uint32_t*)(outl + off) = packbf(l0, l1);
            }
        }
    }
}

// ============================================================
// Kernel 3: output projection. grid = (64, 8), block 512.
// ============================================================
__global__ __launch_bounds__(512, 1) void out_proj_mma_kernel(
    const float* __restrict__ bo, float* __restrict__ out)
{
    extern __shared__ char sm[];
    const uint32_t smb = smem_u32(sm);
    const int tid = threadIdx.x;
    const int wid = tid >> 5;
    const int lane = tid & 31;

    const int n0 = blockIdx.y * 128;
    const int m0 = blockIdx.x * 128;

    const __nv_bfloat16* ah = g_ch + (size_t)m0 * D_;
    const __nv_bfloat16* al = g_cl + (size_t)m0 * D_;
    const __nv_bfloat16* bh = g_wo_h + (size_t)n0 * D_;
    const __nv_bfloat16* bl = g_wo_l + (size_t)n0 * D_;

    float acc[2][4][4];
    #pragma unroll
    for (int i = 0; i < 2; ++i)
        #pragma unroll
        for (int j = 0; j < 4; ++j)
            #pragma unroll
            for (int q = 0; q < 4; ++q) acc[i][j][q] = 0.f;

    gemm_load_stage(smb, ah, al, bh, bl, tid);
    CP_COMMIT();

    for (int kt = 0; kt < NKT; ++kt) {
        if (kt + 1 < NKT) {
            int k1 = (kt + 1) * 32;
            gemm_load_stage(smb + ((kt + 1) & 1) * 40960,
                            ah + k1, al + k1, bh + k1, bl + k1, tid);
            CP_COMMIT();
            CP_WAIT(1);
        } else {
            CP_WAIT(0);
        }
        __syncthreads();
        mma_phase(smb + (kt & 1) * 40960, acc, wid, lane);
        __syncthreads();
    }

    const int warp_m = wid & 3;
    const int warp_n = wid >> 2;
    #pragma unroll
    for (int i = 0; i < 2; ++i) {
        #pragma unroll
        for (int j = 0; j < 4; ++j) {
            int r0 = m0 + warp_m * 32 + i * 16 + (lane >> 2);
            int col = n0 + warp_n * 32 + j * 8 + (lane & 3) * 2;
            float b0 = bo[col], b1 = bo[col + 1];
            {
                float2 v; v.x = acc[i][j][0] + b0; v.y = acc[i][j][1] + b1;
                *(float2*)(out + (size_t)r0 * D_ + col) = v;
            }
            {
                float2 v; v.x = acc[i][j][2] + b0; v.y = acc[i][j][3] + b1;
                *(float2*)(out + (size_t)(r0 + 8) * D_ + col) = v;
            }
        }
    }
}

// ============================================================
// Kernel 2: causal flash attention (unchanged R6).
// ============================================================
#define ATTN_SMEM 110592

__device__ __forceinline__ void attn_load_kv(uint32_t kvb,
    const __nv_bfloat16* kh, const __nv_bfloat16* kl,
    const __nv_bfloat16* vh, const __nv_bfloat16* vl, int tid)
{
    const __nv_bfloat16* p[4] = {kh, kl, vh, vl};
    #pragma unroll
    for (int i = 0; i < 8; ++i) {
        int idx = tid + i * 256;
        int arr = idx >> 9;
        int c = idx & 511;
        int r = c >> 3, c8 = c & 7;
        const __nv_bfloat16* src = p[arr] + (size_t)r * DH_ + c8 * 8;
        uint32_t sa = kvb + arr * 9216 + r * 144 + c8 * 16;
        CP_A16(sa, src);
    }
}

__global__ __launch_bounds__(256, 1) void attn_mma_kernel()
{
    extern __shared__ char sm[];
    const uint32_t smb = smem_u32(sm);
    const int tid = threadIdx.x;
    const int wm = tid >> 5;
    const int lane = tid & 31;

    const int bh = blockIdx.y;
    const int qb = (gridDim.x - 1) - blockIdx.x;
    const int kmax = 2 * qb + 2;

    const uint32_t Qh_b = smb;
    const uint32_t Ql_b = smb + 18432;

    const __nv_bfloat16* kh_g = g_kh + (size_t)bh * S_ * DH_;
    const __nv_bfloat16* kl_g = g_kl + (size_t)bh * S_ * DH_;
    const __nv_bfloat16* vh_g = g_vh + (size_t)bh * S_ * DH_;
    const __nv_bfloat16* vl_g = g_vl + (size_t)bh * S_ * DH_;

    attn_load_kv(smb + 36864, kh_g, kl_g, vh_g, vl_g, tid);
    CP_COMMIT();

    {
        const __nv_bfloat16* qh_g = g_qh + ((size_t)bh * S_ + qb * 128) * DH_;
        const __nv_bfloat16* ql_g = g_ql + ((size_t)bh * S_ + qb * 128) * DH_;
        #pragma unroll
        for (int i = 0; i < 4; ++i) {
            int idx = tid + i * 256;
            int r = idx >> 3, c8 = idx & 7;
            *(uint4*)(sm + (Qh_b - smb) + r * 144 + c8 * 16) =
                *(const uint4*)(qh_g + (size_t)r * DH_ + c8 * 8);
            *(uint4*)(sm + (Ql_b - smb) + r * 144 + c8 * 16) =
                *(const uint4*)(ql_g + (size_t)r * DH_ + c8 * 8);
        }
    }
    __syncthreads();

    uint32_t qh[4][4], ql[4][4];
    {
        const int ar = wm * 16 + (lane & 15);
        const int koff = (lane >> 4) << 3;
        #pragma unroll
        for (int ks = 0; ks < 4; ++ks) {
            LDSM_X4(qh[ks][0], qh[ks][1], qh[ks][2], qh[ks][3],
                    Qh_b + ar * 144 + (ks * 16 + koff) * 2);
            LDSM_X4(ql[ks][0], ql[ks][1], ql[ks][2], ql[ks][3],
                    Ql_b + ar * 144 + (ks * 16 + koff) * 2);
        }
    }

    float mA = -3.0e38f, mB = -3.0e38f, lA = 0.f, lB = 0.f;
    float oacc[8][4];
    #pragma unroll
    for (int t = 0; t < 8; ++t)
        #pragma unroll
        for (int q = 0; q < 4; ++q) oacc[t][q] = 0.f;

    const int kb_row  = (lane & 7) + ((lane >> 4) << 3);
    const int kb_koff = ((lane >> 3) & 1) << 3;
    const int vb_row  = (lane & 7) + (((lane >> 3) & 1) << 3);
    const int vb_eoff = (lane >> 4) << 3;

    const int rA_g = qb * 128 + wm * 16 + (lane >> 2);

    for (int kt = 0; kt < kmax; ++kt) {
        if (kt + 1 < kmax) {
            size_t koff = (size_t)(kt + 1) * 64 * DH_;
            attn_load_kv(smb + 36864 + ((kt + 1) & 1) * 36864,
                         kh_g + koff, kl_g + koff, vh_g + koff, vl_g + koff, tid);
            CP_COMMIT();
            CP_WAIT(1);
        } else {
            CP_WAIT(0);
        }
        __syncthreads();

        const uint32_t kvb = smb + 36864 + (kt & 1) * 36864;
        const uint32_t Kh_b = kvb, Kl_b = kvb + 9216, Vh_b = kvb + 18432, Vl_b = kvb + 27648;

        float sacc[8][4];
        #pragma unroll
        for (int t = 0; t < 8; ++t)
            #pragma unroll
            for (int q = 0; q < 4; ++q) sacc[t][q] = 0.f;

        #pragma unroll
        for (int ks = 0; ks < 4; ++ks) {
            #pragma unroll
            for (int np = 0; np < 4; ++np) {
                uint32_t row = np * 16 + kb_row;
                uint32_t ko  = ks * 16 + kb_koff;
                uint32_t b0, b1, b2, b3, c0, c1, c2, c3;
                LDSM_X4(b0, b1, b2, b3, Kh_b + row * 144 + ko * 2);
                LDSM_X4(c0, c1, c2, c3, Kl_b + row * 144 + ko * 2);
                mma16816(sacc[2 * np],     qh[ks][0], qh[ks][1], qh[ks][2], qh[ks][3], b0, b1);
                mma16816(sacc[2 * np],     qh[ks][0], qh[ks][1], qh[ks][2], qh[ks][3], c0, c1);
                mma16816(sacc[2 * np],     ql[ks][0], ql[ks][1], ql[ks][2], ql[ks][3], b0, b1);
                mma16816(sacc[2 * np + 1], qh[ks][0], qh[ks][1], qh[ks][2], qh[ks][3], b2, b3);
                mma16816(sacc[2 * np + 1], qh[ks][0], qh[ks][1], qh[ks][2], qh[ks][3], c2, c3);
                mma16816(sacc[2 * np + 1], ql[ks][0], ql[ks][1], ql[ks][2], ql[ks][3], b2, b3);
            }
        }

        if (kt >= 2 * qb) {
            const int c0g = kt * 64 + 2 * (lane & 3);
            #pragma unroll
            for (int t = 0; t < 8; ++t) {
                int c = c0g + 8 * t;
                if (c     > rA_g)     sacc[t][0] = -3.0e38f;
                if (c + 1 > rA_g)     sacc[t][1] = -3.0e38f;
                if (c     > rA_g + 8) sacc[t][2] = -3.0e38f;
                if (c + 1 > rA_g + 8) sacc[t][3] = -3.0e38f;
            }
        }

        float mtA = -3.0e38f, mtB = -3.0e38f;
        #pragma unroll
        for (int t = 0; t < 8; ++t) {
            mtA = fmaxf(mtA, fmaxf(sacc[t][0], sacc[t][1]));
            mtB = fmaxf(mtB, fmaxf(sacc[t][2], sacc[t][3]));
        }
        mtA = fmaxf(mtA, __shfl_xor_sync(0xffffffffu, mtA, 1));
        mtA = fmaxf(mtA, __shfl_xor_sync(0xffffffffu, mtA, 2));
        mtB = fmaxf(mtB, __shfl_xor_sync(0xffffffffu, mtB, 1));
        mtB = fmaxf(mtB, __shfl_xor_sync(0xffffffffu, mtB, 2));

        float mnA = fmaxf(mA, mtA), mnB = fmaxf(mB, mtB);
        float corrA = __expf(mA - mnA), corrB = __expf(mB - mnB);

        float rsA = 0.f, rsB = 0.f;
        #pragma unroll
        for (int t = 0; t < 8; ++t) {
            float p0 = __expf(sacc[t][0] - mnA); sacc[t][0] = p0; rsA += p0;
            float p1 = __expf(sacc[t][1] - mnA); sacc[t][1] = p1; rsA += p1;
            float p2 = __expf(sacc[t][2] - mnB); sacc[t][2] = p2; rsB += p2;
            float p3 = __expf(sacc[t][3] - mnB); sacc[t][3] = p3; rsB += p3;
        }
        rsA += __shfl_xor_sync(0xffffffffu, rsA, 1);
        rsA += __shfl_xor_sync(0xffffffffu, rsA, 2);
        rsB += __shfl_xor_sync(0xffffffffu, rsB, 1);
        rsB += __shfl_xor_sync(0xffffffffu, rsB, 2);

        lA = lA * corrA + rsA;
        lB = lB * corrB + rsB;
        #pragma unroll
        for (int t = 0; t < 8; ++t) {
            oacc[t][0] *= corrA; oacc[t][1] *= corrA;
            oacc[t][2] *= corrB; oacc[t][3] *= corrB;
        }
        mA = mnA; mB = mnB;

        #pragma unroll
        for (int ks = 0; ks < 4; ++ks) {
            uint32_t pfh[4], pfl[4];
            {
                float h00, l00, h01, l01, h10, l10, h11, l11;
                bsplit(sacc[2 * ks][0], h00, l00); bsplit(sacc[2 * ks][1], h01, l01);
                bsplit(sacc[2 * ks][2], h10, l10); bsplit(sacc[2 * ks][3], h11, l11);
                pfh[0] = packbf(h00, h01); pfl[0] = packbf(l00, l01);
                pfh[1] = packbf(h10, h11); pfl[1] = packbf(l10, l11);
                bsplit(sacc[2 * ks + 1][0], h00, l00); bsplit(sacc[2 * ks + 1][1], h01, l01);
                bsplit(sacc[2 * ks + 1][2], h10, l10); bsplit(sacc[2 * ks + 1][3], h11, l11);
                pfh[2] = packbf(h00, h01); pfl[2] = packbf(l00, l01);
                pfh[3] = packbf(h10, h11); pfl[3] = packbf(l10, l11);
            }
            #pragma unroll
            for (int ep = 0; ep < 4; ++ep) {
                uint32_t row = ks * 16 + vb_row;
                uint32_t eo  = ep * 16 + vb_eoff;
                uint32_t v0, v1, v2, v3, w0, w1, w2, w3;
                LDSM_X4_T(v0, v1, v2, v3, Vh_b + row * 144 + eo * 2);
                LDSM_X4_T(w0, w1, w2, w3, Vl_b + row * 144 + eo * 2);
                mma16816(oacc[2 * ep],     pfh[0], pfh[1], pfh[2], pfh[3], v0, v1);
                mma16816(oacc[2 * ep],     pfh[0], pfh[1], pfh[2], pfh[3], w0, w1);
                mma16816(oacc[2 * ep],     pfl[0], pfl[1], pfl[2], pfl[3], v0, v1);
                mma16816(oacc[2 * ep + 1], pfh[0], pfh[1], pfh[2], pfh[3], v2, v3);
                mma16816(oacc[2 * ep + 1], pfh[0], pfh[1], pfh[2], pfh[3], w2, w3);
                mma16816(oacc[2 * ep + 1], pfl[0], pfl[1], pfl[2], pfl[3], v2, v3);
            }
        }
        __syncthreads();
    }

    const float invA = 1.0f / lA;
    const float invB = 1.0f / lB;
    const int b = bh >> 4, h = bh & 15;
    const int e0 = 2 * (lane & 3);
    size_t baseA = ((size_t)b * S_ + rA_g) * D_ + h * DH_;
    size_t baseB = ((size_t)b * S_ + rA_g + 8) * D_ + h * DH_;
    #pragma unroll
    for (int t = 0; t < 8; ++t) {
        int e = 8 * t + e0;
        float a0 = oacc[t][0] * invA, a1 = oacc[t][1] * invA;
        float b0v = oacc[t][2] * invB, b1v = oacc[t][3] * invB;
        float h0, l0, h1, l1;
        bsplit(a0, h0, l0); bsplit(a1, h1, l1);
        *(uint32_t*)(g_ch + baseA + e) = packbf(h0, h1);
        *(uint32_t*)(g_cl + baseA + e) = packbf(l0, l1);
        bsplit(b0v, h0, l0); bsplit(b1v, h1, l1);
        *(uint32_t*)(g_ch + baseB + e) = packbf(h0, h1);
        *(uint32_t*)(g_cl + baseB + e) = packbf(l0, l1);
    }
}

// ============================================================
extern "C" void kernel_launch(void* const* d_in, const int* in_sizes, int n_in,
                              void* d_out, int out_size)
{
    const float* x  = (const float*)d_in[0];
    const float* Wq = (const float*)d_in[1];
    const float* Wk = (const float*)d_in[2];
    const float* Wv = (const float*)d_in[3];
    const float* Wo = (const float*)d_in[4];
    const float* bo = (const float*)d_in[5];
    float* out = (float*)d_out;

    cudaFuncSetAttribute(qkv_mma_kernel, cudaFuncAttributeMaxDynamicSharedMemorySize, GEMM_SMEM);
    cudaFuncSetAttribute(out_proj_mma_kernel, cudaFuncAttributeMaxDynamicSharedMemorySize, GEMM_SMEM);
    cudaFuncSetAttribute(attn_mma_kernel, cudaFuncAttributeMaxDynamicSharedMemorySize, ATTN_SMEM);

    conv_x_kernel<<<C_ELEMS / 4 / 256, 256>>>(x);
    conv_w_kernel<<<dim3(D_ / 64, H_, 3), 256>>>(Wq, Wk, Wv);
    conv_wo_kernel<<<dim3(D_ / 64, D_ / 64), 256>>>(Wo);
    qkv_mma_kernel<<<dim3(MROWS / 128, H_ / 2, 3), 512, GEMM_SMEM>>>();
    attn_mma_kernel<<<dim3(S_ / 128, B_ * H_), 256, ATTN_SMEM>>>();
    out_proj_mma_kernel<<<dim3(MROWS / 128, D_ / 128), 512, GEMM_SMEM>>>(bo, out);
}

// round 8
// speedup vs baseline: 1.0654x; 1.0654x over previous
#include <cuda_runtime.h>
#include <cuda_bf16.h>
#include <cstdint>

#define B_ 4
#define S_ 2048
#define D_ 1024
#define H_ 16
#define DH_ 64
#define MROWS (B_ * S_)
#define QKV_ELEMS (B_ * H_ * S_ * DH_)   // 8388608
#define C_ELEMS   (B_ * S_ * D_)         // 8388608

// -------- bf16 hi/lo scratch (no allocation) --------
__device__ __nv_bfloat16 g_xh[C_ELEMS],  g_xl[C_ELEMS];
__device__ __nv_bfloat16 g_wt_h[3 * H_ * DH_ * D_], g_wt_l[3 * H_ * DH_ * D_];
__device__ __nv_bfloat16 g_wo_h[D_ * D_], g_wo_l[D_ * D_];
__device__ __nv_bfloat16 g_qh[QKV_ELEMS], g_ql[QKV_ELEMS];
__device__ __nv_bfloat16 g_kh[QKV_ELEMS], g_kl[QKV_ELEMS];
__device__ __nv_bfloat16 g_vh[QKV_ELEMS], g_vl[QKV_ELEMS];
__device__ __nv_bfloat16 g_ch[C_ELEMS],  g_cl[C_ELEMS];

// ================= helpers =================
__device__ __forceinline__ uint32_t smem_u32(const void* p) {
    uint32_t a;
    asm("{ .reg .u64 t; cvta.to.shared.u64 t, %1; cvt.u32.u64 %0, t; }" : "=r"(a) : "l"(p));
    return a;
}
__device__ __forceinline__ void bsplit(float v, float& h, float& l) {
    __nv_bfloat16 bh = __float2bfloat16(v);
    h = __bfloat162float(bh);
    l = v - h;
}
__device__ __forceinline__ uint32_t packbf(float lo_elem, float hi_elem) {
    uint32_t r;
    asm("cvt.rn.bf16x2.f32 %0, %1, %2;" : "=r"(r) : "f"(hi_elem), "f"(lo_elem));
    return r;
}
#define LDSM_X4(r0, r1, r2, r3, addr) \
    asm volatile("ldmatrix.sync.aligned.m8n8.x4.shared.b16 {%0,%1,%2,%3}, [%4];" \
        : "=r"(r0), "=r"(r1), "=r"(r2), "=r"(r3) : "r"(addr))
#define LDSM_X4_T(r0, r1, r2, r3, addr) \
    asm volatile("ldmatrix.sync.aligned.m8n8.x4.trans.shared.b16 {%0,%1,%2,%3}, [%4];" \
        : "=r"(r0), "=r"(r1), "=r"(r2), "=r"(r3) : "r"(addr))
#define CP_A16(sa, gp) asm volatile("cp.async.ca.shared.global [%0], [%1], 16;" :: "r"(sa), "l"(gp))
#define CP_COMMIT()    asm volatile("cp.async.commit_group;" ::: "memory")
#define CP_WAIT(n)     asm volatile("cp.async.wait_group %0;" :: "n"(n) : "memory")

__device__ __forceinline__ void mma16816(float* c,
    uint32_t a0, uint32_t a1, uint32_t a2, uint32_t a3, uint32_t b0, uint32_t b1)
{
    asm volatile(
        "mma.sync.aligned.m16n8k16.row.col.f32.bf16.bf16.f32 "
        "{%0,%1,%2,%3}, {%4,%5,%6,%7}, {%8,%9}, {%0,%1,%2,%3};"
        : "+f"(c[0]), "+f"(c[1]), "+f"(c[2]), "+f"(c[3])
        : "r"(a0), "r"(a1), "r"(a2), "r"(a3), "r"(b0), "r"(b1));
}

// ============================================================
// Preconversion kernels (unchanged R6)
// ============================================================
__global__ __launch_bounds__(256) void conv_x_kernel(const float* __restrict__ x)
{
    int i = blockIdx.x * 256 + threadIdx.x;
    float4 v = *(const float4*)(x + 4 * (size_t)i);
    float hx, lx, hy, ly, hz, lz, hw, lw;
    bsplit(v.x, hx, lx); bsplit(v.y, hy, ly);
    bsplit(v.z, hz, lz); bsplit(v.w, hw, lw);
    uint2 wh, wl;
    wh.x = packbf(hx, hy); wh.y = packbf(hz, hw);
    wl.x = packbf(lx, ly); wl.y = packbf(lz, lw);
    *(uint2*)(g_xh + 4 * (size_t)i) = wh;
    *(uint2*)(g_xl + 4 * (size_t)i) = wl;
}

__global__ __launch_bounds__(256) void conv_w_kernel(
    const float* __restrict__ Wq, const float* __restrict__ Wk, const float* __restrict__ Wv)
{
    __shared__ float ts[64][65];
    const int tid = threadIdx.x;
    const int d0 = blockIdx.x * 64;
    const int h  = blockIdx.y;
    const int z  = blockIdx.z;
    const float* W = (z == 0) ? Wq : ((z == 1) ? Wk : Wv);
    const float* src = W + (size_t)h * D_ * DH_;

    #pragma unroll
    for (int i = 0; i < 4; ++i) {
        int idx = tid + i * 256;
        int rr = idx >> 4, cc = idx & 15;
        float4 v = *(const float4*)(src + (size_t)(d0 + rr) * DH_ + cc * 4);
        ts[rr][cc * 4 + 0] = v.x; ts[rr][cc * 4 + 1] = v.y;
        ts[rr][cc * 4 + 2] = v.z; ts[rr][cc * 4 + 3] = v.w;
    }
    __syncthreads();
    #pragma unroll
    for (int i = 0; i < 8; ++i) {
        int idx = tid + i * 256;
        int e = idx >> 5, w = idx & 31;
        float v0 = ts[2 * w][e], v1 = ts[2 * w + 1][e];
        float h0, l0, h1, l1;
        bsplit(v0, h0, l0); bsplit(v1, h1, l1);
        size_t off = ((size_t)(z * H_ + h) * DH_ + e) * D_ + d0 + 2 * w;
        *(uint32_t*)(g_wt_h + off) = packbf(h0, h1);
        *(uint32_t*)(g_wt_l + off) = packbf(l0, l1);
    }
}

__global__ __launch_bounds__(256) void conv_wo_kernel(const float* __restrict__ Wo)
{
    __shared__ float ts[64][65];
    const int tid = threadIdx.x;
    const int d0 = blockIdx.x * 64;
    const int f0 = blockIdx.y * 64;

    #pragma unroll
    for (int i = 0; i < 4; ++i) {
        int idx = tid + i * 256;
        int rr = idx >> 4, cc = idx & 15;
        float4 v = *(const float4*)(Wo + (size_t)(d0 + rr) * D_ + f0 + cc * 4);
        ts[rr][cc * 4 + 0] = v.x; ts[rr][cc * 4 + 1] = v.y;
        ts[rr][cc * 4 + 2] = v.z; ts[rr][cc * 4 + 3] = v.w;
    }
    __syncthreads();
    #pragma unroll
    for (int i = 0; i < 8; ++i) {
        int idx = tid + i * 256;
        int e = idx >> 5, w = idx & 31;
        float v0 = ts[2 * w][e], v1 = ts[2 * w + 1][e];
        float h0, l0, h1, l1;
        bsplit(v0, h0, l0); bsplit(v1, h1, l1);
        size_t off = (size_t)(f0 + e) * D_ + d0 + 2 * w;
        *(uint32_t*)(g_wo_h + off) = packbf(h0, h1);
        *(uint32_t*)(g_wo_l + off) = packbf(l0, l1);
    }
}

// ============================================================
// GEMM machinery: 128x128 tile, BK=32, 256 thr (8 warps, 64x32 warp tile),
// THREE-stage cp.async pipeline, ONE __syncthreads per ktile.
// stage: Ah 0, Al 10240, Bh 20480, Bl 30720; rows 80B; stage=40960B; x3.
// ============================================================
#define GEMM_STAGE 40960
#define GEMM_SMEM (3 * GEMM_STAGE)
#define NKT (D_ / 32)

__device__ __forceinline__ void gemm_load_stage(uint32_t sbase,
    const __nv_bfloat16* p0, const __nv_bfloat16* p1,
    const __nv_bfloat16* p2, const __nv_bfloat16* p3, int tid)
{
    const __nv_bfloat16* p[4] = {p0, p1, p2, p3};
    #pragma unroll
    for (int i = 0; i < 8; ++i) {
        int idx = tid + i * 256;
        int arr = idx >> 9;
        int c = idx & 511;
        int r = c >> 2, col = c & 3;
        const __nv_bfloat16* src = p[arr] + (size_t)r * D_ + col * 8;
        uint32_t sa = sbase + arr * 10240 + r * 80 + col * 16;
        CP_A16(sa, src);
    }
}

__device__ __forceinline__ void mma_phase(uint32_t sbase, float acc[4][4][4], int wid, int lane)
{
    const int warp_m = wid & 1;
    const int warp_n = wid >> 1;
    const uint32_t a_hi_b = sbase;
    const uint32_t a_lo_b = sbase + 10240;
    const uint32_t b_hi_b = sbase + 20480;
    const uint32_t b_lo_b = sbase + 30720;

    const int a_row = warp_m * 64 + (lane & 15);
    const int a_kh  = (lane >> 4) << 3;
    const int b_row = warp_n * 32 + (lane & 7) + ((lane >> 4) << 3);
    const int b_kh  = ((lane >> 3) & 1) << 3;

    #pragma unroll
    for (int ks = 0; ks < 2; ++ks) {
        const int koff = ks * 16;
        uint32_t ah[4][4], bh[2][4], bl[2][4];
        #pragma unroll
        for (int i = 0; i < 4; ++i) {
            uint32_t addr = a_hi_b + ((a_row + i * 16) * 40 + koff + a_kh) * 2;
            LDSM_X4(ah[i][0], ah[i][1], ah[i][2], ah[i][3], addr);
        }
        #pragma unroll
        for (int jj = 0; jj < 2; ++jj) {
            uint32_t addr = b_hi_b + ((b_row + jj * 16) * 40 + koff + b_kh) * 2;
            LDSM_X4(bh[jj][0], bh[jj][1], bh[jj][2], bh[jj][3], addr);
            uint32_t addr2 = b_lo_b + ((b_row + jj * 16) * 40 + koff + b_kh) * 2;
            LDSM_X4(bl[jj][0], bl[jj][1], bl[jj][2], bl[jj][3], addr2);
        }
        #pragma unroll
        for (int i = 0; i < 4; ++i)
            #pragma unroll
            for (int j = 0; j < 4; ++j) {
                int jj = j >> 1, s = (j & 1) * 2;
                mma16816(acc[i][j], ah[i][0], ah[i][1], ah[i][2], ah[i][3], bh[jj][s], bh[jj][s + 1]);
                mma16816(acc[i][j], ah[i][0], ah[i][1], ah[i][2], ah[i][3], bl[jj][s], bl[jj][s + 1]);
            }
        #pragma unroll
        for (int i = 0; i < 4; ++i) {
            uint32_t addr = a_lo_b + ((a_row + i * 16) * 40 + koff + a_kh) * 2;
            LDSM_X4(ah[i][0], ah[i][1], ah[i][2], ah[i][3], addr);
        }
        #pragma unroll
        for (int i = 0; i < 4; ++i)
            #pragma unroll
            for (int j = 0; j < 4; ++j) {
                int jj = j >> 1, s = (j & 1) * 2;
                mma16816(acc[i][j], ah[i][0], ah[i][1], ah[i][2], ah[i][3], bh[jj][s], bh[jj][s + 1]);
            }
    }
}

// shared 3-stage mainloop
#define GEMM_MAINLOOP(AH, AL, BH, BL)                                          \
    gemm_load_stage(smb, (AH), (AL), (BH), (BL), tid);                         \
    CP_COMMIT();                                                               \
    gemm_load_stage(smb + GEMM_STAGE, (AH) + 32, (AL) + 32, (BH) + 32, (BL) + 32, tid); \
    CP_COMMIT();                                                               \
    for (int kt = 0; kt < NKT; ++kt) {                                         \
        if (kt + 1 < NKT) { CP_WAIT(1); } else { CP_WAIT(0); }                 \
        __syncthreads();                                                       \
        if (kt + 2 < NKT) {                                                    \
            int k2 = (kt + 2) * 32;                                            \
            gemm_load_stage(smb + ((kt + 2) % 3) * GEMM_STAGE,                 \
                            (AH) + k2, (AL) + k2, (BH) + k2, (BL) + k2, tid);  \
            CP_COMMIT();                                                       \
        }                                                                      \
        mma_phase(smb + (kt % 3) * GEMM_STAGE, acc, wid, lane);                \
    }

// ============================================================
// Kernel 1: QKV projection. grid = (64, 8, 3), block 256.
// ============================================================
__global__ __launch_bounds__(256, 1) void qkv_mma_kernel()
{
    extern __shared__ char sm[];
    const uint32_t smb = smem_u32(sm);
    const int tid = threadIdx.x;
    const int wid = tid >> 5;
    const int lane = tid & 31;

    const int z = blockIdx.z;
    const int hp = blockIdx.y;
    const int m0 = blockIdx.x * 128;

    __nv_bfloat16* outh = (z == 0) ? g_qh : ((z == 1) ? g_kh : g_vh);
    __nv_bfloat16* outl = (z == 0) ? g_ql : ((z == 1) ? g_kl : g_vl);
    const float scale = (z == 0) ? 0.125f : 1.0f;

    const __nv_bfloat16* ah = g_xh + (size_t)m0 * D_;
    const __nv_bfloat16* al = g_xl + (size_t)m0 * D_;
    const __nv_bfloat16* bh = g_wt_h + (size_t)(z * H_ + hp * 2) * DH_ * D_;
    const __nv_bfloat16* bl = g_wt_l + (size_t)(z * H_ + hp * 2) * DH_ * D_;

    float acc[4][4][4];
    #pragma unroll
    for (int i = 0; i < 4; ++i)
        #pragma unroll
        for (int j = 0; j < 4; ++j)
            #pragma unroll
            for (int q = 0; q < 4; ++q) acc[i][j][q] = 0.f;

    GEMM_MAINLOOP(ah, al, bh, bl)

    const int warp_m = wid & 1;
    const int warp_n = wid >> 1;
    #pragma unroll
    for (int i = 0; i < 4; ++i) {
        #pragma unroll
        for (int j = 0; j < 4; ++j) {
            int r0 = m0 + warp_m * 64 + i * 16 + (lane >> 2);
            int col = warp_n * 32 + j * 8 + (lane & 3) * 2;
            int hh = hp * 2 + (col >> 6);
            int ee = col & 63;
            #pragma unroll
            for (int half = 0; half < 2; ++half) {
                int r = r0 + half * 8;
                int b = r >> 11, s = r & 2047;
                float v0 = acc[i][j][2 * half] * scale;
                float v1 = acc[i][j][2 * half + 1] * scale;
                float h0, l0, h1, l1;
                bsplit(v0, h0, l0); bsplit(v1, h1, l1);
                size_t off = ((size_t)(b * H_ + hh) * S_ + s) * DH_ + ee;
                *(uint32_t*)(outh + off) = packbf(h0, h1);
                *(uint32_t*)(outl + off) = packbf(l0, l1);
            }
        }
    }
}

// ============================================================
// Kernel 3: output projection. grid = (64, 8), block 256.
// ============================================================
__global__ __launch_bounds__(256, 1) void out_proj_mma_kernel(
    const float* __restrict__ bo, float* __restrict__ out)
{
    extern __shared__ char sm[];
    const uint32_t smb = smem_u32(sm);
    const int tid = threadIdx.x;
    const int wid = tid >> 5;
    const int lane = tid & 31;

    const int n0 = blockIdx.y * 128;
    const int m0 = blockIdx.x * 128;

    const __nv_bfloat16* ah = g_ch + (size_t)m0 * D_;
    const __nv_bfloat16* al = g_cl + (size_t)m0 * D_;
    const __nv_bfloat16* bh = g_wo_h + (size_t)n0 * D_;
    const __nv_bfloat16* bl = g_wo_l + (size_t)n0 * D_;

    float acc[4][4][4];
    #pragma unroll
    for (int i = 0; i < 4; ++i)
        #pragma unroll
        for (int j = 0; j < 4; ++j)
            #pragma unroll
            for (int q = 0; q < 4; ++q) acc[i][j][q] = 0.f;

    GEMM_MAINLOOP(ah, al, bh, bl)

    const int warp_m = wid & 1;
    const int warp_n = wid >> 1;
    #pragma unroll
    for (int i = 0; i < 4; ++i) {
        #pragma unroll
        for (int j = 0; j < 4; ++j) {
            int r0 = m0 + warp_m * 64 + i * 16 + (lane >> 2);
            int col = n0 + warp_n * 32 + j * 8 + (lane & 3) * 2;
            float b0 = bo[col], b1 = bo[col + 1];
            {
                float2 v; v.x = acc[i][j][0] + b0; v.y = acc[i][j][1] + b1;
                *(float2*)(out + (size_t)r0 * D_ + col) = v;
            }
            {
                float2 v; v.x = acc[i][j][2] + b0; v.y = acc[i][j][3] + b1;
                *(float2*)(out + (size_t)(r0 + 8) * D_ + col) = v;
            }
        }
    }
}

// ============================================================
// Kernel 2: causal flash attention, 3-stage KV pipeline, 1 barrier/tile.
// Smem: Qh 0, Ql 18432; KV stages at 36864 + st*36864 (st=0..2):
//   Kh +0, Kl +9216, Vh +18432, Vl +27648 (rows 144B).
// ============================================================
#define KV_STAGE 36864
#define ATTN_SMEM (36864 + 3 * KV_STAGE)

__device__ __forceinline__ void attn_load_kv(uint32_t kvb,
    const __nv_bfloat16* kh, const __nv_bfloat16* kl,
    const __nv_bfloat16* vh, const __nv_bfloat16* vl, int tid)
{
    const __nv_bfloat16* p[4] = {kh, kl, vh, vl};
    #pragma unroll
    for (int i = 0; i < 8; ++i) {
        int idx = tid + i * 256;
        int arr = idx >> 9;
        int c = idx & 511;
        int r = c >> 3, c8 = c & 7;
        const __nv_bfloat16* src = p[arr] + (size_t)r * DH_ + c8 * 8;
        uint32_t sa = kvb + arr * 9216 + r * 144 + c8 * 16;
        CP_A16(sa, src);
    }
}

__global__ __launch_bounds__(256, 1) void attn_mma_kernel()
{
    extern __shared__ char sm[];
    const uint32_t smb = smem_u32(sm);
    const int tid = threadIdx.x;
    const int wm = tid >> 5;
    const int lane = tid & 31;

    const int bh = blockIdx.y;
    const int qb = (gridDim.x - 1) - blockIdx.x;
    const int kmax = 2 * qb + 2;

    const uint32_t Qh_b = smb;
    const uint32_t Ql_b = smb + 18432;

    const __nv_bfloat16* kh_g = g_kh + (size_t)bh * S_ * DH_;
    const __nv_bfloat16* kl_g = g_kl + (size_t)bh * S_ * DH_;
    const __nv_bfloat16* vh_g = g_vh + (size_t)bh * S_ * DH_;
    const __nv_bfloat16* vl_g = g_vl + (size_t)bh * S_ * DH_;

    // prefetch KV tiles 0,1 (stages 0,1)
    attn_load_kv(smb + 36864, kh_g, kl_g, vh_g, vl_g, tid);
    CP_COMMIT();
    {
        size_t koff = (size_t)64 * DH_;
        attn_load_kv(smb + 36864 + KV_STAGE,
                     kh_g + koff, kl_g + koff, vh_g + koff, vl_g + koff, tid);
        CP_COMMIT();
    }

    // ---- load Q tile 128x64 hi/lo (plain copies) ----
    {
        const __nv_bfloat16* qh_g = g_qh + ((size_t)bh * S_ + qb * 128) * DH_;
        const __nv_bfloat16* ql_g = g_ql + ((size_t)bh * S_ + qb * 128) * DH_;
        #pragma unroll
        for (int i = 0; i < 4; ++i) {
            int idx = tid + i * 256;
            int r = idx >> 3, c8 = idx & 7;
            *(uint4*)(sm + (Qh_b - smb) + r * 144 + c8 * 16) =
                *(const uint4*)(qh_g + (size_t)r * DH_ + c8 * 8);
            *(uint4*)(sm + (Ql_b - smb) + r * 144 + c8 * 16) =
                *(const uint4*)(ql_g + (size_t)r * DH_ + c8 * 8);
        }
    }
    __syncthreads();

    // ---- Q fragments into registers ----
    uint32_t qh[4][4], ql[4][4];
    {
        const int ar = wm * 16 + (lane & 15);
        const int koff = (lane >> 4) << 3;
        #pragma unroll
        for (int ks = 0; ks < 4; ++ks) {
            LDSM_X4(qh[ks][0], qh[ks][1], qh[ks][2], qh[ks][3],
                    Qh_b + ar * 144 + (ks * 16 + koff) * 2);
            LDSM_X4(ql[ks][0], ql[ks][1], ql[ks][2], ql[ks][3],
                    Ql_b + ar * 144 + (ks * 16 + koff) * 2);
        }
    }

    float mA = -3.0e38f, mB = -3.0e38f, lA = 0.f, lB = 0.f;
    float oacc[8][4];
    #pragma unroll
    for (int t = 0; t < 8; ++t)
        #pragma unroll
        for (int q = 0; q < 4; ++q) oacc[t][q] = 0.f;

    const int kb_row  = (lane & 7) + ((lane >> 4) << 3);
    const int kb_koff = ((lane >> 3) & 1) << 3;
    const int vb_row  = (lane & 7) + (((lane >> 3) & 1) << 3);
    const int vb_eoff = (lane >> 4) << 3;

    const int rA_g = qb * 128 + wm * 16 + (lane >> 2);

    for (int kt = 0; kt < kmax; ++kt) {
        if (kt + 1 < kmax) { CP_WAIT(1); } else { CP_WAIT(0); }
        __syncthreads();
        if (kt + 2 < kmax) {
            size_t koff = (size_t)(kt + 2) * 64 * DH_;
            attn_load_kv(smb + 36864 + ((kt + 2) % 3) * KV_STAGE,
                         kh_g + koff, kl_g + koff, vh_g + koff, vl_g + koff, tid);
            CP_COMMIT();
        }

        const uint32_t kvb = smb + 36864 + (kt % 3) * KV_STAGE;
        const uint32_t Kh_b = kvb, Kl_b = kvb + 9216, Vh_b = kvb + 18432, Vl_b = kvb + 27648;

        // ---- S = Q K^T (split-3) ----
        float sacc[8][4];
        #pragma unroll
        for (int t = 0; t < 8; ++t)
            #pragma unroll
            for (int q = 0; q < 4; ++q) sacc[t][q] = 0.f;

        #pragma unroll
        for (int ks = 0; ks < 4; ++ks) {
            #pragma unroll
            for (int np = 0; np < 4; ++np) {
                uint32_t row = np * 16 + kb_row;
                uint32_t ko  = ks * 16 + kb_koff;
                uint32_t b0, b1, b2, b3, c0, c1, c2, c3;
                LDSM_X4(b0, b1, b2, b3, Kh_b + row * 144 + ko * 2);
                LDSM_X4(c0, c1, c2, c3, Kl_b + row * 144 + ko * 2);
                mma16816(sacc[2 * np],     qh[ks][0], qh[ks][1], qh[ks][2], qh[ks][3], b0, b1);
                mma16816(sacc[2 * np],     qh[ks][0], qh[ks][1], qh[ks][2], qh[ks][3], c0, c1);
                mma16816(sacc[2 * np],     ql[ks][0], ql[ks][1], ql[ks][2], ql[ks][3], b0, b1);
                mma16816(sacc[2 * np + 1], qh[ks][0], qh[ks][1], qh[ks][2], qh[ks][3], b2, b3);
                mma16816(sacc[2 * np + 1], qh[ks][0], qh[ks][1], qh[ks][2], qh[ks][3], c2, c3);
                mma16816(sacc[2 * np + 1], ql[ks][0], ql[ks][1], ql[ks][2], ql[ks][3], b2, b3);
            }
        }

        if (kt >= 2 * qb) {
            const int c0g = kt * 64 + 2 * (lane & 3);
            #pragma unroll
            for (int t = 0; t < 8; ++t) {
                int c = c0g + 8 * t;
                if (c     > rA_g)     sacc[t][0] = -3.0e38f;
                if (c + 1 > rA_g)     sacc[t][1] = -3.0e38f;
                if (c     > rA_g + 8) sacc[t][2] = -3.0e38f;
                if (c + 1 > rA_g + 8) sacc[t][3] = -3.0e38f;
            }
        }

        float mtA = -3.0e38f, mtB = -3.0e38f;
        #pragma unroll
        for (int t = 0; t < 8; ++t) {
            mtA = fmaxf(mtA, fmaxf(sacc[t][0], sacc[t][1]));
            mtB = fmaxf(mtB, fmaxf(sacc[t][2], sacc[t][3]));
        }
        mtA = fmaxf(mtA, __shfl_xor_sync(0xffffffffu, mtA, 1));
        mtA = fmaxf(mtA, __shfl_xor_sync(0xffffffffu, mtA, 2));
        mtB = fmaxf(mtB, __shfl_xor_sync(0xffffffffu, mtB, 1));
        mtB = fmaxf(mtB, __shfl_xor_sync(0xffffffffu, mtB, 2));

        float mnA = fmaxf(mA, mtA), mnB = fmaxf(mB, mtB);
        float corrA = __expf(mA - mnA), corrB = __expf(mB - mnB);

        float rsA = 0.f, rsB = 0.f;
        #pragma unroll
        for (int t = 0; t < 8; ++t) {
            float p0 = __expf(sacc[t][0] - mnA); sacc[t][0] = p0; rsA += p0;
            float p1 = __expf(sacc[t][1] - mnA); sacc[t][1] = p1; rsA += p1;
            float p2 = __expf(sacc[t][2] - mnB); sacc[t][2] = p2; rsB += p2;
            float p3 = __expf(sacc[t][3] - mnB); sacc[t][3] = p3; rsB += p3;
        }
        rsA += __shfl_xor_sync(0xffffffffu, rsA, 1);
        rsA += __shfl_xor_sync(0xffffffffu, rsA, 2);
        rsB += __shfl_xor_sync(0xffffffffu, rsB, 1);
        rsB += __shfl_xor_sync(0xffffffffu, rsB, 2);

        lA = lA * corrA + rsA;
        lB = lB * corrB + rsB;
        #pragma unroll
        for (int t = 0; t < 8; ++t) {
            oacc[t][0] *= corrA; oacc[t][1] *= corrA;
            oacc[t][2] *= corrB; oacc[t][3] *= corrB;
        }
        mA = mnA; mB = mnB;

        // ---- O += P V (split-3) ----
        #pragma unroll
        for (int ks = 0; ks < 4; ++ks) {
            uint32_t pfh[4], pfl[4];
            {
                float h00, l00, h01, l01, h10, l10, h11, l11;
                bsplit(sacc[2 * ks][0], h00, l00); bsplit(sacc[2 * ks][1], h01, l01);
                bsplit(sacc[2 * ks][2], h10, l10); bsplit(sacc[2 * ks][3], h11, l11);
                pfh[0] = packbf(h00, h01); pfl[0] = packbf(l00, l01);
                pfh[1] = packbf(h10, h11); pfl[1] = packbf(l10, l11);
                bsplit(sacc[2 * ks + 1][0], h00, l00); bsplit(sacc[2 * ks + 1][1], h01, l01);
                bsplit(sacc[2 * ks + 1][2], h10, l10); bsplit(sacc[2 * ks + 1][3], h11, l11);
                pfh[2] = packbf(h00, h01); pfl[2] = packbf(l00, l01);
                pfh[3] = packbf(h10, h11); pfl[3] = packbf(l10, l11);
            }
            #pragma unroll
            for (int ep = 0; ep < 4; ++ep) {
                uint32_t row = ks * 16 + vb_row;
                uint32_t eo  = ep * 16 + vb_eoff;
                uint32_t v0, v1, v2, v3, w0, w1, w2, w3;
                LDSM_X4_T(v0, v1, v2, v3, Vh_b + row * 144 + eo * 2);
                LDSM_X4_T(w0, w1, w2, w3, Vl_b + row * 144 + eo * 2);
                mma16816(oacc[2 * ep],     pfh[0], pfh[1], pfh[2], pfh[3], v0, v1);
                mma16816(oacc[2 * ep],     pfh[0], pfh[1], pfh[2], pfh[3], w0, w1);
                mma16816(oacc[2 * ep],     pfl[0], pfl[1], pfl[2], pfl[3], v0, v1);
                mma16816(oacc[2 * ep + 1], pfh[0], pfh[1], pfh[2], pfh[3], v2, v3);
                mma16816(oacc[2 * ep + 1], pfh[0], pfh[1], pfh[2], pfh[3], w2, w3);
                mma16816(oacc[2 * ep + 1], pfl[0], pfl[1], pfl[2], pfl[3], v2, v3);
            }
        }
    }

    // ---- finalize: write concat as bf16 hi/lo ----
    const float invA = 1.0f / lA;
    const float invB = 1.0f / lB;
    const int b = bh >> 4, h = bh & 15;
    const int e0 = 2 * (lane & 3);
    size_t baseA = ((size_t)b * S_ + rA_g) * D_ + h * DH_;
    size_t baseB = ((size_t)b * S_ + rA_g + 8) * D_ + h * DH_;
    #pragma unroll
    for (int t = 0; t < 8; ++t) {
        int e = 8 * t + e0;
        float a0 = oacc[t][0] * invA, a1 = oacc[t][1] * invA;
        float b0v = oacc[t][2] * invB, b1v = oacc[t][3] * invB;
        float h0, l0, h1, l1;
        bsplit(a0, h0, l0); bsplit(a1, h1, l1);
        *(uint32_t*)(g_ch + baseA + e) = packbf(h0, h1);
        *(uint32_t*)(g_cl + baseA + e) = packbf(l0, l1);
        bsplit(b0v, h0, l0); bsplit(b1v, h1, l1);
        *(uint32_t*)(g_ch + baseB + e) = packbf(h0, h1);
        *(uint32_t*)(g_cl + baseB + e) = packbf(l0, l1);
    }
}

// ============================================================
extern "C" void kernel_launch(void* const* d_in, const int* in_sizes, int n_in,
                              void* d_out, int out_size)
{
    const float* x  = (const float*)d_in[0];
    const float* Wq = (const float*)d_in[1];
    const float* Wk = (const float*)d_in[2];
    const float* Wv = (const float*)d_in[3];
    const float* Wo = (const float*)d_in[4];
    const float* bo = (const float*)d_in[5];
    float* out = (float*)d_out;

    cudaFuncSetAttribute(qkv_mma_kernel, cudaFuncAttributeMaxDynamicSharedMemorySize, GEMM_SMEM);
    cudaFuncSetAttribute(out_proj_mma_kernel, cudaFuncAttributeMaxDynamicSharedMemorySize, GEMM_SMEM);
    cudaFuncSetAttribute(attn_mma_kernel, cudaFuncAttributeMaxDynamicSharedMemorySize, ATTN_SMEM);

    conv_x_kernel<<<C_ELEMS / 4 / 256, 256>>>(x);
    conv_w_kernel<<<dim3(D_ / 64, H_, 3), 256>>>(Wq, Wk, Wv);
    conv_wo_kernel<<<dim3(D_ / 64, D_ / 64), 256>>>(Wo);
    qkv_mma_kernel<<<dim3(MROWS / 128, H_ / 2, 3), 256, GEMM_SMEM>>>();
    attn_mma_kernel<<<dim3(S_ / 128, B_ * H_), 256, ATTN_SMEM>>>();
    out_proj_mma_kernel<<<dim3(MROWS / 128, D_ / 128), 256, GEMM_SMEM>>>(bo, out);
}

// round 9
// speedup vs baseline: 1.0685x; 1.0029x over previous
#include <cuda_runtime.h>
#include <cuda_bf16.h>
#include <cstdint>

#define B_ 4
#define S_ 2048
#define D_ 1024
#define H_ 16
#define DH_ 64
#define MROWS (B_ * S_)
#define QKV_ELEMS (B_ * H_ * S_ * DH_)   // 8388608
#define C_ELEMS   (B_ * S_ * D_)         // 8388608

// -------- bf16 hi/lo scratch (no allocation) --------
__device__ __nv_bfloat16 g_xh[C_ELEMS],  g_xl[C_ELEMS];
__device__ __nv_bfloat16 g_wt_h[3 * H_ * DH_ * D_], g_wt_l[3 * H_ * DH_ * D_];
__device__ __nv_bfloat16 g_wo_h[D_ * D_], g_wo_l[D_ * D_];
__device__ __nv_bfloat16 g_qh[QKV_ELEMS], g_ql[QKV_ELEMS];
__device__ __nv_bfloat16 g_kh[QKV_ELEMS], g_kl[QKV_ELEMS];
__device__ __nv_bfloat16 g_vh[QKV_ELEMS], g_vl[QKV_ELEMS];
__device__ __nv_bfloat16 g_ch[C_ELEMS],  g_cl[C_ELEMS];

// ================= helpers =================
__device__ __forceinline__ uint32_t smem_u32(const void* p) {
    uint32_t a;
    asm("{ .reg .u64 t; cvta.to.shared.u64 t, %1; cvt.u32.u64 %0, t; }" : "=r"(a) : "l"(p));
    return a;
}
__device__ __forceinline__ void bsplit(float v, float& h, float& l) {
    __nv_bfloat16 bh = __float2bfloat16(v);
    h = __bfloat162float(bh);
    l = v - h;
}
__device__ __forceinline__ uint32_t packbf(float lo_elem, float hi_elem) {
    uint32_t r;
    asm("cvt.rn.bf16x2.f32 %0, %1, %2;" : "=r"(r) : "f"(hi_elem), "f"(lo_elem));
    return r;
}
#define LDSM_X4(r0, r1, r2, r3, addr) \
    asm volatile("ldmatrix.sync.aligned.m8n8.x4.shared.b16 {%0,%1,%2,%3}, [%4];" \
        : "=r"(r0), "=r"(r1), "=r"(r2), "=r"(r3) : "r"(addr))
#define LDSM_X4_T(r0, r1, r2, r3, addr) \
    asm volatile("ldmatrix.sync.aligned.m8n8.x4.trans.shared.b16 {%0,%1,%2,%3}, [%4];" \
        : "=r"(r0), "=r"(r1), "=r"(r2), "=r"(r3) : "r"(addr))
#define CP_A16(sa, gp) asm volatile("cp.async.ca.shared.global [%0], [%1], 16;" :: "r"(sa), "l"(gp))
#define CP_COMMIT()    asm volatile("cp.async.commit_group;" ::: "memory")
#define CP_WAIT(n)     asm volatile("cp.async.wait_group %0;" :: "n"(n) : "memory")

__device__ __forceinline__ void mma16816(float* c,
    uint32_t a0, uint32_t a1, uint32_t a2, uint32_t a3, uint32_t b0, uint32_t b1)
{
    asm volatile(
        "mma.sync.aligned.m16n8k16.row.col.f32.bf16.bf16.f32 "
        "{%0,%1,%2,%3}, {%4,%5,%6,%7}, {%8,%9}, {%0,%1,%2,%3};"
        : "+f"(c[0]), "+f"(c[1]), "+f"(c[2]), "+f"(c[3])
        : "r"(a0), "r"(a1), "r"(a2), "r"(a3), "r"(b0), "r"(b1));
}

// ============================================================
// Preconversion kernels (unchanged)
// ============================================================
__global__ __launch_bounds__(256) void conv_x_kernel(const float* __restrict__ x)
{
    int i = blockIdx.x * 256 + threadIdx.x;
    float4 v = *(const float4*)(x + 4 * (size_t)i);
    float hx, lx, hy, ly, hz, lz, hw, lw;
    bsplit(v.x, hx, lx); bsplit(v.y, hy, ly);
    bsplit(v.z, hz, lz); bsplit(v.w, hw, lw);
    uint2 wh, wl;
    wh.x = packbf(hx, hy); wh.y = packbf(hz, hw);
    wl.x = packbf(lx, ly); wl.y = packbf(lz, lw);
    *(uint2*)(g_xh + 4 * (size_t)i) = wh;
    *(uint2*)(g_xl + 4 * (size_t)i) = wl;
}

__global__ __launch_bounds__(256) void conv_w_kernel(
    const float* __restrict__ Wq, const float* __restrict__ Wk, const float* __restrict__ Wv)
{
    __shared__ float ts[64][65];
    const int tid = threadIdx.x;
    const int d0 = blockIdx.x * 64;
    const int h  = blockIdx.y;
    const int z  = blockIdx.z;
    const float* W = (z == 0) ? Wq : ((z == 1) ? Wk : Wv);
    const float* src = W + (size_t)h * D_ * DH_;

    #pragma unroll
    for (int i = 0; i < 4; ++i) {
        int idx = tid + i * 256;
        int rr = idx >> 4, cc = idx & 15;
        float4 v = *(const float4*)(src + (size_t)(d0 + rr) * DH_ + cc * 4);
        ts[rr][cc * 4 + 0] = v.x; ts[rr][cc * 4 + 1] = v.y;
        ts[rr][cc * 4 + 2] = v.z; ts[rr][cc * 4 + 3] = v.w;
    }
    __syncthreads();
    #pragma unroll
    for (int i = 0; i < 8; ++i) {
        int idx = tid + i * 256;
        int e = idx >> 5, w = idx & 31;
        float v0 = ts[2 * w][e], v1 = ts[2 * w + 1][e];
        float h0, l0, h1, l1;
        bsplit(v0, h0, l0); bsplit(v1, h1, l1);
        size_t off = ((size_t)(z * H_ + h) * DH_ + e) * D_ + d0 + 2 * w;
        *(uint32_t*)(g_wt_h + off) = packbf(h0, h1);
        *(uint32_t*)(g_wt_l + off) = packbf(l0, l1);
    }
}

__global__ __launch_bounds__(256) void conv_wo_kernel(const float* __restrict__ Wo)
{
    __shared__ float ts[64][65];
    const int tid = threadIdx.x;
    const int d0 = blockIdx.x * 64;
    const int f0 = blockIdx.y * 64;

    #pragma unroll
    for (int i = 0; i < 4; ++i) {
        int idx = tid + i * 256;
        int rr = idx >> 4, cc = idx & 15;
        float4 v = *(const float4*)(Wo + (size_t)(d0 + rr) * D_ + f0 + cc * 4);
        ts[rr][cc * 4 + 0] = v.x; ts[rr][cc * 4 + 1] = v.y;
        ts[rr][cc * 4 + 2] = v.z; ts[rr][cc * 4 + 3] = v.w;
    }
    __syncthreads();
    #pragma unroll
    for (int i = 0; i < 8; ++i) {
        int idx = tid + i * 256;
        int e = idx >> 5, w = idx & 31;
        float v0 = ts[2 * w][e], v1 = ts[2 * w + 1][e];
        float h0, l0, h1, l1;
        bsplit(v0, h0, l0); bsplit(v1, h1, l1);
        size_t off = (size_t)(f0 + e) * D_ + d0 + 2 * w;
        *(uint32_t*)(g_wo_h + off) = packbf(h0, h1);
        *(uint32_t*)(g_wo_l + off) = packbf(l0, l1);
    }
}

// ============================================================
// GEMM machinery: CTA tile 128x256, BK=32, 8 warps (2x4), warp tile 64x64.
// 3-stage cp.async pipeline, 1 barrier/ktile.
// stage layout: Ah 0 (10240), Al 10240, Bh 20480 (20480), Bl 40960.
// rows 80B (40 halves). stage = 61440B; x3 = 184320B.
// ============================================================
#define GEMM_STAGE 61440
#define GEMM_SMEM (3 * GEMM_STAGE)
#define NKT (D_ / 32)

__device__ __forceinline__ void gemm_load_stage(uint32_t sbase,
    const __nv_bfloat16* ah, const __nv_bfloat16* al,
    const __nv_bfloat16* bh2, const __nv_bfloat16* bl2, int tid)
{
    #pragma unroll
    for (int i = 0; i < 12; ++i) {
        int idx = tid + i * 256;           // 0..3071 16B-chunks
        int r4 = idx >> 2, col = idx & 3;
        const __nv_bfloat16* src;
        uint32_t sa;
        if (r4 < 256) {                    // A: rows 0..127 hi, 128..255 lo
            int arr = r4 >> 7;
            int r = r4 & 127;
            src = (arr ? al : ah) + (size_t)r * D_ + col * 8;
            sa = sbase + arr * 10240 + r * 80 + col * 16;
        } else {                           // B: 256 rows hi, 256 rows lo
            int q = r4 - 256;
            int arr = q >> 8;
            int r = q & 255;
            src = (arr ? bl2 : bh2) + (size_t)r * D_ + col * 8;
            sa = sbase + 20480 + arr * 20480 + r * 80 + col * 16;
        }
        CP_A16(sa, src);
    }
}

__device__ __forceinline__ void mma_phase(uint32_t sbase, float acc[4][8][4], int wid, int lane)
{
    const int warp_m = wid & 1;
    const int warp_n = wid >> 1;          // 0..3
    const uint32_t a_hi_b = sbase;
    const uint32_t a_lo_b = sbase + 10240;
    const uint32_t b_hi_b = sbase + 20480;
    const uint32_t b_lo_b = sbase + 40960;

    const int a_row = warp_m * 64 + (lane & 15);
    const int a_kh  = (lane >> 4) << 3;
    const int b_row = warp_n * 64 + (lane & 7) + ((lane >> 4) << 3);
    const int b_kh  = ((lane >> 3) & 1) << 3;

    #pragma unroll
    for (int ks = 0; ks < 2; ++ks) {
        const int koff = ks * 16;
        uint32_t ah4[4][4], al4[4][4], bhf[4][4], blf[4][4];
        #pragma unroll
        for (int i = 0; i < 4; ++i) {
            LDSM_X4(ah4[i][0], ah4[i][1], ah4[i][2], ah4[i][3],
                    a_hi_b + ((a_row + i * 16) * 40 + koff + a_kh) * 2);
            LDSM_X4(al4[i][0], al4[i][1], al4[i][2], al4[i][3],
                    a_lo_b + ((a_row + i * 16) * 40 + koff + a_kh) * 2);
        }
        #pragma unroll
        for (int jj = 0; jj < 4; ++jj) {
            LDSM_X4(bhf[jj][0], bhf[jj][1], bhf[jj][2], bhf[jj][3],
                    b_hi_b + ((b_row + jj * 16) * 40 + koff + b_kh) * 2);
            LDSM_X4(blf[jj][0], blf[jj][1], blf[jj][2], blf[jj][3],
                    b_lo_b + ((b_row + jj * 16) * 40 + koff + b_kh) * 2);
        }
        #pragma unroll
        for (int i = 0; i < 4; ++i)
            #pragma unroll
            for (int j = 0; j < 8; ++j) {
                int jj = j >> 1, s = (j & 1) * 2;
                mma16816(acc[i][j], ah4[i][0], ah4[i][1], ah4[i][2], ah4[i][3], bhf[jj][s], bhf[jj][s + 1]);
                mma16816(acc[i][j], ah4[i][0], ah4[i][1], ah4[i][2], ah4[i][3], blf[jj][s], blf[jj][s + 1]);
                mma16816(acc[i][j], al4[i][0], al4[i][1], al4[i][2], al4[i][3], bhf[jj][s], bhf[jj][s + 1]);
            }
    }
}

#define GEMM_MAINLOOP(AH, AL, BH, BL)                                          \
    gemm_load_stage(smb, (AH), (AL), (BH), (BL), tid);                         \
    CP_COMMIT();                                                               \
    gemm_load_stage(smb + GEMM_STAGE, (AH) + 32, (AL) + 32, (BH) + 32, (BL) + 32, tid); \
    CP_COMMIT();                                                               \
    for (int kt = 0; kt < NKT; ++kt) {                                         \
        if (kt + 1 < NKT) { CP_WAIT(1); } else { CP_WAIT(0); }                 \
        __syncthreads();                                                       \
        if (kt + 2 < NKT) {                                                    \
            int k2 = (kt + 2) * 32;                                            \
            gemm_load_stage(smb + ((kt + 2) % 3) * GEMM_STAGE,                 \
                            (AH) + k2, (AL) + k2, (BH) + k2, (BL) + k2, tid);  \
            CP_COMMIT();                                                       \
        }                                                                      \
        mma_phase(smb + (kt % 3) * GEMM_STAGE, acc, wid, lane);                \
    }

// ============================================================
// Kernel 1: QKV projection. grid = (64, 4, 3), block 256. N=256 = 4 heads.
// ============================================================
__global__ __launch_bounds__(256, 1) void qkv_mma_kernel()
{
    extern __shared__ char sm[];
    const uint32_t smb = smem_u32(sm);
    const int tid = threadIdx.x;
    const int wid = tid >> 5;
    const int lane = tid & 31;

    const int z = blockIdx.z;
    const int hp = blockIdx.y;             // group of 4 heads
    const int m0 = blockIdx.x * 128;

    __nv_bfloat16* outh = (z == 0) ? g_qh : ((z == 1) ? g_kh : g_vh);
    __nv_bfloat16* outl = (z == 0) ? g_ql : ((z == 1) ? g_kl : g_vl);
    const float scale = (z == 0) ? 0.125f : 1.0f;

    const __nv_bfloat16* ah = g_xh + (size_t)m0 * D_;
    const __nv_bfloat16* al = g_xl + (size_t)m0 * D_;
    const __nv_bfloat16* bh = g_wt_h + (size_t)(z * H_ + hp * 4) * DH_ * D_;
    const __nv_bfloat16* bl = g_wt_l + (size_t)(z * H_ + hp * 4) * DH_ * D_;

    float acc[4][8][4];
    #pragma unroll
    for (int i = 0; i < 4; ++i)
        #pragma unroll
        for (int j = 0; j < 8; ++j)
            #pragma unroll
            for (int q = 0; q < 4; ++q) acc[i][j][q] = 0.f;

    GEMM_MAINLOOP(ah, al, bh, bl)

    const int warp_m = wid & 1;
    const int warp_n = wid >> 1;
    #pragma unroll
    for (int i = 0; i < 4; ++i) {
        #pragma unroll
        for (int j = 0; j < 8; ++j) {
            int r0 = m0 + warp_m * 64 + i * 16 + (lane >> 2);
            int col = warp_n * 64 + j * 8 + (lane & 3) * 2;
            int hh = hp * 4 + (col >> 6);
            int ee = col & 63;
            #pragma unroll
            for (int half = 0; half < 2; ++half) {
                int r = r0 + half * 8;
                int b = r >> 11, s = r & 2047;
                float v0 = acc[i][j][2 * half] * scale;
                float v1 = acc[i][j][2 * half + 1] * scale;
                float h0, l0, h1, l1;
                bsplit(v0, h0, l0); bsplit(v1, h1, l1);
                size_t off = ((size_t)(b * H_ + hh) * S_ + s) * DH_ + ee;
                *(uint32_t*)(outh + off) = packbf(h0, h1);
                *(uint32_t*)(outl + off) = packbf(l0, l1);
            }
        }
    }
}

// ============================================================
// Kernel 3: output projection. grid = (64, 4), block 256. N=256 slabs.
// ============================================================
__global__ __launch_bounds__(256, 1) void out_proj_mma_kernel(
    const float* __restrict__ bo, float* __restrict__ out)
{
    extern __shared__ char sm[];
    const uint32_t smb = smem_u32(sm);
    const int tid = threadIdx.x;
    const int wid = tid >> 5;
    const int lane = tid & 31;

    const int n0 = blockIdx.y * 256;
    const int m0 = blockIdx.x * 128;

    const __nv_bfloat16* ah = g_ch + (size_t)m0 * D_;
    const __nv_bfloat16* al = g_cl + (size_t)m0 * D_;
    const __nv_bfloat16* bh = g_wo_h + (size_t)n0 * D_;
    const __nv_bfloat16* bl = g_wo_l + (size_t)n0 * D_;

    float acc[4][8][4];
    #pragma unroll
    for (int i = 0; i < 4; ++i)
        #pragma unroll
        for (int j = 0; j < 8; ++j)
            #pragma unroll
            for (int q = 0; q < 4; ++q) acc[i][j][q] = 0.f;

    GEMM_MAINLOOP(ah, al, bh, bl)

    const int warp_m = wid & 1;
    const int warp_n = wid >> 1;
    #pragma unroll
    for (int i = 0; i < 4; ++i) {
        #pragma unroll
        for (int j = 0; j < 8; ++j) {
            int r0 = m0 + warp_m * 64 + i * 16 + (lane >> 2);
            int col = n0 + warp_n * 64 + j * 8 + (lane & 3) * 2;
            float b0 = bo[col], b1 = bo[col + 1];
            {
                float2 v; v.x = acc[i][j][0] + b0; v.y = acc[i][j][1] + b1;
                *(float2*)(out + (size_t)r0 * D_ + col) = v;
            }
            {
                float2 v; v.x = acc[i][j][2] + b0; v.y = acc[i][j][3] + b1;
                *(float2*)(out + (size_t)(r0 + 8) * D_ + col) = v;
            }
        }
    }
}

// ============================================================
// Kernel 2: causal flash attention (unchanged R8: 3-stage KV, 1 barrier).
// ============================================================
#define KV_STAGE 36864
#define ATTN_SMEM (36864 + 3 * KV_STAGE)

__device__ __forceinline__ void attn_load_kv(uint32_t kvb,
    const __nv_bfloat16* kh, const __nv_bfloat16* kl,
    const __nv_bfloat16* vh, const __nv_bfloat16* vl, int tid)
{
    const __nv_bfloat16* p[4] = {kh, kl, vh, vl};
    #pragma unroll
    for (int i = 0; i < 8; ++i) {
        int idx = tid + i * 256;
        int arr = idx >> 9;
        int c = idx & 511;
        int r = c >> 3, c8 = c & 7;
        const __nv_bfloat16* src = p[arr] + (size_t)r * DH_ + c8 * 8;
        uint32_t sa = kvb + arr * 9216 + r * 144 + c8 * 16;
        CP_A16(sa, src);
    }
}

__global__ __launch_bounds__(256, 1) void attn_mma_kernel()
{
    extern __shared__ char sm[];
    const uint32_t smb = smem_u32(sm);
    const int tid = threadIdx.x;
    const int wm = tid >> 5;
    const int lane = tid & 31;

    const int bh = blockIdx.y;
    const int qb = (gridDim.x - 1) - blockIdx.x;
    const int kmax = 2 * qb + 2;

    const uint32_t Qh_b = smb;
    const uint32_t Ql_b = smb + 18432;

    const __nv_bfloat16* kh_g = g_kh + (size_t)bh * S_ * DH_;
    const __nv_bfloat16* kl_g = g_kl + (size_t)bh * S_ * DH_;
    const __nv_bfloat16* vh_g = g_vh + (size_t)bh * S_ * DH_;
    const __nv_bfloat16* vl_g = g_vl + (size_t)bh * S_ * DH_;

    attn_load_kv(smb + 36864, kh_g, kl_g, vh_g, vl_g, tid);
    CP_COMMIT();
    {
        size_t koff = (size_t)64 * DH_;
        attn_load_kv(smb + 36864 + KV_STAGE,
                     kh_g + koff, kl_g + koff, vh_g + koff, vl_g + koff, tid);
        CP_COMMIT();
    }

    {
        const __nv_bfloat16* qh_g = g_qh + ((size_t)bh * S_ + qb * 128) * DH_;
        const __nv_bfloat16* ql_g = g_ql + ((size_t)bh * S_ + qb * 128) * DH_;
        #pragma unroll
        for (int i = 0; i < 4; ++i) {
            int idx = tid + i * 256;
            int r = idx >> 3, c8 = idx & 7;
            *(uint4*)(sm + (Qh_b - smb) + r * 144 + c8 * 16) =
                *(const uint4*)(qh_g + (size_t)r * DH_ + c8 * 8);
            *(uint4*)(sm + (Ql_b - smb) + r * 144 + c8 * 16) =
                *(const uint4*)(ql_g + (size_t)r * DH_ + c8 * 8);
        }
    }
    __syncthreads();

    uint32_t qh[4][4], ql[4][4];
    {
        const int ar = wm * 16 + (lane & 15);
        const int koff = (lane >> 4) << 3;
        #pragma unroll
        for (int ks = 0; ks < 4; ++ks) {
            LDSM_X4(qh[ks][0], qh[ks][1], qh[ks][2], qh[ks][3],
                    Qh_b + ar * 144 + (ks * 16 + koff) * 2);
            LDSM_X4(ql[ks][0], ql[ks][1], ql[ks][2], ql[ks][3],
                    Ql_b + ar * 144 + (ks * 16 + koff) * 2);
        }
    }

    float mA = -3.0e38f, mB = -3.0e38f, lA = 0.f, lB = 0.f;
    float oacc[8][4];
    #pragma unroll
    for (int t = 0; t < 8; ++t)
        #pragma unroll
        for (int q = 0; q < 4; ++q) oacc[t][q] = 0.f;

    const int kb_row  = (lane & 7) + ((lane >> 4) << 3);
    const int kb_koff = ((lane >> 3) & 1) << 3;
    const int vb_row  = (lane & 7) + (((lane >> 3) & 1) << 3);
    const int vb_eoff = (lane >> 4) << 3;

    const int rA_g = qb * 128 + wm * 16 + (lane >> 2);

    for (int kt = 0; kt < kmax; ++kt) {
        if (kt + 1 < kmax) { CP_WAIT(1); } else { CP_WAIT(0); }
        __syncthreads();
        if (kt + 2 < kmax) {
            size_t koff = (size_t)(kt + 2) * 64 * DH_;
            attn_load_kv(smb + 36864 + ((kt + 2) % 3) * KV_STAGE,
                         kh_g + koff, kl_g + koff, vh_g + koff, vl_g + koff, tid);
            CP_COMMIT();
        }

        const uint32_t kvb = smb + 36864 + (kt % 3) * KV_STAGE;
        const uint32_t Kh_b = kvb, Kl_b = kvb + 9216, Vh_b = kvb + 18432, Vl_b = kvb + 27648;

        float sacc[8][4];
        #pragma unroll
        for (int t = 0; t < 8; ++t)
            #pragma unroll
            for (int q = 0; q < 4; ++q) sacc[t][q] = 0.f;

        #pragma unroll
        for (int ks = 0; ks < 4; ++ks) {
            #pragma unroll
            for (int np = 0; np < 4; ++np) {
                uint32_t row = np * 16 + kb_row;
                uint32_t ko  = ks * 16 + kb_koff;
                uint32_t b0, b1, b2, b3, c0, c1, c2, c3;
                LDSM_X4(b0, b1, b2, b3, Kh_b + row * 144 + ko * 2);
                LDSM_X4(c0, c1, c2, c3, Kl_b + row * 144 + ko * 2);
                mma16816(sacc[2 * np],     qh[ks][0], qh[ks][1], qh[ks][2], qh[ks][3], b0, b1);
                mma16816(sacc[2 * np],     qh[ks][0], qh[ks][1], qh[ks][2], qh[ks][3], c0, c1);
                mma16816(sacc[2 * np],     ql[ks][0], ql[ks][1], ql[ks][2], ql[ks][3], b0, b1);
                mma16816(sacc[2 * np + 1], qh[ks][0], qh[ks][1], qh[ks][2], qh[ks][3], b2, b3);
                mma16816(sacc[2 * np + 1], qh[ks][0], qh[ks][1], qh[ks][2], qh[ks][3], c2, c3);
                mma16816(sacc[2 * np + 1], ql[ks][0], ql[ks][1], ql[ks][2], ql[ks][3], b2, b3);
            }
        }

        if (kt >= 2 * qb) {
            const int c0g = kt * 64 + 2 * (lane & 3);
            #pragma unroll
            for (int t = 0; t < 8; ++t) {
                int c = c0g + 8 * t;
                if (c     > rA_g)     sacc[t][0] = -3.0e38f;
                if (c + 1 > rA_g)     sacc[t][1] = -3.0e38f;
                if (c     > rA_g + 8) sacc[t][2] = -3.0e38f;
                if (c + 1 > rA_g + 8) sacc[t][3] = -3.0e38f;
            }
        }

        float mtA = -3.0e38f, mtB = -3.0e38f;
        #pragma unroll
        for (int t = 0; t < 8; ++t) {
            mtA = fmaxf(mtA, fmaxf(sacc[t][0], sacc[t][1]));
            mtB = fmaxf(mtB, fmaxf(sacc[t][2], sacc[t][3]));
        }
        mtA = fmaxf(mtA, __shfl_xor_sync(0xffffffffu, mtA, 1));
        mtA = fmaxf(mtA, __shfl_xor_sync(0xffffffffu, mtA, 2));
        mtB = fmaxf(mtB, __shfl_xor_sync(0xffffffffu, mtB, 1));
        mtB = fmaxf(mtB, __shfl_xor_sync(0xffffffffu, mtB, 2));

        float mnA = fmaxf(mA, mtA), mnB = fmaxf(mB, mtB);
        float corrA = __expf(mA - mnA), corrB = __expf(mB - mnB);

        float rsA = 0.f, rsB = 0.f;
        #pragma unroll
        for (int t = 0; t < 8; ++t) {
            float p0 = __expf(sacc[t][0] - mnA); sacc[t][0] = p0; rsA += p0;
            float p1 = __expf(sacc[t][1] - mnA); sacc[t][1] = p1; rsA += p1;
            float p2 = __expf(sacc[t][2] - mnB); sacc[t][2] = p2; rsB += p2;
            float p3 = __expf(sacc[t][3] - mnB); sacc[t][3] = p3; rsB += p3;
        }
        rsA += __shfl_xor_sync(0xffffffffu, rsA, 1);
        rsA += __shfl_xor_sync(0xffffffffu, rsA, 2);
        rsB += __shfl_xor_sync(0xffffffffu, rsB, 1);
        rsB += __shfl_xor_sync(0xffffffffu, rsB, 2);

        lA = lA * corrA + rsA;
        lB = lB * corrB + rsB;
        #pragma unroll
        for (int t = 0; t < 8; ++t) {
            oacc[t][0] *= corrA; oacc[t][1] *= corrA;
            oacc[t][2] *= corrB; oacc[t][3] *= corrB;
        }
        mA = mnA; mB = mnB;

        #pragma unroll
        for (int ks = 0; ks < 4; ++ks) {
            uint32_t pfh[4], pfl[4];
            {
                float h00, l00, h01, l01, h10, l10, h11, l11;
                bsplit(sacc[2 * ks][0], h00, l00); bsplit(sacc[2 * ks][1], h01, l01);
                bsplit(sacc[2 * ks][2], h10, l10); bsplit(sacc[2 * ks][3], h11, l11);
                pfh[0] = packbf(h00, h01); pfl[0] = packbf(l00, l01);
                pfh[1] = packbf(h10, h11); pfl[1] = packbf(l10, l11);
                bsplit(sacc[2 * ks + 1][0], h00, l00); bsplit(sacc[2 * ks + 1][1], h01, l01);
                bsplit(sacc[2 * ks + 1][2], h10, l10); bsplit(sacc[2 * ks + 1][3], h11, l11);
                pfh[2] = packbf(h00, h01); pfl[2] = packbf(l00, l01);
                pfh[3] = packbf(h10, h11); pfl[3] = packbf(l10, l11);
            }
            #pragma unroll
            for (int ep = 0; ep < 4; ++ep) {
                uint32_t row = ks * 16 + vb_row;
                uint32_t eo  = ep * 16 + vb_eoff;
                uint32_t v0, v1, v2, v3, w0, w1, w2, w3;
                LDSM_X4_T(v0, v1, v2, v3, Vh_b + row * 144 + eo * 2);
                LDSM_X4_T(w0, w1, w2, w3, Vl_b + row * 144 + eo * 2);
                mma16816(oacc[2 * ep],     pfh[0], pfh[1], pfh[2], pfh[3], v0, v1);
                mma16816(oacc[2 * ep],     pfh[0], pfh[1], pfh[2], pfh[3], w0, w1);
                mma16816(oacc[2 * ep],     pfl[0], pfl[1], pfl[2], pfl[3], v0, v1);
                mma16816(oacc[2 * ep + 1], pfh[0], pfh[1], pfh[2], pfh[3], v2, v3);
                mma16816(oacc[2 * ep + 1], pfh[0], pfh[1], pfh[2], pfh[3], w2, w3);
                mma16816(oacc[2 * ep + 1], pfl[0], pfl[1], pfl[2], pfl[3], v2, v3);
            }
        }
    }

    const float invA = 1.0f / lA;
    const float invB = 1.0f / lB;
    const int b = bh >> 4, h = bh & 15;
    const int e0 = 2 * (lane & 3);
    size_t baseA = ((size_t)b * S_ + rA_g) * D_ + h * DH_;
    size_t baseB = ((size_t)b * S_ + rA_g + 8) * D_ + h * DH_;
    #pragma unroll
    for (int t = 0; t < 8; ++t) {
        int e = 8 * t + e0;
        float a0 = oacc[t][0] * invA, a1 = oacc[t][1] * invA;
        float b0v = oacc[t][2] * invB, b1v = oacc[t][3] * invB;
        float h0, l0, h1, l1;
        bsplit(a0, h0, l0); bsplit(a1, h1, l1);
        *(uint32_t*)(g_ch + baseA + e) = packbf(h0, h1);
        *(uint32_t*)(g_cl + baseA + e) = packbf(l0, l1);
        bsplit(b0v, h0, l0); bsplit(b1v, h1, l1);
        *(uint32_t*)(g_ch + baseB + e) = packbf(h0, h1);
        *(uint32_t*)(g_cl + baseB + e) = packbf(l0, l1);
    }
}

// ============================================================
extern "C" void kernel_launch(void* const* d_in, const int* in_sizes, int n_in,
                              void* d_out, int out_size)
{
    const float* x  = (const float*)d_in[0];
    const float* Wq = (const float*)d_in[1];
    const float* Wk = (const float*)d_in[2];
    const float* Wv = (const float*)d_in[3];
    const float* Wo = (const float*)d_in[4];
    const float* bo = (const float*)d_in[5];
    float* out = (float*)d_out;

    cudaFuncSetAttribute(qkv_mma_kernel, cudaFuncAttributeMaxDynamicSharedMemorySize, GEMM_SMEM);
    cudaFuncSetAttribute(out_proj_mma_kernel, cudaFuncAttributeMaxDynamicSharedMemorySize, GEMM_SMEM);
    cudaFuncSetAttribute(attn_mma_kernel, cudaFuncAttributeMaxDynamicSharedMemorySize, ATTN_SMEM);

    conv_x_kernel<<<C_ELEMS / 4 / 256, 256>>>(x);
    conv_w_kernel<<<dim3(D_ / 64, H_, 3), 256>>>(Wq, Wk, Wv);
    conv_wo_kernel<<<dim3(D_ / 64, D_ / 64), 256>>>(Wo);
    qkv_mma_kernel<<<dim3(MROWS / 128, H_ / 4, 3), 256, GEMM_SMEM>>>();
    attn_mma_kernel<<<dim3(S_ / 128, B_ * H_), 256, ATTN_SMEM>>>();
    out_proj_mma_kernel<<<dim3(MROWS / 128, D_ / 256), 256, GEMM_SMEM>>>(bo, out);
}

// round 10
// speedup vs baseline: 1.0953x; 1.0251x over previous
#include <cuda_runtime.h>
#include <cuda_bf16.h>
#include <cstdint>

#define B_ 4
#define S_ 2048
#define D_ 1024
#define H_ 16
#define DH_ 64
#define MROWS (B_ * S_)
#define QKV_ELEMS (B_ * H_ * S_ * DH_)   // 8388608
#define C_ELEMS   (B_ * S_ * D_)         // 8388608

// -------- bf16 hi/lo scratch (no allocation) --------
__device__ __nv_bfloat16 g_xh[C_ELEMS],  g_xl[C_ELEMS];
__device__ __nv_bfloat16 g_wt_h[3 * H_ * DH_ * D_], g_wt_l[3 * H_ * DH_ * D_];
__device__ __nv_bfloat16 g_wo_h[D_ * D_], g_wo_l[D_ * D_];
__device__ __nv_bfloat16 g_qh[QKV_ELEMS], g_ql[QKV_ELEMS];
__device__ __nv_bfloat16 g_kh[QKV_ELEMS], g_kl[QKV_ELEMS];
__device__ __nv_bfloat16 g_vh[QKV_ELEMS], g_vl[QKV_ELEMS];
__device__ __nv_bfloat16 g_ch[C_ELEMS],  g_cl[C_ELEMS];

// ================= helpers =================
__device__ __forceinline__ uint32_t smem_u32(const void* p) {
    uint32_t a;
    asm("{ .reg .u64 t; cvta.to.shared.u64 t, %1; cvt.u32.u64 %0, t; }" : "=r"(a) : "l"(p));
    return a;
}
__device__ __forceinline__ void bsplit(float v, float& h, float& l) {
    __nv_bfloat16 bh = __float2bfloat16(v);
    h = __bfloat162float(bh);
    l = v - h;
}
__device__ __forceinline__ uint32_t packbf(float lo_elem, float hi_elem) {
    uint32_t r;
    asm("cvt.rn.bf16x2.f32 %0, %1, %2;" : "=r"(r) : "f"(hi_elem), "f"(lo_elem));
    return r;
}
#define LDSM_X4(r0, r1, r2, r3, addr) \
    asm volatile("ldmatrix.sync.aligned.m8n8.x4.shared.b16 {%0,%1,%2,%3}, [%4];" \
        : "=r"(r0), "=r"(r1), "=r"(r2), "=r"(r3) : "r"(addr))
#define LDSM_X4_T(r0, r1, r2, r3, addr) \
    asm volatile("ldmatrix.sync.aligned.m8n8.x4.trans.shared.b16 {%0,%1,%2,%3}, [%4];" \
        : "=r"(r0), "=r"(r1), "=r"(r2), "=r"(r3) : "r"(addr))
#define CP_A16(sa, gp) asm volatile("cp.async.ca.shared.global [%0], [%1], 16;" :: "r"(sa), "l"(gp))
#define CP_COMMIT()    asm volatile("cp.async.commit_group;" ::: "memory")
#define CP_WAIT(n)     asm volatile("cp.async.wait_group %0;" :: "n"(n) : "memory")

__device__ __forceinline__ void mma16816(float* c,
    uint32_t a0, uint32_t a1, uint32_t a2, uint32_t a3, uint32_t b0, uint32_t b1)
{
    asm volatile(
        "mma.sync.aligned.m16n8k16.row.col.f32.bf16.bf16.f32 "
        "{%0,%1,%2,%3}, {%4,%5,%6,%7}, {%8,%9}, {%0,%1,%2,%3};"
        : "+f"(c[0]), "+f"(c[1]), "+f"(c[2]), "+f"(c[3])
        : "r"(a0), "r"(a1), "r"(a2), "r"(a3), "r"(b0), "r"(b1));
}

// ============================================================
// Preconversion kernels (unchanged R6)
// ============================================================
__global__ __launch_bounds__(256) void conv_x_kernel(const float* __restrict__ x)
{
    int i = blockIdx.x * 256 + threadIdx.x;
    float4 v = *(const float4*)(x + 4 * (size_t)i);
    float hx, lx, hy, ly, hz, lz, hw, lw;
    bsplit(v.x, hx, lx); bsplit(v.y, hy, ly);
    bsplit(v.z, hz, lz); bsplit(v.w, hw, lw);
    uint2 wh, wl;
    wh.x = packbf(hx, hy); wh.y = packbf(hz, hw);
    wl.x = packbf(lx, ly); wl.y = packbf(lz, lw);
    *(uint2*)(g_xh + 4 * (size_t)i) = wh;
    *(uint2*)(g_xl + 4 * (size_t)i) = wl;
}

__global__ __launch_bounds__(256) void conv_w_kernel(
    const float* __restrict__ Wq, const float* __restrict__ Wk, const float* __restrict__ Wv)
{
    __shared__ float ts[64][65];
    const int tid = threadIdx.x;
    const int d0 = blockIdx.x * 64;
    const int h  = blockIdx.y;
    const int z  = blockIdx.z;
    const float* W = (z == 0) ? Wq : ((z == 1) ? Wk : Wv);
    const float* src = W + (size_t)h * D_ * DH_;

    #pragma unroll
    for (int i = 0; i < 4; ++i) {
        int idx = tid + i * 256;
        int rr = idx >> 4, cc = idx & 15;
        float4 v = *(const float4*)(src + (size_t)(d0 + rr) * DH_ + cc * 4);
        ts[rr][cc * 4 + 0] = v.x; ts[rr][cc * 4 + 1] = v.y;
        ts[rr][cc * 4 + 2] = v.z; ts[rr][cc * 4 + 3] = v.w;
    }
    __syncthreads();
    #pragma unroll
    for (int i = 0; i < 8; ++i) {
        int idx = tid + i * 256;
        int e = idx >> 5, w = idx & 31;
        float v0 = ts[2 * w][e], v1 = ts[2 * w + 1][e];
        float h0, l0, h1, l1;
        bsplit(v0, h0, l0); bsplit(v1, h1, l1);
        size_t off = ((size_t)(z * H_ + h) * DH_ + e) * D_ + d0 + 2 * w;
        *(uint32_t*)(g_wt_h + off) = packbf(h0, h1);
        *(uint32_t*)(g_wt_l + off) = packbf(l0, l1);
    }
}

__global__ __launch_bounds__(256) void conv_wo_kernel(const float* __restrict__ Wo)
{
    __shared__ float ts[64][65];
    const int tid = threadIdx.x;
    const int d0 = blockIdx.x * 64;
    const int f0 = blockIdx.y * 64;

    #pragma unroll
    for (int i = 0; i < 4; ++i) {
        int idx = tid + i * 256;
        int rr = idx >> 4, cc = idx & 15;
        float4 v = *(const float4*)(Wo + (size_t)(d0 + rr) * D_ + f0 + cc * 4);
        ts[rr][cc * 4 + 0] = v.x; ts[rr][cc * 4 + 1] = v.y;
        ts[rr][cc * 4 + 2] = v.z; ts[rr][cc * 4 + 3] = v.w;
    }
    __syncthreads();
    #pragma unroll
    for (int i = 0; i < 8; ++i) {
        int idx = tid + i * 256;
        int e = idx >> 5, w = idx & 31;
        float v0 = ts[2 * w][e], v1 = ts[2 * w + 1][e];
        float h0, l0, h1, l1;
        bsplit(v0, h0, l0); bsplit(v1, h1, l1);
        size_t off = (size_t)(f0 + e) * D_ + d0 + 2 * w;
        *(uint32_t*)(g_wo_h + off) = packbf(h0, h1);
        *(uint32_t*)(g_wo_l + off) = packbf(l0, l1);
    }
}

// ============================================================
// GEMM machinery (R6 config): 128x128 tile, BK=32, 8 warps (64x32 warp tile),
// double-buffered cp.async, __launch_bounds__(256,2) -> 2 CTAs/SM.
// stage: Ah 0, Al 10240, Bh 20480, Bl 30720; rows 80B; 2 stages = 81920B.
// ============================================================
#define GEMM_STAGE 40960
#define GEMM_SMEM (2 * GEMM_STAGE)
#define NKT (D_ / 32)

__device__ __forceinline__ void gemm_load_stage(uint32_t sbase,
    const __nv_bfloat16* p0, const __nv_bfloat16* p1,
    const __nv_bfloat16* p2, const __nv_bfloat16* p3, int tid)
{
    const __nv_bfloat16* p[4] = {p0, p1, p2, p3};
    #pragma unroll
    for (int i = 0; i < 8; ++i) {
        int idx = tid + i * 256;
        int arr = idx >> 9;
        int c = idx & 511;
        int r = c >> 2, col = c & 3;
        const __nv_bfloat16* src = p[arr] + (size_t)r * D_ + col * 8;
        uint32_t sa = sbase + arr * 10240 + r * 80 + col * 16;
        CP_A16(sa, src);
    }
}

__device__ __forceinline__ void mma_phase(uint32_t sbase, float acc[4][4][4], int wid, int lane)
{
    const int warp_m = wid & 1;
    const int warp_n = wid >> 1;
    const uint32_t a_hi_b = sbase;
    const uint32_t a_lo_b = sbase + 10240;
    const uint32_t b_hi_b = sbase + 20480;
    const uint32_t b_lo_b = sbase + 30720;

    const int a_row = warp_m * 64 + (lane & 15);
    const int a_kh  = (lane >> 4) << 3;
    const int b_row = warp_n * 32 + (lane & 7) + ((lane >> 4) << 3);
    const int b_kh  = ((lane >> 3) & 1) << 3;

    #pragma unroll
    for (int ks = 0; ks < 2; ++ks) {
        const int koff = ks * 16;
        uint32_t ah[4][4], bh[2][4], bl[2][4];
        #pragma unroll
        for (int i = 0; i < 4; ++i) {
            uint32_t addr = a_hi_b + ((a_row + i * 16) * 40 + koff + a_kh) * 2;
            LDSM_X4(ah[i][0], ah[i][1], ah[i][2], ah[i][3], addr);
        }
        #pragma unroll
        for (int jj = 0; jj < 2; ++jj) {
            uint32_t addr = b_hi_b + ((b_row + jj * 16) * 40 + koff + b_kh) * 2;
            LDSM_X4(bh[jj][0], bh[jj][1], bh[jj][2], bh[jj][3], addr);
            uint32_t addr2 = b_lo_b + ((b_row + jj * 16) * 40 + koff + b_kh) * 2;
            LDSM_X4(bl[jj][0], bl[jj][1], bl[jj][2], bl[jj][3], addr2);
        }
        #pragma unroll
        for (int i = 0; i < 4; ++i)
            #pragma unroll
            for (int j = 0; j < 4; ++j) {
                int jj = j >> 1, s = (j & 1) * 2;
                mma16816(acc[i][j], ah[i][0], ah[i][1], ah[i][2], ah[i][3], bh[jj][s], bh[jj][s + 1]);
                mma16816(acc[i][j], ah[i][0], ah[i][1], ah[i][2], ah[i][3], bl[jj][s], bl[jj][s + 1]);
            }
        #pragma unroll
        for (int i = 0; i < 4; ++i) {
            uint32_t addr = a_lo_b + ((a_row + i * 16) * 40 + koff + a_kh) * 2;
            LDSM_X4(ah[i][0], ah[i][1], ah[i][2], ah[i][3], addr);
        }
        #pragma unroll
        for (int i = 0; i < 4; ++i)
            #pragma unroll
            for (int j = 0; j < 4; ++j) {
                int jj = j >> 1, s = (j & 1) * 2;
                mma16816(acc[i][j], ah[i][0], ah[i][1], ah[i][2], ah[i][3], bh[jj][s], bh[jj][s + 1]);
            }
    }
}

#define GEMM_MAINLOOP(AH, AL, BH, BL)                                          \
    gemm_load_stage(smb, (AH), (AL), (BH), (BL), tid);                         \
    CP_COMMIT();                                                               \
    for (int kt = 0; kt < NKT; ++kt) {                                         \
        if (kt + 1 < NKT) {                                                    \
            int k1 = (kt + 1) * 32;                                            \
            gemm_load_stage(smb + ((kt + 1) & 1) * GEMM_STAGE,                 \
                            (AH) + k1, (AL) + k1, (BH) + k1, (BL) + k1, tid);  \
            CP_COMMIT();                                                       \
            CP_WAIT(1);                                                        \
        } else {                                                               \
            CP_WAIT(0);                                                        \
        }                                                                      \
        __syncthreads();                                                       \
        mma_phase(smb + (kt & 1) * GEMM_STAGE, acc, wid, lane);                \
        __syncthreads();                                                       \
    }

// ============================================================
// Kernel 1: QKV projection. grid = (64, 8, 3), block 256, 2 CTAs/SM.
// ============================================================
__global__ __launch_bounds__(256, 2) void qkv_mma_kernel()
{
    extern __shared__ char sm[];
    const uint32_t smb = smem_u32(sm);
    const int tid = threadIdx.x;
    const int wid = tid >> 5;
    const int lane = tid & 31;

    const int z = blockIdx.z;
    const int hp = blockIdx.y;
    const int m0 = blockIdx.x * 128;

    __nv_bfloat16* outh = (z == 0) ? g_qh : ((z == 1) ? g_kh : g_vh);
    __nv_bfloat16* outl = (z == 0) ? g_ql : ((z == 1) ? g_kl : g_vl);
    const float scale = (z == 0) ? 0.125f : 1.0f;

    const __nv_bfloat16* ah = g_xh + (size_t)m0 * D_;
    const __nv_bfloat16* al = g_xl + (size_t)m0 * D_;
    const __nv_bfloat16* bh = g_wt_h + (size_t)(z * H_ + hp * 2) * DH_ * D_;
    const __nv_bfloat16* bl = g_wt_l + (size_t)(z * H_ + hp * 2) * DH_ * D_;

    float acc[4][4][4];
    #pragma unroll
    for (int i = 0; i < 4; ++i)
        #pragma unroll
        for (int j = 0; j < 4; ++j)
            #pragma unroll
            for (int q = 0; q < 4; ++q) acc[i][j][q] = 0.f;

    GEMM_MAINLOOP(ah, al, bh, bl)

    const int warp_m = wid & 1;
    const int warp_n = wid >> 1;
    #pragma unroll
    for (int i = 0; i < 4; ++i) {
        #pragma unroll
        for (int j = 0; j < 4; ++j) {
            int r0 = m0 + warp_m * 64 + i * 16 + (lane >> 2);
            int col = warp_n * 32 + j * 8 + (lane & 3) * 2;
            int hh = hp * 2 + (col >> 6);
            int ee = col & 63;
            #pragma unroll
            for (int half = 0; half < 2; ++half) {
                int r = r0 + half * 8;
                int b = r >> 11, s = r & 2047;
                float v0 = acc[i][j][2 * half] * scale;
                float v1 = acc[i][j][2 * half + 1] * scale;
                float h0, l0, h1, l1;
                bsplit(v0, h0, l0); bsplit(v1, h1, l1);
                size_t off = ((size_t)(b * H_ + hh) * S_ + s) * DH_ + ee;
                *(uint32_t*)(outh + off) = packbf(h0, h1);
                *(uint32_t*)(outl + off) = packbf(l0, l1);
            }
        }
    }
}

// ============================================================
// Kernel 3: output projection. grid = (64, 8), block 256, 2 CTAs/SM.
// ============================================================
__global__ __launch_bounds__(256, 2) void out_proj_mma_kernel(
    const float* __restrict__ bo, float* __restrict__ out)
{
    extern __shared__ char sm[];
    const uint32_t smb = smem_u32(sm);
    const int tid = threadIdx.x;
    const int wid = tid >> 5;
    const int lane = tid & 31;

    const int n0 = blockIdx.y * 128;
    const int m0 = blockIdx.x * 128;

    const __nv_bfloat16* ah = g_ch + (size_t)m0 * D_;
    const __nv_bfloat16* al = g_cl + (size_t)m0 * D_;
    const __nv_bfloat16* bh = g_wo_h + (size_t)n0 * D_;
    const __nv_bfloat16* bl = g_wo_l + (size_t)n0 * D_;

    float acc[4][4][4];
    #pragma unroll
    for (int i = 0; i < 4; ++i)
        #pragma unroll
        for (int j = 0; j < 4; ++j)
            #pragma unroll
            for (int q = 0; q < 4; ++q) acc[i][j][q] = 0.f;

    GEMM_MAINLOOP(ah, al, bh, bl)

    const int warp_m = wid & 1;
    const int warp_n = wid >> 1;
    #pragma unroll
    for (int i = 0; i < 4; ++i) {
        #pragma unroll
        for (int j = 0; j < 4; ++j) {
            int r0 = m0 + warp_m * 64 + i * 16 + (lane >> 2);
            int col = n0 + warp_n * 32 + j * 8 + (lane & 3) * 2;
            float b0 = bo[col], b1 = bo[col + 1];
            {
                float2 v; v.x = acc[i][j][0] + b0; v.y = acc[i][j][1] + b1;
                *(float2*)(out + (size_t)r0 * D_ + col) = v;
            }
            {
                float2 v; v.x = acc[i][j][2] + b0; v.y = acc[i][j][3] + b1;
                *(float2*)(out + (size_t)(r0 + 8) * D_ + col) = v;
            }
        }
    }
}

// ============================================================
// Kernel 2: causal flash attention (R6 2-stage KV), 2 CTAs/SM target.
// Smem: Qh 0, Ql 18432; KV stages at 36864 + st*36864.
// ============================================================
#define KV_STAGE 36864
#define ATTN_SMEM (36864 + 2 * KV_STAGE)

__device__ __forceinline__ void attn_load_kv(uint32_t kvb,
    const __nv_bfloat16* kh, const __nv_bfloat16* kl,
    const __nv_bfloat16* vh, const __nv_bfloat16* vl, int tid)
{
    const __nv_bfloat16* p[4] = {kh, kl, vh, vl};
    #pragma unroll
    for (int i = 0; i < 8; ++i) {
        int idx = tid + i * 256;
        int arr = idx >> 9;
        int c = idx & 511;
        int r = c >> 3, c8 = c & 7;
        const __nv_bfloat16* src = p[arr] + (size_t)r * DH_ + c8 * 8;
        uint32_t sa = kvb + arr * 9216 + r * 144 + c8 * 16;
        CP_A16(sa, src);
    }
}

__global__ __launch_bounds__(256, 2) void attn_mma_kernel()
{
    extern __shared__ char sm[];
    const uint32_t smb = smem_u32(sm);
    const int tid = threadIdx.x;
    const int wm = tid >> 5;
    const int lane = tid & 31;

    const int bh = blockIdx.y;
    const int qb = (gridDim.x - 1) - blockIdx.x;
    const int kmax = 2 * qb + 2;

    const uint32_t Qh_b = smb;
    const uint32_t Ql_b = smb + 18432;

    const __nv_bfloat16* kh_g = g_kh + (size_t)bh * S_ * DH_;
    const __nv_bfloat16* kl_g = g_kl + (size_t)bh * S_ * DH_;
    const __nv_bfloat16* vh_g = g_vh + (size_t)bh * S_ * DH_;
    const __nv_bfloat16* vl_g = g_vl + (size_t)bh * S_ * DH_;

    attn_load_kv(smb + 36864, kh_g, kl_g, vh_g, vl_g, tid);
    CP_COMMIT();

    {
        const __nv_bfloat16* qh_g = g_qh + ((size_t)bh * S_ + qb * 128) * DH_;
        const __nv_bfloat16* ql_g = g_ql + ((size_t)bh * S_ + qb * 128) * DH_;
        #pragma unroll
        for (int i = 0; i < 4; ++i) {
            int idx = tid + i * 256;
            int r = idx >> 3, c8 = idx & 7;
            *(uint4*)(sm + (Qh_b - smb) + r * 144 + c8 * 16) =
                *(const uint4*)(qh_g + (size_t)r * DH_ + c8 * 8);
            *(uint4*)(sm + (Ql_b - smb) + r * 144 + c8 * 16) =
                *(const uint4*)(ql_g + (size_t)r * DH_ + c8 * 8);
        }
    }
    __syncthreads();

    uint32_t qh[4][4], ql[4][4];
    {
        const int ar = wm * 16 + (lane & 15);
        const int koff = (lane >> 4) << 3;
        #pragma unroll
        for (int ks = 0; ks < 4; ++ks) {
            LDSM_X4(qh[ks][0], qh[ks][1], qh[ks][2], qh[ks][3],
                    Qh_b + ar * 144 + (ks * 16 + koff) * 2);
            LDSM_X4(ql[ks][0], ql[ks][1], ql[ks][2], ql[ks][3],
                    Ql_b + ar * 144 + (ks * 16 + koff) * 2);
        }
    }

    float mA = -3.0e38f, mB = -3.0e38f, lA = 0.f, lB = 0.f;
    float oacc[8][4];
    #pragma unroll
    for (int t = 0; t < 8; ++t)
        #pragma unroll
        for (int q = 0; q < 4; ++q) oacc[t][q] = 0.f;

    const int kb_row  = (lane & 7) + ((lane >> 4) << 3);
    const int kb_koff = ((lane >> 3) & 1) << 3;
    const int vb_row  = (lane & 7) + (((lane >> 3) & 1) << 3);
    const int vb_eoff = (lane >> 4) << 3;

    const int rA_g = qb * 128 + wm * 16 + (lane >> 2);

    for (int kt = 0; kt < kmax; ++kt) {
        if (kt + 1 < kmax) {
            size_t koff = (size_t)(kt + 1) * 64 * DH_;
            attn_load_kv(smb + 36864 + ((kt + 1) & 1) * KV_STAGE,
                         kh_g + koff, kl_g + koff, vh_g + koff, vl_g + koff, tid);
            CP_COMMIT();
            CP_WAIT(1);
        } else {
            CP_WAIT(0);
        }
        __syncthreads();

        const uint32_t kvb = smb + 36864 + (kt & 1) * KV_STAGE;
        const uint32_t Kh_b = kvb, Kl_b = kvb + 9216, Vh_b = kvb + 18432, Vl_b = kvb + 27648;

        // ---- S = Q K^T (split-3) ----
        float sacc[8][4];
        #pragma unroll
        for (int t = 0; t < 8; ++t)
            #pragma unroll
            for (int q = 0; q < 4; ++q) sacc[t][q] = 0.f;

        #pragma unroll
        for (int ks = 0; ks < 4; ++ks) {
            #pragma unroll
            for (int np = 0; np < 4; ++np) {
                uint32_t row = np * 16 + kb_row;
                uint32_t ko  = ks * 16 + kb_koff;
                uint32_t b0, b1, b2, b3, c0, c1, c2, c3;
                LDSM_X4(b0, b1, b2, b3, Kh_b + row * 144 + ko * 2);
                LDSM_X4(c0, c1, c2, c3, Kl_b + row * 144 + ko * 2);
                mma16816(sacc[2 * np],     qh[ks][0], qh[ks][1], qh[ks][2], qh[ks][3], b0, b1);
                mma16816(sacc[2 * np],     qh[ks][0], qh[ks][1], qh[ks][2], qh[ks][3], c0, c1);
                mma16816(sacc[2 * np],     ql[ks][0], ql[ks][1], ql[ks][2], ql[ks][3], b0, b1);
                mma16816(sacc[2 * np + 1], qh[ks][0], qh[ks][1], qh[ks][2], qh[ks][3], b2, b3);
                mma16816(sacc[2 * np + 1], qh[ks][0], qh[ks][1], qh[ks][2], qh[ks][3], c2, c3);
                mma16816(sacc[2 * np + 1], ql[ks][0], ql[ks][1], ql[ks][2], ql[ks][3], b2, b3);
            }
        }

        if (kt >= 2 * qb) {
            const int c0g = kt * 64 + 2 * (lane & 3);
            #pragma unroll
            for (int t = 0; t < 8; ++t) {
                int c = c0g + 8 * t;
                if (c     > rA_g)     sacc[t][0] = -3.0e38f;
                if (c + 1 > rA_g)     sacc[t][1] = -3.0e38f;
                if (c     > rA_g + 8) sacc[t][2] = -3.0e38f;
                if (c + 1 > rA_g + 8) sacc[t][3] = -3.0e38f;
            }
        }

        float mtA = -3.0e38f, mtB = -3.0e38f;
        #pragma unroll
        for (int t = 0; t < 8; ++t) {
            mtA = fmaxf(mtA, fmaxf(sacc[t][0], sacc[t][1]));
            mtB = fmaxf(mtB, fmaxf(sacc[t][2], sacc[t][3]));
        }
        mtA = fmaxf(mtA, __shfl_xor_sync(0xffffffffu, mtA, 1));
        mtA = fmaxf(mtA, __shfl_xor_sync(0xffffffffu, mtA, 2));
        mtB = fmaxf(mtB, __shfl_xor_sync(0xffffffffu, mtB, 1));
        mtB = fmaxf(mtB, __shfl_xor_sync(0xffffffffu, mtB, 2));

        float mnA = fmaxf(mA, mtA), mnB = fmaxf(mB, mtB);
        float corrA = __expf(mA - mnA), corrB = __expf(mB - mnB);

        float rsA = 0.f, rsB = 0.f;
        #pragma unroll
        for (int t = 0; t < 8; ++t) {
            float p0 = __expf(sacc[t][0] - mnA); sacc[t][0] = p0; rsA += p0;
            float p1 = __expf(sacc[t][1] - mnA); sacc[t][1] = p1; rsA += p1;
            float p2 = __expf(sacc[t][2] - mnB); sacc[t][2] = p2; rsB += p2;
            float p3 = __expf(sacc[t][3] - mnB); sacc[t][3] = p3; rsB += p3;
        }
        rsA += __shfl_xor_sync(0xffffffffu, rsA, 1);
        rsA += __shfl_xor_sync(0xffffffffu, rsA, 2);
        rsB += __shfl_xor_sync(0xffffffffu, rsB, 1);
        rsB += __shfl_xor_sync(0xffffffffu, rsB, 2);

        lA = lA * corrA + rsA;
        lB = lB * corrB + rsB;
        #pragma unroll
        for (int t = 0; t < 8; ++t) {
            oacc[t][0] *= corrA; oacc[t][1] *= corrA;
            oacc[t][2] *= corrB; oacc[t][3] *= corrB;
        }
        mA = mnA; mB = mnB;

        // ---- O += P V (split-3) ----
        #pragma unroll
        for (int ks = 0; ks < 4; ++ks) {
            uint32_t pfh[4], pfl[4];
            {
                float h00, l00, h01, l01, h10, l10, h11, l11;
                bsplit(sacc[2 * ks][0], h00, l00); bsplit(sacc[2 * ks][1], h01, l01);
                bsplit(sacc[2 * ks][2], h10, l10); bsplit(sacc[2 * ks][3], h11, l11);
                pfh[0] = packbf(h00, h01); pfl[0] = packbf(l00, l01);
                pfh[1] = packbf(h10, h11); pfl[1] = packbf(l10, l11);
                bsplit(sacc[2 * ks + 1][0], h00, l00); bsplit(sacc[2 * ks + 1][1], h01, l01);
                bsplit(sacc[2 * ks + 1][2], h10, l10); bsplit(sacc[2 * ks + 1][3], h11, l11);
                pfh[2] = packbf(h00, h01); pfl[2] = packbf(l00, l01);
                pfh[3] = packbf(h10, h11); pfl[3] = packbf(l10, l11);
            }
            #pragma unroll
            for (int ep = 0; ep < 4; ++ep) {
                uint32_t row = ks * 16 + vb_row;
                uint32_t eo  = ep * 16 + vb_eoff;
                uint32_t v0, v1, v2, v3, w0, w1, w2, w3;
                LDSM_X4_T(v0, v1, v2, v3, Vh_b + row * 144 + eo * 2);
                LDSM_X4_T(w0, w1, w2, w3, Vl_b + row * 144 + eo * 2);
                mma16816(oacc[2 * ep],     pfh[0], pfh[1], pfh[2], pfh[3], v0, v1);
                mma16816(oacc[2 * ep],     pfh[0], pfh[1], pfh[2], pfh[3], w0, w1);
                mma16816(oacc[2 * ep],     pfl[0], pfl[1], pfl[2], pfl[3], v0, v1);
                mma16816(oacc[2 * ep + 1], pfh[0], pfh[1], pfh[2], pfh[3], v2, v3);
                mma16816(oacc[2 * ep + 1], pfh[0], pfh[1], pfh[2], pfh[3], w2, w3);
                mma16816(oacc[2 * ep + 1], pfl[0], pfl[1], pfl[2], pfl[3], v2, v3);
            }
        }
        __syncthreads();
    }

    const float invA = 1.0f / lA;
    const float invB = 1.0f / lB;
    const int b = bh >> 4, h = bh & 15;
    const int e0 = 2 * (lane & 3);
    size_t baseA = ((size_t)b * S_ + rA_g) * D_ + h * DH_;
    size_t baseB = ((size_t)b * S_ + rA_g + 8) * D_ + h * DH_;
    #pragma unroll
    for (int t = 0; t < 8; ++t) {
        int e = 8 * t + e0;
        float a0 = oacc[t][0] * invA, a1 = oacc[t][1] * invA;
        float b0v = oacc[t][2] * invB, b1v = oacc[t][3] * invB;
        float h0, l0, h1, l1;
        bsplit(a0, h0, l0); bsplit(a1, h1, l1);
        *(uint32_t*)(g_ch + baseA + e) = packbf(h0, h1);
        *(uint32_t*)(g_cl + baseA + e) = packbf(l0, l1);
        bsplit(b0v, h0, l0); bsplit(b1v, h1, l1);
        *(uint32_t*)(g_ch + baseB + e) = packbf(h0, h1);
        *(uint32_t*)(g_cl + baseB + e) = packbf(l0, l1);
    }
}

// ============================================================
extern "C" void kernel_launch(void* const* d_in, const int* in_sizes, int n_in,
                              void* d_out, int out_size)
{
    const float* x  = (const float*)d_in[0];
    const float* Wq = (const float*)d_in[1];
    const float* Wk = (const float*)d_in[2];
    const float* Wv = (const float*)d_in[3];
    const float* Wo = (const float*)d_in[4];
    const float* bo = (const float*)d_in[5];
    float* out = (float*)d_out;

    cudaFuncSetAttribute(qkv_mma_kernel, cudaFuncAttributeMaxDynamicSharedMemorySize, GEMM_SMEM);
    cudaFuncSetAttribute(out_proj_mma_kernel, cudaFuncAttributeMaxDynamicSharedMemorySize, GEMM_SMEM);
    cudaFuncSetAttribute(attn_mma_kernel, cudaFuncAttributeMaxDynamicSharedMemorySize, ATTN_SMEM);

    conv_x_kernel<<<C_ELEMS / 4 / 256, 256>>>(x);
    conv_w_kernel<<<dim3(D_ / 64, H_, 3), 256>>>(Wq, Wk, Wv);
    conv_wo_kernel<<<dim3(D_ / 64, D_ / 64), 256>>>(Wo);
    qkv_mma_kernel<<<dim3(MROWS / 128, H_ / 2, 3), 256, GEMM_SMEM>>>();
    attn_mma_kernel<<<dim3(S_ / 128, B_ * H_), 256, ATTN_SMEM>>>();
    out_proj_mma_kernel<<<dim3(MROWS / 128, D_ / 128), 256, GEMM_SMEM>>>(bo, out);
}

// round 11
// speedup vs baseline: 1.1410x; 1.0417x over previous
#include <cuda_runtime.h>
#include <cuda_bf16.h>
#include <cstdint>

#define B_ 4
#define S_ 2048
#define D_ 1024
#define H_ 16
#define DH_ 64
#define MROWS (B_ * S_)
#define QKV_ELEMS (B_ * H_ * S_ * DH_)   // 8388608
#define C_ELEMS   (B_ * S_ * D_)         // 8388608

// -------- bf16 hi/lo scratch (no allocation) --------
__device__ __nv_bfloat16 g_xh[C_ELEMS],  g_xl[C_ELEMS];
__device__ __nv_bfloat16 g_wt_h[3 * H_ * DH_ * D_], g_wt_l[3 * H_ * DH_ * D_];
__device__ __nv_bfloat16 g_wo_h[D_ * D_], g_wo_l[D_ * D_];
__device__ __nv_bfloat16 g_qh[QKV_ELEMS], g_ql[QKV_ELEMS];
__device__ __nv_bfloat16 g_kh[QKV_ELEMS], g_kl[QKV_ELEMS];
__device__ __nv_bfloat16 g_vh[QKV_ELEMS], g_vl[QKV_ELEMS];
__device__ __nv_bfloat16 g_ch[C_ELEMS],  g_cl[C_ELEMS];

// work-steal counters: [0]=qkv, [1]=attn, [2]=out_proj
__device__ unsigned int g_ctrs[3];

#define PERSIST_CTAS 304

// ================= helpers =================
__device__ __forceinline__ uint32_t smem_u32(const void* p) {
    uint32_t a;
    asm("{ .reg .u64 t; cvta.to.shared.u64 t, %1; cvt.u32.u64 %0, t; }" : "=r"(a) : "l"(p));
    return a;
}
__device__ __forceinline__ void bsplit(float v, float& h, float& l) {
    __nv_bfloat16 bh = __float2bfloat16(v);
    h = __bfloat162float(bh);
    l = v - h;
}
__device__ __forceinline__ uint32_t packbf(float lo_elem, float hi_elem) {
    uint32_t r;
    asm("cvt.rn.bf16x2.f32 %0, %1, %2;" : "=r"(r) : "f"(hi_elem), "f"(lo_elem));
    return r;
}
#define LDSM_X4(r0, r1, r2, r3, addr) \
    asm volatile("ldmatrix.sync.aligned.m8n8.x4.shared.b16 {%0,%1,%2,%3}, [%4];" \
        : "=r"(r0), "=r"(r1), "=r"(r2), "=r"(r3) : "r"(addr))
#define LDSM_X4_T(r0, r1, r2, r3, addr) \
    asm volatile("ldmatrix.sync.aligned.m8n8.x4.trans.shared.b16 {%0,%1,%2,%3}, [%4];" \
        : "=r"(r0), "=r"(r1), "=r"(r2), "=r"(r3) : "r"(addr))
#define CP_A16(sa, gp) asm volatile("cp.async.ca.shared.global [%0], [%1], 16;" :: "r"(sa), "l"(gp))
#define CP_COMMIT()    asm volatile("cp.async.commit_group;" ::: "memory")
#define CP_WAIT(n)     asm volatile("cp.async.wait_group %0;" :: "n"(n) : "memory")

__device__ __forceinline__ void mma16816(float* c,
    uint32_t a0, uint32_t a1, uint32_t a2, uint32_t a3, uint32_t b0, uint32_t b1)
{
    asm volatile(
        "mma.sync.aligned.m16n8k16.row.col.f32.bf16.bf16.f32 "
        "{%0,%1,%2,%3}, {%4,%5,%6,%7}, {%8,%9}, {%0,%1,%2,%3};"
        : "+f"(c[0]), "+f"(c[1]), "+f"(c[2]), "+f"(c[3])
        : "r"(a0), "r"(a1), "r"(a2), "r"(a3), "r"(b0), "r"(b1));
}

// ============================================================
// Counter reset (captured into the graph; runs every replay)
// ============================================================
__global__ void reset_ctr_kernel()
{
    if (threadIdx.x < 3) g_ctrs[threadIdx.x] = 0u;
}

// ============================================================
// Preconversion kernels (unchanged)
// ============================================================
__global__ __launch_bounds__(256) void conv_x_kernel(const float* __restrict__ x)
{
    int i = blockIdx.x * 256 + threadIdx.x;
    float4 v = *(const float4*)(x + 4 * (size_t)i);
    float hx, lx, hy, ly, hz, lz, hw, lw;
    bsplit(v.x, hx, lx); bsplit(v.y, hy, ly);
    bsplit(v.z, hz, lz); bsplit(v.w, hw, lw);
    uint2 wh, wl;
    wh.x = packbf(hx, hy); wh.y = packbf(hz, hw);
    wl.x = packbf(lx, ly); wl.y = packbf(lz, lw);
    *(uint2*)(g_xh + 4 * (size_t)i) = wh;
    *(uint2*)(g_xl + 4 * (size_t)i) = wl;
}

__global__ __launch_bounds__(256) void conv_w_kernel(
    const float* __restrict__ Wq, const float* __restrict__ Wk, const float* __restrict__ Wv)
{
    __shared__ float ts[64][65];
    const int tid = threadIdx.x;
    const int d0 = blockIdx.x * 64;
    const int h  = blockIdx.y;
    const int z  = blockIdx.z;
    const float* W = (z == 0) ? Wq : ((z == 1) ? Wk : Wv);
    const float* src = W + (size_t)h * D_ * DH_;

    #pragma unroll
    for (int i = 0; i < 4; ++i) {
        int idx = tid + i * 256;
        int rr = idx >> 4, cc = idx & 15;
        float4 v = *(const float4*)(src + (size_t)(d0 + rr) * DH_ + cc * 4);
        ts[rr][cc * 4 + 0] = v.x; ts[rr][cc * 4 + 1] = v.y;
        ts[rr][cc * 4 + 2] = v.z; ts[rr][cc * 4 + 3] = v.w;
    }
    __syncthreads();
    #pragma unroll
    for (int i = 0; i < 8; ++i) {
        int idx = tid + i * 256;
        int e = idx >> 5, w = idx & 31;
        float v0 = ts[2 * w][e], v1 = ts[2 * w + 1][e];
        float h0, l0, h1, l1;
        bsplit(v0, h0, l0); bsplit(v1, h1, l1);
        size_t off = ((size_t)(z * H_ + h) * DH_ + e) * D_ + d0 + 2 * w;
        *(uint32_t*)(g_wt_h + off) = packbf(h0, h1);
        *(uint32_t*)(g_wt_l + off) = packbf(l0, l1);
    }
}

__global__ __launch_bounds__(256) void conv_wo_kernel(const float* __restrict__ Wo)
{
    __shared__ float ts[64][65];
    const int tid = threadIdx.x;
    const int d0 = blockIdx.x * 64;
    const int f0 = blockIdx.y * 64;

    #pragma unroll
    for (int i = 0; i < 4; ++i) {
        int idx = tid + i * 256;
        int rr = idx >> 4, cc = idx & 15;
        float4 v = *(const float4*)(Wo + (size_t)(d0 + rr) * D_ + f0 + cc * 4);
        ts[rr][cc * 4 + 0] = v.x; ts[rr][cc * 4 + 1] = v.y;
        ts[rr][cc * 4 + 2] = v.z; ts[rr][cc * 4 + 3] = v.w;
    }
    __syncthreads();
    #pragma unroll
    for (int i = 0; i < 8; ++i) {
        int idx = tid + i * 256;
        int e = idx >> 5, w = idx & 31;
        float v0 = ts[2 * w][e], v1 = ts[2 * w + 1][e];
        float h0, l0, h1, l1;
        bsplit(v0, h0, l0); bsplit(v1, h1, l1);
        size_t off = (size_t)(f0 + e) * D_ + d0 + 2 * w;
        *(uint32_t*)(g_wo_h + off) = packbf(h0, h1);
        *(uint32_t*)(g_wo_l + off) = packbf(l0, l1);
    }
}

// ============================================================
// GEMM machinery (R10): 128x128 tile, BK=32, 8 warps (64x32 warp tile),
// double-buffered cp.async, 2 CTAs/SM, persistent work-stealing.
// ============================================================
#define GEMM_STAGE 40960
#define GEMM_SMEM (2 * GEMM_STAGE)
#define NKT (D_ / 32)

__device__ __forceinline__ void gemm_load_stage(uint32_t sbase,
    const __nv_bfloat16* p0, const __nv_bfloat16* p1,
    const __nv_bfloat16* p2, const __nv_bfloat16* p3, int tid)
{
    const __nv_bfloat16* p[4] = {p0, p1, p2, p3};
    #pragma unroll
    for (int i = 0; i < 8; ++i) {
        int idx = tid + i * 256;
        int arr = idx >> 9;
        int c = idx & 511;
        int r = c >> 2, col = c & 3;
        const __nv_bfloat16* src = p[arr] + (size_t)r * D_ + col * 8;
        uint32_t sa = sbase + arr * 10240 + r * 80 + col * 16;
        CP_A16(sa, src);
    }
}

__device__ __forceinline__ void mma_phase(uint32_t sbase, float acc[4][4][4], int wid, int lane)
{
    const int warp_m = wid & 1;
    const int warp_n = wid >> 1;
    const uint32_t a_hi_b = sbase;
    const uint32_t a_lo_b = sbase + 10240;
    const uint32_t b_hi_b = sbase + 20480;
    const uint32_t b_lo_b = sbase + 30720;

    const int a_row = warp_m * 64 + (lane & 15);
    const int a_kh  = (lane >> 4) << 3;
    const int b_row = warp_n * 32 + (lane & 7) + ((lane >> 4) << 3);
    const int b_kh  = ((lane >> 3) & 1) << 3;

    #pragma unroll
    for (int ks = 0; ks < 2; ++ks) {
        const int koff = ks * 16;
        uint32_t ah[4][4], bh[2][4], bl[2][4];
        #pragma unroll
        for (int i = 0; i < 4; ++i) {
            uint32_t addr = a_hi_b + ((a_row + i * 16) * 40 + koff + a_kh) * 2;
            LDSM_X4(ah[i][0], ah[i][1], ah[i][2], ah[i][3], addr);
        }
        #pragma unroll
        for (int jj = 0; jj < 2; ++jj) {
            uint32_t addr = b_hi_b + ((b_row + jj * 16) * 40 + koff + b_kh) * 2;
            LDSM_X4(bh[jj][0], bh[jj][1], bh[jj][2], bh[jj][3], addr);
            uint32_t addr2 = b_lo_b + ((b_row + jj * 16) * 40 + koff + b_kh) * 2;
            LDSM_X4(bl[jj][0], bl[jj][1], bl[jj][2], bl[jj][3], addr2);
        }
        #pragma unroll
        for (int i = 0; i < 4; ++i)
            #pragma unroll
            for (int j = 0; j < 4; ++j) {
                int jj = j >> 1, s = (j & 1) * 2;
                mma16816(acc[i][j], ah[i][0], ah[i][1], ah[i][2], ah[i][3], bh[jj][s], bh[jj][s + 1]);
                mma16816(acc[i][j], ah[i][0], ah[i][1], ah[i][2], ah[i][3], bl[jj][s], bl[jj][s + 1]);
            }
        #pragma unroll
        for (int i = 0; i < 4; ++i) {
            uint32_t addr = a_lo_b + ((a_row + i * 16) * 40 + koff + a_kh) * 2;
            LDSM_X4(ah[i][0], ah[i][1], ah[i][2], ah[i][3], addr);
        }
        #pragma unroll
        for (int i = 0; i < 4; ++i)
            #pragma unroll
            for (int j = 0; j < 4; ++j) {
                int jj = j >> 1, s = (j & 1) * 2;
                mma16816(acc[i][j], ah[i][0], ah[i][1], ah[i][2], ah[i][3], bh[jj][s], bh[jj][s + 1]);
            }
    }
}

#define GEMM_MAINLOOP(AH, AL, BH, BL)                                          \
    gemm_load_stage(smb, (AH), (AL), (BH), (BL), tid);                         \
    CP_COMMIT();                                                               \
    for (int kt = 0; kt < NKT; ++kt) {                                         \
        if (kt + 1 < NKT) {                                                    \
            int k1 = (kt + 1) * 32;                                            \
            gemm_load_stage(smb + ((kt + 1) & 1) * GEMM_STAGE,                 \
                            (AH) + k1, (AL) + k1, (BH) + k1, (BL) + k1, tid);  \
            CP_COMMIT();                                                       \
            CP_WAIT(1);                                                        \
        } else {                                                               \
            CP_WAIT(0);                                                        \
        }                                                                      \
        __syncthreads();                                                       \
        mma_phase(smb + (kt & 1) * GEMM_STAGE, acc, wid, lane);                \
        __syncthreads();                                                       \
    }

// ============================================================
// Kernel 1: QKV projection, persistent. tiles = 64*8*3 = 1536.
// idx -> (mx = idx&63, hp = (idx>>6)&7, z = idx>>9)
// ============================================================
#define QKV_TILES 1536

__global__ __launch_bounds__(256, 2) void qkv_mma_kernel()
{
    extern __shared__ char sm[];
    __shared__ int s_idx;
    const uint32_t smb = smem_u32(sm);
    const int tid = threadIdx.x;
    const int wid = tid >> 5;
    const int lane = tid & 31;

    for (;;) {
        if (tid == 0) s_idx = (int)atomicAdd(&g_ctrs[0], 1u);
        __syncthreads();
        const int idx = s_idx;
        if (idx >= QKV_TILES) return;

        const int m0 = (idx & 63) * 128;
        const int hp = (idx >> 6) & 7;
        const int z  = idx >> 9;

        __nv_bfloat16* outh = (z == 0) ? g_qh : ((z == 1) ? g_kh : g_vh);
        __nv_bfloat16* outl = (z == 0) ? g_ql : ((z == 1) ? g_kl : g_vl);
        const float scale = (z == 0) ? 0.125f : 1.0f;

        const __nv_bfloat16* ah = g_xh + (size_t)m0 * D_;
        const __nv_bfloat16* al = g_xl + (size_t)m0 * D_;
        const __nv_bfloat16* bh = g_wt_h + (size_t)(z * H_ + hp * 2) * DH_ * D_;
        const __nv_bfloat16* bl = g_wt_l + (size_t)(z * H_ + hp * 2) * DH_ * D_;

        float acc[4][4][4];
        #pragma unroll
        for (int i = 0; i < 4; ++i)
            #pragma unroll
            for (int j = 0; j < 4; ++j)
                #pragma unroll
                for (int q = 0; q < 4; ++q) acc[i][j][q] = 0.f;

        GEMM_MAINLOOP(ah, al, bh, bl)

        const int warp_m = wid & 1;
        const int warp_n = wid >> 1;
        #pragma unroll
        for (int i = 0; i < 4; ++i) {
            #pragma unroll
            for (int j = 0; j < 4; ++j) {
                int r0 = m0 + warp_m * 64 + i * 16 + (lane >> 2);
                int col = warp_n * 32 + j * 8 + (lane & 3) * 2;
                int hh = hp * 2 + (col >> 6);
                int ee = col & 63;
                #pragma unroll
                for (int half = 0; half < 2; ++half) {
                    int r = r0 + half * 8;
                    int b = r >> 11, s = r & 2047;
                    float v0 = acc[i][j][2 * half] * scale;
                    float v1 = acc[i][j][2 * half + 1] * scale;
                    float h0, l0, h1, l1;
                    bsplit(v0, h0, l0); bsplit(v1, h1, l1);
                    size_t off = ((size_t)(b * H_ + hh) * S_ + s) * DH_ + ee;
                    *(uint32_t*)(outh + off) = packbf(h0, h1);
                    *(uint32_t*)(outl + off) = packbf(l0, l1);
                }
            }
        }
        __syncthreads();   // all threads done with s_idx before next fetch
    }
}

// ============================================================
// Kernel 3: output projection, persistent. tiles = 64*8 = 512.
// idx -> (mx = idx&63, n-slab = idx>>6)
// ============================================================
#define OUT_TILES 512

__global__ __launch_bounds__(256, 2) void out_proj_mma_kernel(
    const float* __restrict__ bo, float* __restrict__ out)
{
    extern __shared__ char sm[];
    __shared__ int s_idx;
    const uint32_t smb = smem_u32(sm);
    const int tid = threadIdx.x;
    const int wid = tid >> 5;
    const int lane = tid & 31;

    for (;;) {
        if (tid == 0) s_idx = (int)atomicAdd(&g_ctrs[2], 1u);
        __syncthreads();
        const int idx = s_idx;
        if (idx >= OUT_TILES) return;

        const int m0 = (idx & 63) * 128;
        const int n0 = (idx >> 6) * 128;

        const __nv_bfloat16* ah = g_ch + (size_t)m0 * D_;
        const __nv_bfloat16* al = g_cl + (size_t)m0 * D_;
        const __nv_bfloat16* bh = g_wo_h + (size_t)n0 * D_;
        const __nv_bfloat16* bl = g_wo_l + (size_t)n0 * D_;

        float acc[4][4][4];
        #pragma unroll
        for (int i = 0; i < 4; ++i)
            #pragma unroll
            for (int j = 0; j < 4; ++j)
                #pragma unroll
                for (int q = 0; q < 4; ++q) acc[i][j][q] = 0.f;

        GEMM_MAINLOOP(ah, al, bh, bl)

        const int warp_m = wid & 1;
        const int warp_n = wid >> 1;
        #pragma unroll
        for (int i = 0; i < 4; ++i) {
            #pragma unroll
            for (int j = 0; j < 4; ++j) {
                int r0 = m0 + warp_m * 64 + i * 16 + (lane >> 2);
                int col = n0 + warp_n * 32 + j * 8 + (lane & 3) * 2;
                float b0 = bo[col], b1 = bo[col + 1];
                {
                    float2 v; v.x = acc[i][j][0] + b0; v.y = acc[i][j][1] + b1;
                    *(float2*)(out + (size_t)r0 * D_ + col) = v;
                }
                {
                    float2 v; v.x = acc[i][j][2] + b0; v.y = acc[i][j][3] + b1;
                    *(float2*)(out + (size_t)(r0 + 8) * D_ + col) = v;
                }
            }
        }
        __syncthreads();
    }
}

// ============================================================
// Kernel 2: causal flash attention, persistent + LPT stealing.
// tiles = 64 bh * 16 qb = 1024; idx -> qb = 15 - (idx>>6) [expensive first],
// bh = idx & 63.
// ============================================================
#define KV_STAGE 36864
#define ATTN_SMEM (36864 + 2 * KV_STAGE)
#define ATTN_TILES 1024

__device__ __forceinline__ void attn_load_kv(uint32_t kvb,
    const __nv_bfloat16* kh, const __nv_bfloat16* kl,
    const __nv_bfloat16* vh, const __nv_bfloat16* vl, int tid)
{
    const __nv_bfloat16* p[4] = {kh, kl, vh, vl};
    #pragma unroll
    for (int i = 0; i < 8; ++i) {
        int idx = tid + i * 256;
        int arr = idx >> 9;
        int c = idx & 511;
        int r = c >> 3, c8 = c & 7;
        const __nv_bfloat16* src = p[arr] + (size_t)r * DH_ + c8 * 8;
        uint32_t sa = kvb + arr * 9216 + r * 144 + c8 * 16;
        CP_A16(sa, src);
    }
}

__global__ __launch_bounds__(256, 2) void attn_mma_kernel()
{
    extern __shared__ char sm[];
    __shared__ int s_idx;
    const uint32_t smb = smem_u32(sm);
    const int tid = threadIdx.x;
    const int wm = tid >> 5;
    const int lane = tid & 31;

    const uint32_t Qh_b = smb;
    const uint32_t Ql_b = smb + 18432;

    for (;;) {
        if (tid == 0) s_idx = (int)atomicAdd(&g_ctrs[1], 1u);
        __syncthreads();
        const int idx = s_idx;
        if (idx >= ATTN_TILES) return;

        const int qb = 15 - (idx >> 6);   // expensive tiles first (LPT)
        const int bh = idx & 63;
        const int kmax = 2 * qb + 2;

        const __nv_bfloat16* kh_g = g_kh + (size_t)bh * S_ * DH_;
        const __nv_bfloat16* kl_g = g_kl + (size_t)bh * S_ * DH_;
        const __nv_bfloat16* vh_g = g_vh + (size_t)bh * S_ * DH_;
        const __nv_bfloat16* vl_g = g_vl + (size_t)bh * S_ * DH_;

        attn_load_kv(smb + 36864, kh_g, kl_g, vh_g, vl_g, tid);
        CP_COMMIT();

        {
            const __nv_bfloat16* qh_g = g_qh + ((size_t)bh * S_ + qb * 128) * DH_;
            const __nv_bfloat16* ql_g = g_ql + ((size_t)bh * S_ + qb * 128) * DH_;
            #pragma unroll
            for (int i = 0; i < 4; ++i) {
                int ii = tid + i * 256;
                int r = ii >> 3, c8 = ii & 7;
                *(uint4*)(sm + (Qh_b - smb) + r * 144 + c8 * 16) =
                    *(const uint4*)(qh_g + (size_t)r * DH_ + c8 * 8);
                *(uint4*)(sm + (Ql_b - smb) + r * 144 + c8 * 16) =
                    *(const uint4*)(ql_g + (size_t)r * DH_ + c8 * 8);
            }
        }
        __syncthreads();

        uint32_t qh[4][4], ql[4][4];
        {
            const int ar = wm * 16 + (lane & 15);
            const int koff = (lane >> 4) << 3;
            #pragma unroll
            for (int ks = 0; ks < 4; ++ks) {
                LDSM_X4(qh[ks][0], qh[ks][1], qh[ks][2], qh[ks][3],
                        Qh_b + ar * 144 + (ks * 16 + koff) * 2);
                LDSM_X4(ql[ks][0], ql[ks][1], ql[ks][2], ql[ks][3],
                        Ql_b + ar * 144 + (ks * 16 + koff) * 2);
            }
        }

        float mA = -3.0e38f, mB = -3.0e38f, lA = 0.f, lB = 0.f;
        float oacc[8][4];
        #pragma unroll
        for (int t = 0; t < 8; ++t)
            #pragma unroll
            for (int q = 0; q < 4; ++q) oacc[t][q] = 0.f;

        const int kb_row  = (lane & 7) + ((lane >> 4) << 3);
        const int kb_koff = ((lane >> 3) & 1) << 3;
        const int vb_row  = (lane & 7) + (((lane >> 3) & 1) << 3);
        const int vb_eoff = (lane >> 4) << 3;

        const int rA_g = qb * 128 + wm * 16 + (lane >> 2);

        for (int kt = 0; kt < kmax; ++kt) {
            if (kt + 1 < kmax) {
                size_t koff = (size_t)(kt + 1) * 64 * DH_;
                attn_load_kv(smb + 36864 + ((kt + 1) & 1) * KV_STAGE,
                             kh_g + koff, kl_g + koff, vh_g + koff, vl_g + koff, tid);
                CP_COMMIT();
                CP_WAIT(1);
            } else {
                CP_WAIT(0);
            }
            __syncthreads();

            const uint32_t kvb = smb + 36864 + (kt & 1) * KV_STAGE;
            const uint32_t Kh_b = kvb, Kl_b = kvb + 9216, Vh_b = kvb + 18432, Vl_b = kvb + 27648;

            float sacc[8][4];
            #pragma unroll
            for (int t = 0; t < 8; ++t)
                #pragma unroll
                for (int q = 0; q < 4; ++q) sacc[t][q] = 0.f;

            #pragma unroll
            for (int ks = 0; ks < 4; ++ks) {
                #pragma unroll
                for (int np = 0; np < 4; ++np) {
                    uint32_t row = np * 16 + kb_row;
                    uint32_t ko  = ks * 16 + kb_koff;
                    uint32_t b0, b1, b2, b3, c0, c1, c2, c3;
                    LDSM_X4(b0, b1, b2, b3, Kh_b + row * 144 + ko * 2);
                    LDSM_X4(c0, c1, c2, c3, Kl_b + row * 144 + ko * 2);
                    mma16816(sacc[2 * np],     qh[ks][0], qh[ks][1], qh[ks][2], qh[ks][3], b0, b1);
                    mma16816(sacc[2 * np],     qh[ks][0], qh[ks][1], qh[ks][2], qh[ks][3], c0, c1);
                    mma16816(sacc[2 * np],     ql[ks][0], ql[ks][1], ql[ks][2], ql[ks][3], b0, b1);
                    mma16816(sacc[2 * np + 1], qh[ks][0], qh[ks][1], qh[ks][2], qh[ks][3], b2, b3);
                    mma16816(sacc[2 * np + 1], qh[ks][0], qh[ks][1], qh[ks][2], qh[ks][3], c2, c3);
                    mma16816(sacc[2 * np + 1], ql[ks][0], ql[ks][1], ql[ks][2], ql[ks][3], b2, b3);
                }
            }

            if (kt >= 2 * qb) {
                const int c0g = kt * 64 + 2 * (lane & 3);
                #pragma unroll
                for (int t = 0; t < 8; ++t) {
                    int c = c0g + 8 * t;
                    if (c     > rA_g)     sacc[t][0] = -3.0e38f;
                    if (c + 1 > rA_g)     sacc[t][1] = -3.0e38f;
                    if (c     > rA_g + 8) sacc[t][2] = -3.0e38f;
                    if (c + 1 > rA_g + 8) sacc[t][3] = -3.0e38f;
                }
            }

            float mtA = -3.0e38f, mtB = -3.0e38f;
            #pragma unroll
            for (int t = 0; t < 8; ++t) {
                mtA = fmaxf(mtA, fmaxf(sacc[t][0], sacc[t][1]));
                mtB = fmaxf(mtB, fmaxf(sacc[t][2], sacc[t][3]));
            }
            mtA = fmaxf(mtA, __shfl_xor_sync(0xffffffffu, mtA, 1));
            mtA = fmaxf(mtA, __shfl_xor_sync(0xffffffffu, mtA, 2));
            mtB = fmaxf(mtB, __shfl_xor_sync(0xffffffffu, mtB, 1));
            mtB = fmaxf(mtB, __shfl_xor_sync(0xffffffffu, mtB, 2));

            float mnA = fmaxf(mA, mtA), mnB = fmaxf(mB, mtB);
            float corrA = __expf(mA - mnA), corrB = __expf(mB - mnB);

            float rsA = 0.f, rsB = 0.f;
            #pragma unroll
            for (int t = 0; t < 8; ++t) {
                float p0 = __expf(sacc[t][0] - mnA); sacc[t][0] = p0; rsA += p0;
                float p1 = __expf(sacc[t][1] - mnA); sacc[t][1] = p1; rsA += p1;
                float p2 = __expf(sacc[t][2] - mnB); sacc[t][2] = p2; rsB += p2;
                float p3 = __expf(sacc[t][3] - mnB); sacc[t][3] = p3; rsB += p3;
            }
            rsA += __shfl_xor_sync(0xffffffffu, rsA, 1);
            rsA += __shfl_xor_sync(0xffffffffu, rsA, 2);
            rsB += __shfl_xor_sync(0xffffffffu, rsB, 1);
            rsB += __shfl_xor_sync(0xffffffffu, rsB, 2);

            lA = lA * corrA + rsA;
            lB = lB * corrB + rsB;
            #pragma unroll
            for (int t = 0; t < 8; ++t) {
                oacc[t][0] *= corrA; oacc[t][1] *= corrA;
                oacc[t][2] *= corrB; oacc[t][3] *= corrB;
            }
            mA = mnA; mB = mnB;

            #pragma unroll
            for (int ks = 0; ks < 4; ++ks) {
                uint32_t pfh[4], pfl[4];
                {
                    float h00, l00, h01, l01, h10, l10, h11, l11;
                    bsplit(sacc[2 * ks][0], h00, l00); bsplit(sacc[2 * ks][1], h01, l01);
                    bsplit(sacc[2 * ks][2], h10, l10); bsplit(sacc[2 * ks][3], h11, l11);
                    pfh[0] = packbf(h00, h01); pfl[0] = packbf(l00, l01);
                    pfh[1] = packbf(h10, h11); pfl[1] = packbf(l10, l11);
                    bsplit(sacc[2 * ks + 1][0], h00, l00); bsplit(sacc[2 * ks + 1][1], h01, l01);
                    bsplit(sacc[2 * ks + 1][2], h10, l10); bsplit(sacc[2 * ks + 1][3], h11, l11);
                    pfh[2] = packbf(h00, h01); pfl[2] = packbf(l00, l01);
                    pfh[3] = packbf(h10, h11); pfl[3] = packbf(l10, l11);
                }
                #pragma unroll
                for (int ep = 0; ep < 4; ++ep) {
                    uint32_t row = ks * 16 + vb_row;
                    uint32_t eo  = ep * 16 + vb_eoff;
                    uint32_t v0, v1, v2, v3, w0, w1, w2, w3;
                    LDSM_X4_T(v0, v1, v2, v3, Vh_b + row * 144 + eo * 2);
                    LDSM_X4_T(w0, w1, w2, w3, Vl_b + row * 144 + eo * 2);
                    mma16816(oacc[2 * ep],     pfh[0], pfh[1], pfh[2], pfh[3], v0, v1);
                    mma16816(oacc[2 * ep],     pfh[0], pfh[1], pfh[2], pfh[3], w0, w1);
                    mma16816(oacc[2 * ep],     pfl[0], pfl[1], pfl[2], pfl[3], v0, v1);
                    mma16816(oacc[2 * ep + 1], pfh[0], pfh[1], pfh[2], pfh[3], v2, v3);
                    mma16816(oacc[2 * ep + 1], pfh[0], pfh[1], pfh[2], pfh[3], w2, w3);
                    mma16816(oacc[2 * ep + 1], pfl[0], pfl[1], pfl[2], pfl[3], v2, v3);
                }
            }
            __syncthreads();
        }

        const float invA = 1.0f / lA;
        const float invB = 1.0f / lB;
        const int b = bh >> 4, h = bh & 15;
        const int e0 = 2 * (lane & 3);
        size_t baseA = ((size_t)b * S_ + rA_g) * D_ + h * DH_;
        size_t baseB = ((size_t)b * S_ + rA_g + 8) * D_ + h * DH_;
        #pragma unroll
        for (int t = 0; t < 8; ++t) {
            int e = 8 * t + e0;
            float a0 = oacc[t][0] * invA, a1 = oacc[t][1] * invA;
            float b0v = oacc[t][2] * invB, b1v = oacc[t][3] * invB;
            float h0, l0, h1, l1;
            bsplit(a0, h0, l0); bsplit(a1, h1, l1);
            *(uint32_t*)(g_ch + baseA + e) = packbf(h0, h1);
            *(uint32_t*)(g_cl + baseA + e) = packbf(l0, l1);
            bsplit(b0v, h0, l0); bsplit(b1v, h1, l1);
            *(uint32_t*)(g_ch + baseB + e) = packbf(h0, h1);
            *(uint32_t*)(g_cl + baseB + e) = packbf(l0, l1);
        }
        __syncthreads();
    }
}

// ============================================================
extern "C" void kernel_launch(void* const* d_in, const int* in_sizes, int n_in,
                              void* d_out, int out_size)
{
    const float* x  = (const float*)d_in[0];
    const float* Wq = (const float*)d_in[1];
    const float* Wk = (const float*)d_in[2];
    const float* Wv = (const float*)d_in[3];
    const float* Wo = (const float*)d_in[4];
    const float* bo = (const float*)d_in[5];
    float* out = (float*)d_out;

    cudaFuncSetAttribute(qkv_mma_kernel, cudaFuncAttributeMaxDynamicSharedMemorySize, GEMM_SMEM);
    cudaFuncSetAttribute(out_proj_mma_kernel, cudaFuncAttributeMaxDynamicSharedMemorySize, GEMM_SMEM);
    cudaFuncSetAttribute(attn_mma_kernel, cudaFuncAttributeMaxDynamicSharedMemorySize, ATTN_SMEM);

    reset_ctr_kernel<<<1, 32>>>();
    conv_x_kernel<<<C_ELEMS / 4 / 256, 256>>>(x);
    conv_w_kernel<<<dim3(D_ / 64, H_, 3), 256>>>(Wq, Wk, Wv);
    conv_wo_kernel<<<dim3(D_ / 64, D_ / 64), 256>>>(Wo);
    qkv_mma_kernel<<<PERSIST_CTAS, 256, GEMM_SMEM>>>();
    attn_mma_kernel<<<PERSIST_CTAS, 256, ATTN_SMEM>>>();
    out_proj_mma_kernel<<<PERSIST_CTAS, 256, GEMM_SMEM>>>(bo, out);
}

// round 12
// speedup vs baseline: 1.2055x; 1.0565x over previous
#include <cuda_runtime.h>
#include <cuda_bf16.h>
#include <cstdint>

#define B_ 4
#define S_ 2048
#define D_ 1024
#define H_ 16
#define DH_ 64
#define MROWS (B_ * S_)
#define QKV_ELEMS (B_ * H_ * S_ * DH_)   // 8388608
#define C_ELEMS   (B_ * S_ * D_)         // 8388608

// -------- bf16 hi/lo scratch (no allocation) --------
__device__ __nv_bfloat16 g_xh[C_ELEMS],  g_xl[C_ELEMS];
__device__ __nv_bfloat16 g_wt_h[3 * H_ * DH_ * D_], g_wt_l[3 * H_ * DH_ * D_];
__device__ __nv_bfloat16 g_wo_h[D_ * D_], g_wo_l[D_ * D_];
__device__ __nv_bfloat16 g_qh[QKV_ELEMS], g_ql[QKV_ELEMS];
__device__ __nv_bfloat16 g_kh[QKV_ELEMS], g_kl[QKV_ELEMS];
__device__ __nv_bfloat16 g_vh[QKV_ELEMS], g_vl[QKV_ELEMS];
__device__ __nv_bfloat16 g_ch[C_ELEMS],  g_cl[C_ELEMS];

// work-steal counters: [0]=qkv, [1]=attn, [2]=out_proj
__device__ unsigned int g_ctrs[3];

#define PERSIST_CTAS 304

// ================= helpers =================
__device__ __forceinline__ uint32_t smem_u32(const void* p) {
    uint32_t a;
    asm("{ .reg .u64 t; cvta.to.shared.u64 t, %1; cvt.u32.u64 %0, t; }" : "=r"(a) : "l"(p));
    return a;
}
__device__ __forceinline__ void bsplit(float v, float& h, float& l) {
    __nv_bfloat16 bh = __float2bfloat16(v);
    h = __bfloat162float(bh);
    l = v - h;
}
__device__ __forceinline__ uint32_t packbf(float lo_elem, float hi_elem) {
    uint32_t r;
    asm("cvt.rn.bf16x2.f32 %0, %1, %2;" : "=r"(r) : "f"(hi_elem), "f"(lo_elem));
    return r;
}
#define LDSM_X4(r0, r1, r2, r3, addr) \
    asm volatile("ldmatrix.sync.aligned.m8n8.x4.shared.b16 {%0,%1,%2,%3}, [%4];" \
        : "=r"(r0), "=r"(r1), "=r"(r2), "=r"(r3) : "r"(addr))
#define LDSM_X4_T(r0, r1, r2, r3, addr) \
    asm volatile("ldmatrix.sync.aligned.m8n8.x4.trans.shared.b16 {%0,%1,%2,%3}, [%4];" \
        : "=r"(r0), "=r"(r1), "=r"(r2), "=r"(r3) : "r"(addr))
#define CP_A16(sa, gp) asm volatile("cp.async.ca.shared.global [%0], [%1], 16;" :: "r"(sa), "l"(gp))
#define CP_COMMIT()    asm volatile("cp.async.commit_group;" ::: "memory")
#define CP_WAIT(n)     asm volatile("cp.async.wait_group %0;" :: "n"(n) : "memory")

__device__ __forceinline__ void mma16816(float* c,
    uint32_t a0, uint32_t a1, uint32_t a2, uint32_t a3, uint32_t b0, uint32_t b1)
{
    asm volatile(
        "mma.sync.aligned.m16n8k16.row.col.f32.bf16.bf16.f32 "
        "{%0,%1,%2,%3}, {%4,%5,%6,%7}, {%8,%9}, {%0,%1,%2,%3};"
        : "+f"(c[0]), "+f"(c[1]), "+f"(c[2]), "+f"(c[3])
        : "r"(a0), "r"(a1), "r"(a2), "r"(a3), "r"(b0), "r"(b1));
}

// ============================================================
// Preconversion kernels (conv_x also resets work counters)
// ============================================================
__global__ __launch_bounds__(256) void conv_x_kernel(const float* __restrict__ x)
{
    if (blockIdx.x == 0 && threadIdx.x < 3) g_ctrs[threadIdx.x] = 0u;
    int i = blockIdx.x * 256 + threadIdx.x;
    float4 v = *(const float4*)(x + 4 * (size_t)i);
    float hx, lx, hy, ly, hz, lz, hw, lw;
    bsplit(v.x, hx, lx); bsplit(v.y, hy, ly);
    bsplit(v.z, hz, lz); bsplit(v.w, hw, lw);
    uint2 wh, wl;
    wh.x = packbf(hx, hy); wh.y = packbf(hz, hw);
    wl.x = packbf(lx, ly); wl.y = packbf(lz, lw);
    *(uint2*)(g_xh + 4 * (size_t)i) = wh;
    *(uint2*)(g_xl + 4 * (size_t)i) = wl;
}

__global__ __launch_bounds__(256) void conv_w_kernel(
    const float* __restrict__ Wq, const float* __restrict__ Wk, const float* __restrict__ Wv)
{
    __shared__ float ts[64][65];
    const int tid = threadIdx.x;
    const int d0 = blockIdx.x * 64;
    const int h  = blockIdx.y;
    const int z  = blockIdx.z;
    const float* W = (z == 0) ? Wq : ((z == 1) ? Wk : Wv);
    const float* src = W + (size_t)h * D_ * DH_;

    #pragma unroll
    for (int i = 0; i < 4; ++i) {
        int idx = tid + i * 256;
        int rr = idx >> 4, cc = idx & 15;
        float4 v = *(const float4*)(src + (size_t)(d0 + rr) * DH_ + cc * 4);
        ts[rr][cc * 4 + 0] = v.x; ts[rr][cc * 4 + 1] = v.y;
        ts[rr][cc * 4 + 2] = v.z; ts[rr][cc * 4 + 3] = v.w;
    }
    __syncthreads();
    #pragma unroll
    for (int i = 0; i < 8; ++i) {
        int idx = tid + i * 256;
        int e = idx >> 5, w = idx & 31;
        float v0 = ts[2 * w][e], v1 = ts[2 * w + 1][e];
        float h0, l0, h1, l1;
        bsplit(v0, h0, l0); bsplit(v1, h1, l1);
        size_t off = ((size_t)(z * H_ + h) * DH_ + e) * D_ + d0 + 2 * w;
        *(uint32_t*)(g_wt_h + off) = packbf(h0, h1);
        *(uint32_t*)(g_wt_l + off) = packbf(l0, l1);
    }
}

__global__ __launch_bounds__(256) void conv_wo_kernel(const float* __restrict__ Wo)
{
    __shared__ float ts[64][65];
    const int tid = threadIdx.x;
    const int d0 = blockIdx.x * 64;
    const int f0 = blockIdx.y * 64;

    #pragma unroll
    for (int i = 0; i < 4; ++i) {
        int idx = tid + i * 256;
        int rr = idx >> 4, cc = idx & 15;
        float4 v = *(const float4*)(Wo + (size_t)(d0 + rr) * D_ + f0 + cc * 4);
        ts[rr][cc * 4 + 0] = v.x; ts[rr][cc * 4 + 1] = v.y;
        ts[rr][cc * 4 + 2] = v.z; ts[rr][cc * 4 + 3] = v.w;
    }
    __syncthreads();
    #pragma unroll
    for (int i = 0; i < 8; ++i) {
        int idx = tid + i * 256;
        int e = idx >> 5, w = idx & 31;
        float v0 = ts[2 * w][e], v1 = ts[2 * w + 1][e];
        float h0, l0, h1, l1;
        bsplit(v0, h0, l0); bsplit(v1, h1, l1);
        size_t off = (size_t)(f0 + e) * D_ + d0 + 2 * w;
        *(uint32_t*)(g_wo_h + off) = packbf(h0, h1);
        *(uint32_t*)(g_wo_l + off) = packbf(l0, l1);
    }
}

// ============================================================
// GEMM machinery: 128x128 tile, BK=32, 8 warps (64x32 warp tile),
// double-buffered cp.async, 2 CTAs/SM, persistent work-stealing.
// mma_phase NOW fine-grain interleaves LDSM with MMA.
// ============================================================
#define GEMM_STAGE 40960
#define GEMM_SMEM (2 * GEMM_STAGE)
#define NKT (D_ / 32)

__device__ __forceinline__ void gemm_load_stage(uint32_t sbase,
    const __nv_bfloat16* p0, const __nv_bfloat16* p1,
    const __nv_bfloat16* p2, const __nv_bfloat16* p3, int tid)
{
    const __nv_bfloat16* p[4] = {p0, p1, p2, p3};
    #pragma unroll
    for (int i = 0; i < 8; ++i) {
        int idx = tid + i * 256;
        int arr = idx >> 9;
        int c = idx & 511;
        int r = c >> 2, col = c & 3;
        const __nv_bfloat16* src = p[arr] + (size_t)r * D_ + col * 8;
        uint32_t sa = sbase + arr * 10240 + r * 80 + col * 16;
        CP_A16(sa, src);
    }
}

__device__ __forceinline__ void mma_phase(uint32_t sbase, float acc[4][4][4], int wid, int lane)
{
    const int warp_m = wid & 1;
    const int warp_n = wid >> 1;
    const uint32_t a_hi_b = sbase;
    const uint32_t a_lo_b = sbase + 10240;
    const uint32_t b_hi_b = sbase + 20480;
    const uint32_t b_lo_b = sbase + 30720;

    const int a_row = warp_m * 64 + (lane & 15);
    const int a_kh  = (lane >> 4) << 3;
    const int b_row = warp_n * 32 + (lane & 7) + ((lane >> 4) << 3);
    const int b_kh  = ((lane >> 3) & 1) << 3;

    #pragma unroll
    for (int ks = 0; ks < 2; ++ks) {
        const int koff = ks * 16;
        uint32_t bh[2][4], bl[2][4];
        #pragma unroll
        for (int jj = 0; jj < 2; ++jj) {
            LDSM_X4(bh[jj][0], bh[jj][1], bh[jj][2], bh[jj][3],
                    b_hi_b + ((b_row + jj * 16) * 40 + koff + b_kh) * 2);
            LDSM_X4(bl[jj][0], bl[jj][1], bl[jj][2], bl[jj][3],
                    b_lo_b + ((b_row + jj * 16) * 40 + koff + b_kh) * 2);
        }
        // per A-row-group: load A-hi, 8 MMAs, load A-lo (same regs), 4 MMAs.
        #pragma unroll
        for (int i = 0; i < 4; ++i) {
            uint32_t a0, a1, a2, a3;
            LDSM_X4(a0, a1, a2, a3,
                    a_hi_b + ((a_row + i * 16) * 40 + koff + a_kh) * 2);
            #pragma unroll
            for (int j = 0; j < 4; ++j) {
                int jj = j >> 1, s = (j & 1) * 2;
                mma16816(acc[i][j], a0, a1, a2, a3, bh[jj][s], bh[jj][s + 1]);
                mma16816(acc[i][j], a0, a1, a2, a3, bl[jj][s], bl[jj][s + 1]);
            }
            LDSM_X4(a0, a1, a2, a3,
                    a_lo_b + ((a_row + i * 16) * 40 + koff + a_kh) * 2);
            #pragma unroll
            for (int j = 0; j < 4; ++j) {
                int jj = j >> 1, s = (j & 1) * 2;
                mma16816(acc[i][j], a0, a1, a2, a3, bh[jj][s], bh[jj][s + 1]);
            }
        }
    }
}

#define GEMM_MAINLOOP(AH, AL, BH, BL)                                          \
    gemm_load_stage(smb, (AH), (AL), (BH), (BL), tid);                         \
    CP_COMMIT();                                                               \
    for (int kt = 0; kt < NKT; ++kt) {                                         \
        if (kt + 1 < NKT) {                                                    \
            int k1 = (kt + 1) * 32;                                            \
            gemm_load_stage(smb + ((kt + 1) & 1) * GEMM_STAGE,                 \
                            (AH) + k1, (AL) + k1, (BH) + k1, (BL) + k1, tid);  \
            CP_COMMIT();                                                       \
            CP_WAIT(1);                                                        \
        } else {                                                               \
            CP_WAIT(0);                                                        \
        }                                                                      \
        __syncthreads();                                                       \
        mma_phase(smb + (kt & 1) * GEMM_STAGE, acc, wid, lane);                \
        __syncthreads();                                                       \
    }

// ============================================================
// Kernel 1: QKV projection, persistent. tiles = 64*8*3 = 1536.
// ============================================================
#define QKV_TILES 1536

__global__ __launch_bounds__(256, 2) void qkv_mma_kernel()
{
    extern __shared__ char sm[];
    __shared__ int s_idx;
    const uint32_t smb = smem_u32(sm);
    const int tid = threadIdx.x;
    const int wid = tid >> 5;
    const int lane = tid & 31;

    for (;;) {
        if (tid == 0) s_idx = (int)atomicAdd(&g_ctrs[0], 1u);
        __syncthreads();
        const int idx = s_idx;
        if (idx >= QKV_TILES) return;

        const int m0 = (idx & 63) * 128;
        const int hp = (idx >> 6) & 7;
        const int z  = idx >> 9;

        __nv_bfloat16* outh = (z == 0) ? g_qh : ((z == 1) ? g_kh : g_vh);
        __nv_bfloat16* outl = (z == 0) ? g_ql : ((z == 1) ? g_kl : g_vl);
        const float scale = (z == 0) ? 0.125f : 1.0f;

        const __nv_bfloat16* ah = g_xh + (size_t)m0 * D_;
        const __nv_bfloat16* al = g_xl + (size_t)m0 * D_;
        const __nv_bfloat16* bh = g_wt_h + (size_t)(z * H_ + hp * 2) * DH_ * D_;
        const __nv_bfloat16* bl = g_wt_l + (size_t)(z * H_ + hp * 2) * DH_ * D_;

        float acc[4][4][4];
        #pragma unroll
        for (int i = 0; i < 4; ++i)
            #pragma unroll
            for (int j = 0; j < 4; ++j)
                #pragma unroll
                for (int q = 0; q < 4; ++q) acc[i][j][q] = 0.f;

        GEMM_MAINLOOP(ah, al, bh, bl)

        const int warp_m = wid & 1;
        const int warp_n = wid >> 1;
        #pragma unroll
        for (int i = 0; i < 4; ++i) {
            #pragma unroll
            for (int j = 0; j < 4; ++j) {
                int r0 = m0 + warp_m * 64 + i * 16 + (lane >> 2);
                int col = warp_n * 32 + j * 8 + (lane & 3) * 2;
                int hh = hp * 2 + (col >> 6);
                int ee = col & 63;
                #pragma unroll
                for (int half = 0; half < 2; ++half) {
                    int r = r0 + half * 8;
                    int b = r >> 11, s = r & 2047;
                    float v0 = acc[i][j][2 * half] * scale;
                    float v1 = acc[i][j][2 * half + 1] * scale;
                    float h0, l0, h1, l1;
                    bsplit(v0, h0, l0); bsplit(v1, h1, l1);
                    size_t off = ((size_t)(b * H_ + hh) * S_ + s) * DH_ + ee;
                    *(uint32_t*)(outh + off) = packbf(h0, h1);
                    *(uint32_t*)(outl + off) = packbf(l0, l1);
                }
            }
        }
        __syncthreads();
    }
}

// ============================================================
// Kernel 3: output projection, persistent. tiles = 64*8 = 512.
// ============================================================
#define OUT_TILES 512

__global__ __launch_bounds__(256, 2) void out_proj_mma_kernel(
    const float* __restrict__ bo, float* __restrict__ out)
{
    extern __shared__ char sm[];
    __shared__ int s_idx;
    const uint32_t smb = smem_u32(sm);
    const int tid = threadIdx.x;
    const int wid = tid >> 5;
    const int lane = tid & 31;

    for (;;) {
        if (tid == 0) s_idx = (int)atomicAdd(&g_ctrs[2], 1u);
        __syncthreads();
        const int idx = s_idx;
        if (idx >= OUT_TILES) return;

        const int m0 = (idx & 63) * 128;
        const int n0 = (idx >> 6) * 128;

        const __nv_bfloat16* ah = g_ch + (size_t)m0 * D_;
        const __nv_bfloat16* al = g_cl + (size_t)m0 * D_;
        const __nv_bfloat16* bh = g_wo_h + (size_t)n0 * D_;
        const __nv_bfloat16* bl = g_wo_l + (size_t)n0 * D_;

        float acc[4][4][4];
        #pragma unroll
        for (int i = 0; i < 4; ++i)
            #pragma unroll
            for (int j = 0; j < 4; ++j)
                #pragma unroll
                for (int q = 0; q < 4; ++q) acc[i][j][q] = 0.f;

        GEMM_MAINLOOP(ah, al, bh, bl)

        const int warp_m = wid & 1;
        const int warp_n = wid >> 1;
        #pragma unroll
        for (int i = 0; i < 4; ++i) {
            #pragma unroll
            for (int j = 0; j < 4; ++j) {
                int r0 = m0 + warp_m * 64 + i * 16 + (lane >> 2);
                int col = n0 + warp_n * 32 + j * 8 + (lane & 3) * 2;
                float b0 = bo[col], b1 = bo[col + 1];
                {
                    float2 v; v.x = acc[i][j][0] + b0; v.y = acc[i][j][1] + b1;
                    *(float2*)(out + (size_t)r0 * D_ + col) = v;
                }
                {
                    float2 v; v.x = acc[i][j][2] + b0; v.y = acc[i][j][3] + b1;
                    *(float2*)(out + (size_t)(r0 + 8) * D_ + col) = v;
                }
            }
        }
        __syncthreads();
    }
}

// ============================================================
// Kernel 2: causal flash attention, persistent + LPT (unchanged R11).
// ============================================================
#define KV_STAGE 36864
#define ATTN_SMEM (36864 + 2 * KV_STAGE)
#define ATTN_TILES 1024

__device__ __forceinline__ void attn_load_kv(uint32_t kvb,
    const __nv_bfloat16* kh, const __nv_bfloat16* kl,
    const __nv_bfloat16* vh, const __nv_bfloat16* vl, int tid)
{
    const __nv_bfloat16* p[4] = {kh, kl, vh, vl};
    #pragma unroll
    for (int i = 0; i < 8; ++i) {
        int idx = tid + i * 256;
        int arr = idx >> 9;
        int c = idx & 511;
        int r = c >> 3, c8 = c & 7;
        const __nv_bfloat16* src = p[arr] + (size_t)r * DH_ + c8 * 8;
        uint32_t sa = kvb + arr * 9216 + r * 144 + c8 * 16;
        CP_A16(sa, src);
    }
}

__global__ __launch_bounds__(256, 2) void attn_mma_kernel()
{
    extern __shared__ char sm[];
    __shared__ int s_idx;
    const uint32_t smb = smem_u32(sm);
    const int tid = threadIdx.x;
    const int wm = tid >> 5;
    const int lane = tid & 31;

    const uint32_t Qh_b = smb;
    const uint32_t Ql_b = smb + 18432;

    for (;;) {
        if (tid == 0) s_idx = (int)atomicAdd(&g_ctrs[1], 1u);
        __syncthreads();
        const int idx = s_idx;
        if (idx >= ATTN_TILES) return;

        const int qb = 15 - (idx >> 6);
        const int bh = idx & 63;
        const int kmax = 2 * qb + 2;

        const __nv_bfloat16* kh_g = g_kh + (size_t)bh * S_ * DH_;
        const __nv_bfloat16* kl_g = g_kl + (size_t)bh * S_ * DH_;
        const __nv_bfloat16* vh_g = g_vh + (size_t)bh * S_ * DH_;
        const __nv_bfloat16* vl_g = g_vl + (size_t)bh * S_ * DH_;

        attn_load_kv(smb + 36864, kh_g, kl_g, vh_g, vl_g, tid);
        CP_COMMIT();

        {
            const __nv_bfloat16* qh_g = g_qh + ((size_t)bh * S_ + qb * 128) * DH_;
            const __nv_bfloat16* ql_g = g_ql + ((size_t)bh * S_ + qb * 128) * DH_;
            #pragma unroll
            for (int i = 0; i < 4; ++i) {
                int ii = tid + i * 256;
                int r = ii >> 3, c8 = ii & 7;
                *(uint4*)(sm + (Qh_b - smb) + r * 144 + c8 * 16) =
                    *(const uint4*)(qh_g + (size_t)r * DH_ + c8 * 8);
                *(uint4*)(sm + (Ql_b - smb) + r * 144 + c8 * 16) =
                    *(const uint4*)(ql_g + (size_t)r * DH_ + c8 * 8);
            }
        }
        __syncthreads();

        uint32_t qh[4][4], ql[4][4];
        {
            const int ar = wm * 16 + (lane & 15);
            const int koff = (lane >> 4) << 3;
            #pragma unroll
            for (int ks = 0; ks < 4; ++ks) {
                LDSM_X4(qh[ks][0], qh[ks][1], qh[ks][2], qh[ks][3],
                        Qh_b + ar * 144 + (ks * 16 + koff) * 2);
                LDSM_X4(ql[ks][0], ql[ks][1], ql[ks][2], ql[ks][3],
                        Ql_b + ar * 144 + (ks * 16 + koff) * 2);
            }
        }

        float mA = -3.0e38f, mB = -3.0e38f, lA = 0.f, lB = 0.f;
        float oacc[8][4];
        #pragma unroll
        for (int t = 0; t < 8; ++t)
            #pragma unroll
            for (int q = 0; q < 4; ++q) oacc[t][q] = 0.f;

        const int kb_row  = (lane & 7) + ((lane >> 4) << 3);
        const int kb_koff = ((lane >> 3) & 1) << 3;
        const int vb_row  = (lane & 7) + (((lane >> 3) & 1) << 3);
        const int vb_eoff = (lane >> 4) << 3;

        const int rA_g = qb * 128 + wm * 16 + (lane >> 2);

        for (int kt = 0; kt < kmax; ++kt) {
            if (kt + 1 < kmax) {
                size_t koff = (size_t)(kt + 1) * 64 * DH_;
                attn_load_kv(smb + 36864 + ((kt + 1) & 1) * KV_STAGE,
                             kh_g + koff, kl_g + koff, vh_g + koff, vl_g + koff, tid);
                CP_COMMIT();
                CP_WAIT(1);
            } else {
                CP_WAIT(0);
            }
            __syncthreads();

            const uint32_t kvb = smb + 36864 + (kt & 1) * KV_STAGE;
            const uint32_t Kh_b = kvb, Kl_b = kvb + 9216, Vh_b = kvb + 18432, Vl_b = kvb + 27648;

            float sacc[8][4];
            #pragma unroll
            for (int t = 0; t < 8; ++t)
                #pragma unroll
                for (int q = 0; q < 4; ++q) sacc[t][q] = 0.f;

            #pragma unroll
            for (int ks = 0; ks < 4; ++ks) {
                #pragma unroll
                for (int np = 0; np < 4; ++np) {
                    uint32_t row = np * 16 + kb_row;
                    uint32_t ko  = ks * 16 + kb_koff;
                    uint32_t b0, b1, b2, b3, c0, c1, c2, c3;
                    LDSM_X4(b0, b1, b2, b3, Kh_b + row * 144 + ko * 2);
                    LDSM_X4(c0, c1, c2, c3, Kl_b + row * 144 + ko * 2);
                    mma16816(sacc[2 * np],     qh[ks][0], qh[ks][1], qh[ks][2], qh[ks][3], b0, b1);
                    mma16816(sacc[2 * np],     qh[ks][0], qh[ks][1], qh[ks][2], qh[ks][3], c0, c1);
                    mma16816(sacc[2 * np],     ql[ks][0], ql[ks][1], ql[ks][2], ql[ks][3], b0, b1);
                    mma16816(sacc[2 * np + 1], qh[ks][0], qh[ks][1], qh[ks][2], qh[ks][3], b2, b3);
                    mma16816(sacc[2 * np + 1], qh[ks][0], qh[ks][1], qh[ks][2], qh[ks][3], c2, c3);
                    mma16816(sacc[2 * np + 1], ql[ks][0], ql[ks][1], ql[ks][2], ql[ks][3], b2, b3);
                }
            }

            if (kt >= 2 * qb) {
                const int c0g = kt * 64 + 2 * (lane & 3);
                #pragma unroll
                for (int t = 0; t < 8; ++t) {
                    int c = c0g + 8 * t;
                    if (c     > rA_g)     sacc[t][0] = -3.0e38f;
                    if (c + 1 > rA_g)     sacc[t][1] = -3.0e38f;
                    if (c     > rA_g + 8) sacc[t][2] = -3.0e38f;
                    if (c + 1 > rA_g + 8) sacc[t][3] = -3.0e38f;
                }
            }

            float mtA = -3.0e38f, mtB = -3.0e38f;
            #pragma unroll
            for (int t = 0; t < 8; ++t) {
                mtA = fmaxf(mtA, fmaxf(sacc[t][0], sacc[t][1]));
                mtB = fmaxf(mtB, fmaxf(sacc[t][2], sacc[t][3]));
            }
            mtA = fmaxf(mtA, __shfl_xor_sync(0xffffffffu, mtA, 1));
            mtA = fmaxf(mtA, __shfl_xor_sync(0xffffffffu, mtA, 2));
            mtB = fmaxf(mtB, __shfl_xor_sync(0xffffffffu, mtB, 1));
            mtB = fmaxf(mtB, __shfl_xor_sync(0xffffffffu, mtB, 2));

            float mnA = fmaxf(mA, mtA), mnB = fmaxf(mB, mtB);
            float corrA = __expf(mA - mnA), corrB = __expf(mB - mnB);

            float rsA = 0.f, rsB = 0.f;
            #pragma unroll
            for (int t = 0; t < 8; ++t) {
                float p0 = __expf(sacc[t][0] - mnA); sacc[t][0] = p0; rsA += p0;
                float p1 = __expf(sacc[t][1] - mnA); sacc[t][1] = p1; rsA += p1;
                float p2 = __expf(sacc[t][2] - mnB); sacc[t][2] = p2; rsB += p2;
                float p3 = __expf(sacc[t][3] - mnB); sacc[t][3] = p3; rsB += p3;
            }
            rsA += __shfl_xor_sync(0xffffffffu, rsA, 1);
            rsA += __shfl_xor_sync(0xffffffffu, rsA, 2);
            rsB += __shfl_xor_sync(0xffffffffu, rsB, 1);
            rsB += __shfl_xor_sync(0xffffffffu, rsB, 2);

            lA = lA * corrA + rsA;
            lB = lB * corrB + rsB;
            #pragma unroll
            for (int t = 0; t < 8; ++t) {
                oacc[t][0] *= corrA; oacc[t][1] *= corrA;
                oacc[t][2] *= corrB; oacc[t][3] *= corrB;
            }
            mA = mnA; mB = mnB;

            #pragma unroll
            for (int ks = 0; ks < 4; ++ks) {
                uint32_t pfh[4], pfl[4];
                {
                    float h00, l00, h01, l01, h10, l10, h11, l11;
                    bsplit(sacc[2 * ks][0], h00, l00); bsplit(sacc[2 * ks][1], h01, l01);
                    bsplit(sacc[2 * ks][2], h10, l10); bsplit(sacc[2 * ks][3], h11, l11);
                    pfh[0] = packbf(h00, h01); pfl[0] = packbf(l00, l01);
                    pfh[1] = packbf(h10, h11); pfl[1] = packbf(l10, l11);
                    bsplit(sacc[2 * ks + 1][0], h00, l00); bsplit(sacc[2 * ks + 1][1], h01, l01);
                    bsplit(sacc[2 * ks + 1][2], h10, l10); bsplit(sacc[2 * ks + 1][3], h11, l11);
                    pfh[2] = packbf(h00, h01); pfl[2] = packbf(l00, l01);
                    pfh[3] = packbf(h10, h11); pfl[3] = packbf(l10, l11);
                }
                #pragma unroll
                for (int ep = 0; ep < 4; ++ep) {
                    uint32_t row = ks * 16 + vb_row;
                    uint32_t eo  = ep * 16 + vb_eoff;
                    uint32_t v0, v1, v2, v3, w0, w1, w2, w3;
                    LDSM_X4_T(v0, v1, v2, v3, Vh_b + row * 144 + eo * 2);
                    LDSM_X4_T(w0, w1, w2, w3, Vl_b + row * 144 + eo * 2);
                    mma16816(oacc[2 * ep],     pfh[0], pfh[1], pfh[2], pfh[3], v0, v1);
                    mma16816(oacc[2 * ep],     pfh[0], pfh[1], pfh[2], pfh[3], w0, w1);
                    mma16816(oacc[2 * ep],     pfl[0], pfl[1], pfl[2], pfl[3], v0, v1);
                    mma16816(oacc[2 * ep + 1], pfh[0], pfh[1], pfh[2], pfh[3], v2, v3);
                    mma16816(oacc[2 * ep + 1], pfh[0], pfh[1], pfh[2], pfh[3], w2, w3);
                    mma16816(oacc[2 * ep + 1], pfl[0], pfl[1], pfl[2], pfl[3], v2, v3);
                }
            }
            __syncthreads();
        }

        const float invA = 1.0f / lA;
        const float invB = 1.0f / lB;
        const int b = bh >> 4, h = bh & 15;
        const int e0 = 2 * (lane & 3);
        size_t baseA = ((size_t)b * S_ + rA_g) * D_ + h * DH_;
        size_t baseB = ((size_t)b * S_ + rA_g + 8) * D_ + h * DH_;
        #pragma unroll
        for (int t = 0; t < 8; ++t) {
            int e = 8 * t + e0;
            float a0 = oacc[t][0] * invA, a1 = oacc[t][1] * invA;
            float b0v = oacc[t][2] * invB, b1v = oacc[t][3] * invB;
            float h0, l0, h1, l1;
            bsplit(a0, h0, l0); bsplit(a1, h1, l1);
            *(uint32_t*)(g_ch + baseA + e) = packbf(h0, h1);
            *(uint32_t*)(g_cl + baseA + e) = packbf(l0, l1);
            bsplit(b0v, h0, l0); bsplit(b1v, h1, l1);
            *(uint32_t*)(g_ch + baseB + e) = packbf(h0, h1);
            *(uint32_t*)(g_cl + baseB + e) = packbf(l0, l1);
        }
        __syncthreads();
    }
}

// ============================================================
extern "C" void kernel_launch(void* const* d_in, const int* in_sizes, int n_in,
                              void* d_out, int out_size)
{
    const float* x  = (const float*)d_in[0];
    const float* Wq = (const float*)d_in[1];
    const float* Wk = (const float*)d_in[2];
    const float* Wv = (const float*)d_in[3];
    const float* Wo = (const float*)d_in[4];
    const float* bo = (const float*)d_in[5];
    float* out = (float*)d_out;

    cudaFuncSetAttribute(qkv_mma_kernel, cudaFuncAttributeMaxDynamicSharedMemorySize, GEMM_SMEM);
    cudaFuncSetAttribute(out_proj_mma_kernel, cudaFuncAttributeMaxDynamicSharedMemorySize, GEMM_SMEM);
    cudaFuncSetAttribute(attn_mma_kernel, cudaFuncAttributeMaxDynamicSharedMemorySize, ATTN_SMEM);

    conv_x_kernel<<<C_ELEMS / 4 / 256, 256>>>(x);
    conv_w_kernel<<<dim3(D_ / 64, H_, 3), 256>>>(Wq, Wk, Wv);
    conv_wo_kernel<<<dim3(D_ / 64, D_ / 64), 256>>>(Wo);
    qkv_mma_kernel<<<PERSIST_CTAS, 256, GEMM_SMEM>>>();
    attn_mma_kernel<<<PERSIST_CTAS, 256, ATTN_SMEM>>>();
    out_proj_mma_kernel<<<PERSIST_CTAS, 256, GEMM_SMEM>>>(bo, out);
}

// round 13
// speedup vs baseline: 1.2201x; 1.0121x over previous
#include <cuda_runtime.h>
#include <cuda_bf16.h>
#include <cstdint>

#define B_ 4
#define S_ 2048
#define D_ 1024
#define H_ 16
#define DH_ 64
#define MROWS (B_ * S_)
#define QKV_ELEMS (B_ * H_ * S_ * DH_)   // 8388608
#define C_ELEMS   (B_ * S_ * D_)         // 8388608

// -------- bf16 hi/lo scratch (no allocation) --------
__device__ __nv_bfloat16 g_xh[C_ELEMS],  g_xl[C_ELEMS];
__device__ __nv_bfloat16 g_wt_h[3 * H_ * DH_ * D_], g_wt_l[3 * H_ * DH_ * D_];
__device__ __nv_bfloat16 g_wo_h[D_ * D_], g_wo_l[D_ * D_];
__device__ __nv_bfloat16 g_qh[QKV_ELEMS], g_ql[QKV_ELEMS];
__device__ __nv_bfloat16 g_kh[QKV_ELEMS], g_kl[QKV_ELEMS];
__device__ __nv_bfloat16 g_vh[QKV_ELEMS], g_vl[QKV_ELEMS];
__device__ __nv_bfloat16 g_ch[C_ELEMS],  g_cl[C_ELEMS];

// work-steal counters: [0]=qkv, [1]=attn, [2]=out_proj
__device__ unsigned int g_ctrs[3];

#define PERSIST_CTAS 304

// ================= helpers =================
__device__ __forceinline__ uint32_t smem_u32(const void* p) {
    uint32_t a;
    asm("{ .reg .u64 t; cvta.to.shared.u64 t, %1; cvt.u32.u64 %0, t; }" : "=r"(a) : "l"(p));
    return a;
}
__device__ __forceinline__ void bsplit(float v, float& h, float& l) {
    __nv_bfloat16 bh = __float2bfloat16(v);
    h = __bfloat162float(bh);
    l = v - h;
}
__device__ __forceinline__ uint32_t packbf(float lo_elem, float hi_elem) {
    uint32_t r;
    asm("cvt.rn.bf16x2.f32 %0, %1, %2;" : "=r"(r) : "f"(hi_elem), "f"(lo_elem));
    return r;
}
#define LDSM_X4(r0, r1, r2, r3, addr) \
    asm volatile("ldmatrix.sync.aligned.m8n8.x4.shared.b16 {%0,%1,%2,%3}, [%4];" \
        : "=r"(r0), "=r"(r1), "=r"(r2), "=r"(r3) : "r"(addr))
#define LDSM_X4_T(r0, r1, r2, r3, addr) \
    asm volatile("ldmatrix.sync.aligned.m8n8.x4.trans.shared.b16 {%0,%1,%2,%3}, [%4];" \
        : "=r"(r0), "=r"(r1), "=r"(r2), "=r"(r3) : "r"(addr))
#define CP_A16(sa, gp) asm volatile("cp.async.ca.shared.global [%0], [%1], 16;" :: "r"(sa), "l"(gp))
#define CP_COMMIT()    asm volatile("cp.async.commit_group;" ::: "memory")
#define CP_WAIT(n)     asm volatile("cp.async.wait_group %0;" :: "n"(n) : "memory")

__device__ __forceinline__ void mma16816(float* c,
    uint32_t a0, uint32_t a1, uint32_t a2, uint32_t a3, uint32_t b0, uint32_t b1)
{
    asm volatile(
        "mma.sync.aligned.m16n8k16.row.col.f32.bf16.bf16.f32 "
        "{%0,%1,%2,%3}, {%4,%5,%6,%7}, {%8,%9}, {%0,%1,%2,%3};"
        : "+f"(c[0]), "+f"(c[1]), "+f"(c[2]), "+f"(c[3])
        : "r"(a0), "r"(a1), "r"(a2), "r"(a3), "r"(b0), "r"(b1));
}

// ============================================================
// Fused preconversion kernel (x + W + Wo, one launch).
// Blocks [0,8192): conv_x; [8192,8960): conv_w; [8960,9216): conv_wo.
// ============================================================
__global__ __launch_bounds__(256) void conv_all_kernel(
    const float* __restrict__ x,
    const float* __restrict__ Wq, const float* __restrict__ Wk,
    const float* __restrict__ Wv, const float* __restrict__ Wo)
{
    __shared__ float ts[64][65];
    const int blk = blockIdx.x;
    const int tid = threadIdx.x;

    if (blk < 8192) {
        if (blk == 0 && tid < 3) g_ctrs[tid] = 0u;
        int i = blk * 256 + tid;
        float4 v = *(const float4*)(x + 4 * (size_t)i);
        float hx, lx, hy, ly, hz, lz, hw, lw;
        bsplit(v.x, hx, lx); bsplit(v.y, hy, ly);
        bsplit(v.z, hz, lz); bsplit(v.w, hw, lw);
        uint2 wh, wl;
        wh.x = packbf(hx, hy); wh.y = packbf(hz, hw);
        wl.x = packbf(lx, ly); wl.y = packbf(lz, lw);
        *(uint2*)(g_xh + 4 * (size_t)i) = wh;
        *(uint2*)(g_xl + 4 * (size_t)i) = wl;
        return;
    }

    if (blk < 8960) {
        const int q = blk - 8192;
        const int d0 = (q & 15) * 64;
        const int h  = (q >> 4) & 15;
        const int z  = q >> 8;
        const float* W = (z == 0) ? Wq : ((z == 1) ? Wk : Wv);
        const float* src = W + (size_t)h * D_ * DH_;

        #pragma unroll
        for (int i = 0; i < 4; ++i) {
            int idx = tid + i * 256;
            int rr = idx >> 4, cc = idx & 15;
            float4 v = *(const float4*)(src + (size_t)(d0 + rr) * DH_ + cc * 4);
            ts[rr][cc * 4 + 0] = v.x; ts[rr][cc * 4 + 1] = v.y;
            ts[rr][cc * 4 + 2] = v.z; ts[rr][cc * 4 + 3] = v.w;
        }
        __syncthreads();
        #pragma unroll
        for (int i = 0; i < 8; ++i) {
            int idx = tid + i * 256;
            int e = idx >> 5, w = idx & 31;
            float v0 = ts[2 * w][e], v1 = ts[2 * w + 1][e];
            float h0, l0, h1, l1;
            bsplit(v0, h0, l0); bsplit(v1, h1, l1);
            size_t off = ((size_t)(z * H_ + h) * DH_ + e) * D_ + d0 + 2 * w;
            *(uint32_t*)(g_wt_h + off) = packbf(h0, h1);
            *(uint32_t*)(g_wt_l + off) = packbf(l0, l1);
        }
        return;
    }

    {
        const int q = blk - 8960;
        const int d0 = (q & 15) * 64;
        const int f0 = (q >> 4) * 64;

        #pragma unroll
        for (int i = 0; i < 4; ++i) {
            int idx = tid + i * 256;
            int rr = idx >> 4, cc = idx & 15;
            float4 v = *(const float4*)(Wo + (size_t)(d0 + rr) * D_ + f0 + cc * 4);
            ts[rr][cc * 4 + 0] = v.x; ts[rr][cc * 4 + 1] = v.y;
            ts[rr][cc * 4 + 2] = v.z; ts[rr][cc * 4 + 3] = v.w;
        }
        __syncthreads();
        #pragma unroll
        for (int i = 0; i < 8; ++i) {
            int idx = tid + i * 256;
            int e = idx >> 5, w = idx & 31;
            float v0 = ts[2 * w][e], v1 = ts[2 * w + 1][e];
            float h0, l0, h1, l1;
            bsplit(v0, h0, l0); bsplit(v1, h1, l1);
            size_t off = (size_t)(f0 + e) * D_ + d0 + 2 * w;
            *(uint32_t*)(g_wo_h + off) = packbf(h0, h1);
            *(uint32_t*)(g_wo_l + off) = packbf(l0, l1);
        }
    }
}

// ============================================================
// GEMM machinery: 128x128 tile, BK=32, 8 warps (64x32 warp tile),
// 2-stage cp.async, 2 CTAs/SM, persistent, interleaved mma_phase,
// ONE barrier per ktile (wait -> barrier -> prefetch -> mma).
// ============================================================
#define GEMM_STAGE 40960
#define GEMM_SMEM (2 * GEMM_STAGE)
#define NKT (D_ / 32)

__device__ __forceinline__ void gemm_load_stage(uint32_t sbase,
    const __nv_bfloat16* p0, const __nv_bfloat16* p1,
    const __nv_bfloat16* p2, const __nv_bfloat16* p3, int tid)
{
    const __nv_bfloat16* p[4] = {p0, p1, p2, p3};
    #pragma unroll
    for (int i = 0; i < 8; ++i) {
        int idx = tid + i * 256;
        int arr = idx >> 9;
        int c = idx & 511;
        int r = c >> 2, col = c & 3;
        const __nv_bfloat16* src = p[arr] + (size_t)r * D_ + col * 8;
        uint32_t sa = sbase + arr * 10240 + r * 80 + col * 16;
        CP_A16(sa, src);
    }
}

__device__ __forceinline__ void mma_phase(uint32_t sbase, float acc[4][4][4], int wid, int lane)
{
    const int warp_m = wid & 1;
    const int warp_n = wid >> 1;
    const uint32_t a_hi_b = sbase;
    const uint32_t a_lo_b = sbase + 10240;
    const uint32_t b_hi_b = sbase + 20480;
    const uint32_t b_lo_b = sbase + 30720;

    const int a_row = warp_m * 64 + (lane & 15);
    const int a_kh  = (lane >> 4) << 3;
    const int b_row = warp_n * 32 + (lane & 7) + ((lane >> 4) << 3);
    const int b_kh  = ((lane >> 3) & 1) << 3;

    #pragma unroll
    for (int ks = 0; ks < 2; ++ks) {
        const int koff = ks * 16;
        uint32_t bh[2][4], bl[2][4];
        #pragma unroll
        for (int jj = 0; jj < 2; ++jj) {
            LDSM_X4(bh[jj][0], bh[jj][1], bh[jj][2], bh[jj][3],
                    b_hi_b + ((b_row + jj * 16) * 40 + koff + b_kh) * 2);
            LDSM_X4(bl[jj][0], bl[jj][1], bl[jj][2], bl[jj][3],
                    b_lo_b + ((b_row + jj * 16) * 40 + koff + b_kh) * 2);
        }
        #pragma unroll
        for (int i = 0; i < 4; ++i) {
            uint32_t a0, a1, a2, a3;
            LDSM_X4(a0, a1, a2, a3,
                    a_hi_b + ((a_row + i * 16) * 40 + koff + a_kh) * 2);
            #pragma unroll
            for (int j = 0; j < 4; ++j) {
                int jj = j >> 1, s = (j & 1) * 2;
                mma16816(acc[i][j], a0, a1, a2, a3, bh[jj][s], bh[jj][s + 1]);
                mma16816(acc[i][j], a0, a1, a2, a3, bl[jj][s], bl[jj][s + 1]);
            }
            LDSM_X4(a0, a1, a2, a3,
                    a_lo_b + ((a_row + i * 16) * 40 + koff + a_kh) * 2);
            #pragma unroll
            for (int j = 0; j < 4; ++j) {
                int jj = j >> 1, s = (j & 1) * 2;
                mma16816(acc[i][j], a0, a1, a2, a3, bh[jj][s], bh[jj][s + 1]);
            }
        }
    }
}

// one barrier per ktile: wait(0) -> barrier -> prefetch(kt+1) -> mma(kt)
#define GEMM_MAINLOOP(AH, AL, BH, BL)                                          \
    gemm_load_stage(smb, (AH), (AL), (BH), (BL), tid);                         \
    CP_COMMIT();                                                               \
    for (int kt = 0; kt < NKT; ++kt) {                                         \
        CP_WAIT(0);                                                            \
        __syncthreads();                                                       \
        if (kt + 1 < NKT) {                                                    \
            int k1 = (kt + 1) * 32;                                            \
            gemm_load_stage(smb + ((kt + 1) & 1) * GEMM_STAGE,                 \
                            (AH) + k1, (AL) + k1, (BH) + k1, (BL) + k1, tid);  \
            CP_COMMIT();                                                       \
        }                                                                      \
        mma_phase(smb + (kt & 1) * GEMM_STAGE, acc, wid, lane);                \
    }

// ============================================================
// Kernel 1: QKV projection, persistent. tiles = 64*8*3 = 1536.
// ============================================================
#define QKV_TILES 1536

__global__ __launch_bounds__(256, 2) void qkv_mma_kernel()
{
    extern __shared__ char sm[];
    __shared__ int s_idx;
    const uint32_t smb = smem_u32(sm);
    const int tid = threadIdx.x;
    const int wid = tid >> 5;
    const int lane = tid & 31;

    for (;;) {
        if (tid == 0) s_idx = (int)atomicAdd(&g_ctrs[0], 1u);
        __syncthreads();
        const int idx = s_idx;
        if (idx >= QKV_TILES) return;

        const int m0 = (idx & 63) * 128;
        const int hp = (idx >> 6) & 7;
        const int z  = idx >> 9;

        __nv_bfloat16* outh = (z == 0) ? g_qh : ((z == 1) ? g_kh : g_vh);
        __nv_bfloat16* outl = (z == 0) ? g_ql : ((z == 1) ? g_kl : g_vl);
        const float scale = (z == 0) ? 0.125f : 1.0f;

        const __nv_bfloat16* ah = g_xh + (size_t)m0 * D_;
        const __nv_bfloat16* al = g_xl + (size_t)m0 * D_;
        const __nv_bfloat16* bh = g_wt_h + (size_t)(z * H_ + hp * 2) * DH_ * D_;
        const __nv_bfloat16* bl = g_wt_l + (size_t)(z * H_ + hp * 2) * DH_ * D_;

        float acc[4][4][4];
        #pragma unroll
        for (int i = 0; i < 4; ++i)
            #pragma unroll
            for (int j = 0; j < 4; ++j)
                #pragma unroll
                for (int q = 0; q < 4; ++q) acc[i][j][q] = 0.f;

        GEMM_MAINLOOP(ah, al, bh, bl)

        const int warp_m = wid & 1;
        const int warp_n = wid >> 1;
        #pragma unroll
        for (int i = 0; i < 4; ++i) {
            #pragma unroll
            for (int j = 0; j < 4; ++j) {
                int r0 = m0 + warp_m * 64 + i * 16 + (lane >> 2);
                int col = warp_n * 32 + j * 8 + (lane & 3) * 2;
                int hh = hp * 2 + (col >> 6);
                int ee = col & 63;
                #pragma unroll
                for (int half = 0; half < 2; ++half) {
                    int r = r0 + half * 8;
                    int b = r >> 11, s = r & 2047;
                    float v0 = acc[i][j][2 * half] * scale;
                    float v1 = acc[i][j][2 * half + 1] * scale;
                    float h0, l0, h1, l1;
                    bsplit(v0, h0, l0); bsplit(v1, h1, l1);
                    size_t off = ((size_t)(b * H_ + hh) * S_ + s) * DH_ + ee;
                    *(uint32_t*)(outh + off) = packbf(h0, h1);
                    *(uint32_t*)(outl + off) = packbf(l0, l1);
                }
            }
        }
        __syncthreads();   // all warps done reading smem/s_idx before next tile
    }
}

// ============================================================
// Kernel 3: output projection, persistent. tiles = 64*8 = 512.
// ============================================================
#define OUT_TILES 512

__global__ __launch_bounds__(256, 2) void out_proj_mma_kernel(
    const float* __restrict__ bo, float* __restrict__ out)
{
    extern __shared__ char sm[];
    __shared__ int s_idx;
    const uint32_t smb = smem_u32(sm);
    const int tid = threadIdx.x;
    const int wid = tid >> 5;
    const int lane = tid & 31;

    for (;;) {
        if (tid == 0) s_idx = (int)atomicAdd(&g_ctrs[2], 1u);
        __syncthreads();
        const int idx = s_idx;
        if (idx >= OUT_TILES) return;

        const int m0 = (idx & 63) * 128;
        const int n0 = (idx >> 6) * 128;

        const __nv_bfloat16* ah = g_ch + (size_t)m0 * D_;
        const __nv_bfloat16* al = g_cl + (size_t)m0 * D_;
        const __nv_bfloat16* bh = g_wo_h + (size_t)n0 * D_;
        const __nv_bfloat16* bl = g_wo_l + (size_t)n0 * D_;

        float acc[4][4][4];
        #pragma unroll
        for (int i = 0; i < 4; ++i)
            #pragma unroll
            for (int j = 0; j < 4; ++j)
                #pragma unroll
                for (int q = 0; q < 4; ++q) acc[i][j][q] = 0.f;

        GEMM_MAINLOOP(ah, al, bh, bl)

        const int warp_m = wid & 1;
        const int warp_n = wid >> 1;
        #pragma unroll
        for (int i = 0; i < 4; ++i) {
            #pragma unroll
            for (int j = 0; j < 4; ++j) {
                int r0 = m0 + warp_m * 64 + i * 16 + (lane >> 2);
                int col = n0 + warp_n * 32 + j * 8 + (lane & 3) * 2;
                float b0 = bo[col], b1 = bo[col + 1];
                {
                    float2 v; v.x = acc[i][j][0] + b0; v.y = acc[i][j][1] + b1;
                    *(float2*)(out + (size_t)r0 * D_ + col) = v;
                }
                {
                    float2 v; v.x = acc[i][j][2] + b0; v.y = acc[i][j][3] + b1;
                    *(float2*)(out + (size_t)(r0 + 8) * D_ + col) = v;
                }
            }
        }
        __syncthreads();
    }
}

// ============================================================
// Kernel 2: causal flash attention, persistent + LPT,
// now ONE barrier per kv-tile (wait -> barrier -> prefetch -> compute).
// ============================================================
#define KV_STAGE 36864
#define ATTN_SMEM (36864 + 2 * KV_STAGE)
#define ATTN_TILES 1024

__device__ __forceinline__ void attn_load_kv(uint32_t kvb,
    const __nv_bfloat16* kh, const __nv_bfloat16* kl,
    const __nv_bfloat16* vh, const __nv_bfloat16* vl, int tid)
{
    const __nv_bfloat16* p[4] = {kh, kl, vh, vl};
    #pragma unroll
    for (int i = 0; i < 8; ++i) {
        int idx = tid + i * 256;
        int arr = idx >> 9;
        int c = idx & 511;
        int r = c >> 3, c8 = c & 7;
        const __nv_bfloat16* src = p[arr] + (size_t)r * DH_ + c8 * 8;
        uint32_t sa = kvb + arr * 9216 + r * 144 + c8 * 16;
        CP_A16(sa, src);
    }
}

__global__ __launch_bounds__(256, 2) void attn_mma_kernel()
{
    extern __shared__ char sm[];
    __shared__ int s_idx;
    const uint32_t smb = smem_u32(sm);
    const int tid = threadIdx.x;
    const int wm = tid >> 5;
    const int lane = tid & 31;

    const uint32_t Qh_b = smb;
    const uint32_t Ql_b = smb + 18432;

    for (;;) {
        if (tid == 0) s_idx = (int)atomicAdd(&g_ctrs[1], 1u);
        __syncthreads();
        const int idx = s_idx;
        if (idx >= ATTN_TILES) return;

        const int qb = 15 - (idx >> 6);
        const int bh = idx & 63;
        const int kmax = 2 * qb + 2;

        const __nv_bfloat16* kh_g = g_kh + (size_t)bh * S_ * DH_;
        const __nv_bfloat16* kl_g = g_kl + (size_t)bh * S_ * DH_;
        const __nv_bfloat16* vh_g = g_vh + (size_t)bh * S_ * DH_;
        const __nv_bfloat16* vl_g = g_vl + (size_t)bh * S_ * DH_;

        attn_load_kv(smb + 36864, kh_g, kl_g, vh_g, vl_g, tid);
        CP_COMMIT();

        {
            const __nv_bfloat16* qh_g = g_qh + ((size_t)bh * S_ + qb * 128) * DH_;
            const __nv_bfloat16* ql_g = g_ql + ((size_t)bh * S_ + qb * 128) * DH_;
            #pragma unroll
            for (int i = 0; i < 4; ++i) {
                int ii = tid + i * 256;
                int r = ii >> 3, c8 = ii & 7;
                *(uint4*)(sm + (Qh_b - smb) + r * 144 + c8 * 16) =
                    *(const uint4*)(qh_g + (size_t)r * DH_ + c8 * 8);
                *(uint4*)(sm + (Ql_b - smb) + r * 144 + c8 * 16) =
                    *(const uint4*)(ql_g + (size_t)r * DH_ + c8 * 8);
            }
        }
        __syncthreads();

        uint32_t qh[4][4], ql[4][4];
        {
            const int ar = wm * 16 + (lane & 15);
            const int koff = (lane >> 4) << 3;
            #pragma unroll
            for (int ks = 0; ks < 4; ++ks) {
                LDSM_X4(qh[ks][0], qh[ks][1], qh[ks][2], qh[ks][3],
                        Qh_b + ar * 144 + (ks * 16 + koff) * 2);
                LDSM_X4(ql[ks][0], ql[ks][1], ql[ks][2], ql[ks][3],
                        Ql_b + ar * 144 + (ks * 16 + koff) * 2);
            }
        }

        float mA = -3.0e38f, mB = -3.0e38f, lA = 0.f, lB = 0.f;
        float oacc[8][4];
        #pragma unroll
        for (int t = 0; t < 8; ++t)
            #pragma unroll
            for (int q = 0; q < 4; ++q) oacc[t][q] = 0.f;

        const int kb_row  = (lane & 7) + ((lane >> 4) << 3);
        const int kb_koff = ((lane >> 3) & 1) << 3;
        const int vb_row  = (lane & 7) + (((lane >> 3) & 1) << 3);
        const int vb_eoff = (lane >> 4) << 3;

        const int rA_g = qb * 128 + wm * 16 + (lane >> 2);

        for (int kt = 0; kt < kmax; ++kt) {
            CP_WAIT(0);
            __syncthreads();
            if (kt + 1 < kmax) {
                size_t koff = (size_t)(kt + 1) * 64 * DH_;
                attn_load_kv(smb + 36864 + ((kt + 1) & 1) * KV_STAGE,
                             kh_g + koff, kl_g + koff, vh_g + koff, vl_g + koff, tid);
                CP_COMMIT();
            }

            const uint32_t kvb = smb + 36864 + (kt & 1) * KV_STAGE;
            const uint32_t Kh_b = kvb, Kl_b = kvb + 9216, Vh_b = kvb + 18432, Vl_b = kvb + 27648;

            float sacc[8][4];
            #pragma unroll
            for (int t = 0; t < 8; ++t)
                #pragma unroll
                for (int q = 0; q < 4; ++q) sacc[t][q] = 0.f;

            #pragma unroll
            for (int ks = 0; ks < 4; ++ks) {
                #pragma unroll
                for (int np = 0; np < 4; ++np) {
                    uint32_t row = np * 16 + kb_row;
                    uint32_t ko  = ks * 16 + kb_koff;
                    uint32_t b0, b1, b2, b3, c0, c1, c2, c3;
                    LDSM_X4(b0, b1, b2, b3, Kh_b + row * 144 + ko * 2);
                    LDSM_X4(c0, c1, c2, c3, Kl_b + row * 144 + ko * 2);
                    mma16816(sacc[2 * np],     qh[ks][0], qh[ks][1], qh[ks][2], qh[ks][3], b0, b1);
                    mma16816(sacc[2 * np],     qh[ks][0], qh[ks][1], qh[ks][2], qh[ks][3], c0, c1);
                    mma16816(sacc[2 * np],     ql[ks][0], ql[ks][1], ql[ks][2], ql[ks][3], b0, b1);
                    mma16816(sacc[2 * np + 1], qh[ks][0], qh[ks][1], qh[ks][2], qh[ks][3], b2, b3);
                    mma16816(sacc[2 * np + 1], qh[ks][0], qh[ks][1], qh[ks][2], qh[ks][3], c2, c3);
                    mma16816(sacc[2 * np + 1], ql[ks][0], ql[ks][1], ql[ks][2], ql[ks][3], b2, b3);
                }
            }

            if (kt >= 2 * qb) {
                const int c0g = kt * 64 + 2 * (lane & 3);
                #pragma unroll
                for (int t = 0; t < 8; ++t) {
                    int c = c0g + 8 * t;
                    if (c     > rA_g)     sacc[t][0] = -3.0e38f;
                    if (c + 1 > rA_g)     sacc[t][1] = -3.0e38f;
                    if (c     > rA_g + 8) sacc[t][2] = -3.0e38f;
                    if (c + 1 > rA_g + 8) sacc[t][3] = -3.0e38f;
                }
            }

            float mtA = -3.0e38f, mtB = -3.0e38f;
            #pragma unroll
            for (int t = 0; t < 8; ++t) {
                mtA = fmaxf(mtA, fmaxf(sacc[t][0], sacc[t][1]));
                mtB = fmaxf(mtB, fmaxf(sacc[t][2], sacc[t][3]));
            }
            mtA = fmaxf(mtA, __shfl_xor_sync(0xffffffffu, mtA, 1));
            mtA = fmaxf(mtA, __shfl_xor_sync(0xffffffffu, mtA, 2));
            mtB = fmaxf(mtB, __shfl_xor_sync(0xffffffffu, mtB, 1));
            mtB = fmaxf(mtB, __shfl_xor_sync(0xffffffffu, mtB, 2));

            float mnA = fmaxf(mA, mtA), mnB = fmaxf(mB, mtB);
            float corrA = __expf(mA - mnA), corrB = __expf(mB - mnB);

            float rsA = 0.f, rsB = 0.f;
            #pragma unroll
            for (int t = 0; t < 8; ++t) {
                float p0 = __expf(sacc[t][0] - mnA); sacc[t][0] = p0; rsA += p0;
                float p1 = __expf(sacc[t][1] - mnA); sacc[t][1] = p1; rsA += p1;
                float p2 = __expf(sacc[t][2] - mnB); sacc[t][2] = p2; rsB += p2;
                float p3 = __expf(sacc[t][3] - mnB); sacc[t][3] = p3; rsB += p3;
            }
            rsA += __shfl_xor_sync(0xffffffffu, rsA, 1);
            rsA += __shfl_xor_sync(0xffffffffu, rsA, 2);
            rsB += __shfl_xor_sync(0xffffffffu, rsB, 1);
            rsB += __shfl_xor_sync(0xffffffffu, rsB, 2);

            lA = lA * corrA + rsA;
            lB = lB * corrB + rsB;
            #pragma unroll
            for (int t = 0; t < 8; ++t) {
                oacc[t][0] *= corrA; oacc[t][1] *= corrA;
                oacc[t][2] *= corrB; oacc[t][3] *= corrB;
            }
            mA = mnA; mB = mnB;

            #pragma unroll
            for (int ks = 0; ks < 4; ++ks) {
                uint32_t pfh[4], pfl[4];
                {
                    float h00, l00, h01, l01, h10, l10, h11, l11;
                    bsplit(sacc[2 * ks][0], h00, l00); bsplit(sacc[2 * ks][1], h01, l01);
                    bsplit(sacc[2 * ks][2], h10, l10); bsplit(sacc[2 * ks][3], h11, l11);
                    pfh[0] = packbf(h00, h01); pfl[0] = packbf(l00, l01);
                    pfh[1] = packbf(h10, h11); pfl[1] = packbf(l10, l11);
                    bsplit(sacc[2 * ks + 1][0], h00, l00); bsplit(sacc[2 * ks + 1][1], h01, l01);
                    bsplit(sacc[2 * ks + 1][2], h10, l10); bsplit(sacc[2 * ks + 1][3], h11, l11);
                    pfh[2] = packbf(h00, h01); pfl[2] = packbf(l00, l01);
                    pfh[3] = packbf(h10, h11); pfl[3] = packbf(l10, l11);
                }
                #pragma unroll
                for (int ep = 0; ep < 4; ++ep) {
                    uint32_t row = ks * 16 + vb_row;
                    uint32_t eo  = ep * 16 + vb_eoff;
                    uint32_t v0, v1, v2, v3, w0, w1, w2, w3;
                    LDSM_X4_T(v0, v1, v2, v3, Vh_b + row * 144 + eo * 2);
                    LDSM_X4_T(w0, w1, w2, w3, Vl_b + row * 144 + eo * 2);
                    mma16816(oacc[2 * ep],     pfh[0], pfh[1], pfh[2], pfh[3], v0, v1);
                    mma16816(oacc[2 * ep],     pfh[0], pfh[1], pfh[2], pfh[3], w0, w1);
                    mma16816(oacc[2 * ep],     pfl[0], pfl[1], pfl[2], pfl[3], v0, v1);
                    mma16816(oacc[2 * ep + 1], pfh[0], pfh[1], pfh[2], pfh[3], v2, v3);
                    mma16816(oacc[2 * ep + 1], pfh[0], pfh[1], pfh[2], pfh[3], w2, w3);
                    mma16816(oacc[2 * ep + 1], pfl[0], pfl[1], pfl[2], pfl[3], v2, v3);
                }
            }
        }

        const float invA = 1.0f / lA;
        const float invB = 1.0f / lB;
        const int b = bh >> 4, h = bh & 15;
        const int e0 = 2 * (lane & 3);
        size_t baseA = ((size_t)b * S_ + rA_g) * D_ + h * DH_;
        size_t baseB = ((size_t)b * S_ + rA_g + 8) * D_ + h * DH_;
        #pragma unroll
        for (int t = 0; t < 8; ++t) {
            int e = 8 * t + e0;
            float a0 = oacc[t][0] * invA, a1 = oacc[t][1] * invA;
            float b0v = oacc[t][2] * invB, b1v = oacc[t][3] * invB;
            float h0, l0, h1, l1;
            bsplit(a0, h0, l0); bsplit(a1, h1, l1);
            *(uint32_t*)(g_ch + baseA + e) = packbf(h0, h1);
            *(uint32_t*)(g_cl + baseA + e) = packbf(l0, l1);
            bsplit(b0v, h0, l0); bsplit(b1v, h1, l1);
            *(uint32_t*)(g_ch + baseB + e) = packbf(h0, h1);
            *(uint32_t*)(g_cl + baseB + e) = packbf(l0, l1);
        }
        __syncthreads();
    }
}

// ============================================================
extern "C" void kernel_launch(void* const* d_in, const int* in_sizes, int n_in,
                              void* d_out, int out_size)
{
    const float* x  = (const float*)d_in[0];
    const float* Wq = (const float*)d_in[1];
    const float* Wk = (const float*)d_in[2];
    const float* Wv = (const float*)d_in[3];
    const float* Wo = (const float*)d_in[4];
    const float* bo = (const float*)d_in[5];
    float* out = (float*)d_out;

    cudaFuncSetAttribute(qkv_mma_kernel, cudaFuncAttributeMaxDynamicSharedMemorySize, GEMM_SMEM);
    cudaFuncSetAttribute(out_proj_mma_kernel, cudaFuncAttributeMaxDynamicSharedMemorySize, GEMM_SMEM);
    cudaFuncSetAttribute(attn_mma_kernel, cudaFuncAttributeMaxDynamicSharedMemorySize, ATTN_SMEM);

    conv_all_kernel<<<9216, 256>>>(x, Wq, Wk, Wv, Wo);
    qkv_mma_kernel<<<PERSIST_CTAS, 256, GEMM_SMEM>>>();
    attn_mma_kernel<<<PERSIST_CTAS, 256, ATTN_SMEM>>>();
    out_proj_mma_kernel<<<PERSIST_CTAS, 256, GEMM_SMEM>>>(bo, out);
}